// round 2
// baseline (speedup 1.0000x reference)
#include <cuda_runtime.h>
#include <math.h>

#define NN 50000
#define EE 800000
#define INF_DIM 256
#define H1 8
#define D1 32
#define OUTD 32
#define NEG_SLOPE 0.2f

// ---------------- scratch (device globals; no allocation allowed) ----------------
__device__ float g_feat1[NN * 256];   // layer1 transformed features
__device__ float g_y[NN * 256];       // layer1 output (after relu)
__device__ float g_el1[NN * H1];
__device__ float g_er1[NN * H1];
__device__ float g_e1[EE * H1];       // edge scores layer1
__device__ float g_feat2[NN * OUTD];
__device__ float g_res2[NN * OUTD];   // y @ resW2
__device__ float g_el2[NN];
__device__ float g_er2[NN];
__device__ float g_e2[EE];
__device__ int   g_deg[NN];
__device__ int   g_rowoff[NN + 1];
__device__ int   g_cursor[NN];
__device__ int   g_csr_eid[EE];
__device__ int   g_csr_src[EE];

// ---------------- CSR build ----------------
__global__ void zero_deg_kernel() {
    int i = blockIdx.x * blockDim.x + threadIdx.x;
    if (i < NN) g_deg[i] = 0;
}

__global__ void hist_kernel(const int* __restrict__ dst) {
    int e = blockIdx.x * blockDim.x + threadIdx.x;
    if (e < EE) atomicAdd(&g_deg[dst[e]], 1);
}

__global__ void scan_kernel() {
    __shared__ int sm[1024];
    __shared__ int carry;
    int tid = threadIdx.x;
    if (tid == 0) carry = 0;
    __syncthreads();
    for (int base = 0; base < NN; base += 1024) {
        int i = base + tid;
        int v = (i < NN) ? g_deg[i] : 0;
        sm[tid] = v;
        __syncthreads();
        #pragma unroll
        for (int off = 1; off < 1024; off <<= 1) {
            int t2 = (tid >= off) ? sm[tid - off] : 0;
            __syncthreads();
            sm[tid] += t2;
            __syncthreads();
        }
        if (i < NN) g_rowoff[i] = carry + sm[tid] - v;   // exclusive
        __syncthreads();
        if (tid == 0) carry += sm[1023];
        __syncthreads();
    }
    if (tid == 0) g_rowoff[NN] = carry;
}

__global__ void cursor_copy_kernel() {
    int i = blockIdx.x * blockDim.x + threadIdx.x;
    if (i < NN) g_cursor[i] = g_rowoff[i];
}

__global__ void scatter_kernel(const int* __restrict__ src, const int* __restrict__ dst) {
    int e = blockIdx.x * blockDim.x + threadIdx.x;
    if (e < EE) {
        int d = dst[e];
        int slot = atomicAdd(&g_cursor[d], 1);
        g_csr_eid[slot] = e;
        g_csr_src[slot] = src[e];
    }
}

// ---------------- fp32 tiled GEMM: C[M,N] = A[M,K] @ B[K,N] ----------------
// BM=64 BN=64 BK=16, 256 threads, 4x4 per thread. K % 16 == 0, N % 4 == 0.
__global__ void gemm_kernel(const float* __restrict__ A, const float* __restrict__ B,
                            float* __restrict__ C, int M, int N, int K) {
    __shared__ float As[16][65];
    __shared__ float Bs[16][64];
    int tid  = threadIdx.x;
    int row0 = blockIdx.y * 64;
    int col0 = blockIdx.x * 64;
    int tr = tid / 16;       // 0..15
    int tc = tid % 16;       // 0..15
    float acc[4][4] = {};
    for (int k0 = 0; k0 < K; k0 += 16) {
        {   // load A tile: 64 rows x 16 cols
            int r = tid / 4;
            int c = (tid % 4) * 4;
            int gr = row0 + r;
            float4 v = make_float4(0.f, 0.f, 0.f, 0.f);
            if (gr < M) v = *(const float4*)&A[(size_t)gr * K + k0 + c];
            As[c + 0][r] = v.x; As[c + 1][r] = v.y; As[c + 2][r] = v.z; As[c + 3][r] = v.w;
        }
        {   // load B tile: 16 rows x 64 cols
            int r = tid / 16;
            int c = (tid % 16) * 4;
            float4 v = make_float4(0.f, 0.f, 0.f, 0.f);
            if (col0 + c < N) v = *(const float4*)&B[(size_t)(k0 + r) * N + col0 + c];
            *(float4*)&Bs[r][c] = v;
        }
        __syncthreads();
        #pragma unroll
        for (int k = 0; k < 16; k++) {
            float a0 = As[k][tr * 4 + 0];
            float a1 = As[k][tr * 4 + 1];
            float a2 = As[k][tr * 4 + 2];
            float a3 = As[k][tr * 4 + 3];
            float4 bv = *(float4*)&Bs[k][tc * 4];
            acc[0][0] += a0 * bv.x; acc[0][1] += a0 * bv.y; acc[0][2] += a0 * bv.z; acc[0][3] += a0 * bv.w;
            acc[1][0] += a1 * bv.x; acc[1][1] += a1 * bv.y; acc[1][2] += a1 * bv.z; acc[1][3] += a1 * bv.w;
            acc[2][0] += a2 * bv.x; acc[2][1] += a2 * bv.y; acc[2][2] += a2 * bv.z; acc[2][3] += a2 * bv.w;
            acc[3][0] += a3 * bv.x; acc[3][1] += a3 * bv.y; acc[3][2] += a3 * bv.z; acc[3][3] += a3 * bv.w;
        }
        __syncthreads();
    }
    #pragma unroll
    for (int i = 0; i < 4; i++) {
        int gr = row0 + tr * 4 + i;
        if (gr >= M) continue;
        #pragma unroll
        for (int j = 0; j < 4; j++) {
            int gc = col0 + tc * 4 + j;
            if (gc < N) C[(size_t)gr * N + gc] = acc[i][j];
        }
    }
}

// ---------------- attention logits: el/er per (node, head), D=32 ----------------
__global__ void attn_kernel(const float* __restrict__ feat, const float* __restrict__ al,
                            const float* __restrict__ ar, float* __restrict__ el,
                            float* __restrict__ er, int NH, int H) {
    int t = blockIdx.x * blockDim.x + threadIdx.x;
    int w = t >> 5;
    if (w >= NH) return;
    int lane = t & 31;
    int h = w % H;
    float f  = feat[(size_t)w * 32 + lane];
    float s1 = f * al[h * 32 + lane];
    float s2 = f * ar[h * 32 + lane];
    #pragma unroll
    for (int o = 16; o; o >>= 1) {
        s1 += __shfl_xor_sync(0xffffffffu, s1, o);
        s2 += __shfl_xor_sync(0xffffffffu, s2, o);
    }
    if (lane == 0) { el[w] = s1; er[w] = s2; }
}

// ---------------- edge score: leaky_relu(el[src]+er[dst]) ----------------
__global__ void escore_kernel(const int* __restrict__ src, const int* __restrict__ dst,
                              const float* __restrict__ el, const float* __restrict__ er,
                              float* __restrict__ eo, int EH, int H) {
    int i = blockIdx.x * blockDim.x + threadIdx.x;
    if (i >= EH) return;
    int e = i / H;
    int h = i - e * H;
    float v = el[src[e] * H + h] + er[dst[e] * H + h];
    eo[i] = v > 0.f ? v : NEG_SLOPE * v;
}

// ---------------- layer1 softmax+aggregate: 1 block per node, warp = head ----------------
__global__ void agg1_kernel(const float* __restrict__ x, const float* __restrict__ b1) {
    int n = blockIdx.x;
    int h = threadIdx.x >> 5;
    int lane = threadIdx.x & 31;
    int beg = g_rowoff[n], end = g_rowoff[n + 1];
    // pass 1: max (lane-strided + warp reduce)
    float m = -INFINITY;
    for (int i = beg + lane; i < end; i += 32) m = fmaxf(m, g_e1[g_csr_eid[i] * H1 + h]);
    #pragma unroll
    for (int o = 16; o; o >>= 1) m = fmaxf(m, __shfl_xor_sync(0xffffffffu, m, o));
    // pass 2: sum exp
    float s = 0.f;
    for (int i = beg + lane; i < end; i += 32) s += __expf(g_e1[g_csr_eid[i] * H1 + h] - m);
    #pragma unroll
    for (int o = 16; o; o >>= 1) s += __shfl_xor_sync(0xffffffffu, s, o);
    float inv = (end > beg) ? 1.0f / s : 0.f;
    // pass 3: weighted aggregation (w uniform per warp; feat read is one 128B line)
    float acc = 0.f;
    for (int i = beg; i < end; i++) {
        int eid = g_csr_eid[i];
        int sn  = g_csr_src[i];
        float w = __expf(g_e1[eid * H1 + h] - m) * inv;
        acc += g_feat1[(size_t)sn * 256 + h * 32 + lane] * w;
    }
    int o = n * 256 + h * 32 + lane;
    float r = acc + x[o] + b1[h * 32 + lane];     // identity residual + bias
    g_y[o] = fmaxf(r, 0.f);                        // relu between layers
}

// ---------------- layer2 softmax+aggregate: warp per node (H=1, D=32) ----------------
__global__ void agg2_kernel(const float* __restrict__ b2, float* __restrict__ out) {
    int t = blockIdx.x * blockDim.x + threadIdx.x;
    int n = t >> 5;
    if (n >= NN) return;
    int lane = t & 31;
    int beg = g_rowoff[n], end = g_rowoff[n + 1];
    float m = -INFINITY;
    for (int i = beg + lane; i < end; i += 32) m = fmaxf(m, g_e2[g_csr_eid[i]]);
    #pragma unroll
    for (int o = 16; o; o >>= 1) m = fmaxf(m, __shfl_xor_sync(0xffffffffu, m, o));
    float s = 0.f;
    for (int i = beg + lane; i < end; i += 32) s += __expf(g_e2[g_csr_eid[i]] - m);
    #pragma unroll
    for (int o = 16; o; o >>= 1) s += __shfl_xor_sync(0xffffffffu, s, o);
    float inv = (end > beg) ? 1.0f / s : 0.f;
    float acc = 0.f;
    for (int i = beg; i < end; i++) {
        int eid = g_csr_eid[i];
        int sn  = g_csr_src[i];
        float w = __expf(g_e2[eid] - m) * inv;
        acc += g_feat2[(size_t)sn * 32 + lane] * w;
    }
    out[n * 32 + lane] = acc + g_res2[n * 32 + lane] + b2[lane];
}

// ---------------- launch ----------------
extern "C" void kernel_launch(void* const* d_in, const int* in_sizes, int n_in,
                              void* d_out, int out_size) {
    const float* x     = (const float*)d_in[0];
    const int*   src   = (const int*)d_in[1];
    const int*   dst   = (const int*)d_in[2];
    const float* W1    = (const float*)d_in[3];
    const float* al1   = (const float*)d_in[4];
    const float* ar1   = (const float*)d_in[5];
    const float* b1    = (const float*)d_in[6];
    const float* W2    = (const float*)d_in[7];
    const float* al2   = (const float*)d_in[8];
    const float* ar2   = (const float*)d_in[9];
    const float* resW2 = (const float*)d_in[10];
    const float* b2    = (const float*)d_in[11];
    float* out = (float*)d_out;

    float *feat1, *yb, *el1, *er1, *e1, *feat2, *res2, *el2, *er2, *e2;
    cudaGetSymbolAddress((void**)&feat1, g_feat1);
    cudaGetSymbolAddress((void**)&yb,    g_y);
    cudaGetSymbolAddress((void**)&el1,   g_el1);
    cudaGetSymbolAddress((void**)&er1,   g_er1);
    cudaGetSymbolAddress((void**)&e1,    g_e1);
    cudaGetSymbolAddress((void**)&feat2, g_feat2);
    cudaGetSymbolAddress((void**)&res2,  g_res2);
    cudaGetSymbolAddress((void**)&el2,   g_el2);
    cudaGetSymbolAddress((void**)&er2,   g_er2);
    cudaGetSymbolAddress((void**)&e2,    g_e2);

    // CSR by dst (shared by both layers)
    zero_deg_kernel<<<(NN + 255) / 256, 256>>>();
    hist_kernel<<<(EE + 255) / 256, 256>>>(dst);
    scan_kernel<<<1, 1024>>>();
    cursor_copy_kernel<<<(NN + 255) / 256, 256>>>();
    scatter_kernel<<<(EE + 255) / 256, 256>>>(src, dst);

    // layer 1
    gemm_kernel<<<dim3(4, (NN + 63) / 64), 256>>>(x, W1, feat1, NN, 256, 256);
    attn_kernel<<<(NN * H1 * 32 + 255) / 256, 256>>>(feat1, al1, ar1, el1, er1, NN * H1, H1);
    escore_kernel<<<(EE * H1 + 255) / 256, 256>>>(src, dst, el1, er1, e1, EE * H1, H1);
    agg1_kernel<<<NN, 256>>>(x, b1);

    // layer 2
    gemm_kernel<<<dim3(1, (NN + 63) / 64), 256>>>(yb, W2, feat2, NN, 32, 256);
    gemm_kernel<<<dim3(1, (NN + 63) / 64), 256>>>(yb, resW2, res2, NN, 32, 256);
    attn_kernel<<<(NN * 32 + 255) / 256, 256>>>(feat2, al2, ar2, el2, er2, NN, 1);
    escore_kernel<<<(EE + 255) / 256, 256>>>(src, dst, el2, er2, e2, EE, 1);
    agg2_kernel<<<(NN * 32 + 255) / 256, 256>>>(b2, out);
}

// round 3
// speedup vs baseline: 1.0002x; 1.0002x over previous
#include <cuda_runtime.h>
#include <math.h>

#define NN 50000
#define EE 800000
#define INF_DIM 256
#define H1 8
#define D1 32
#define OUTD 32
#define NEG_SLOPE 0.2f

// ---------------- scratch (device globals; no allocation allowed) ----------------
__device__ float g_feat1[NN * 256];   // layer1 transformed features
__device__ float g_y[NN * 256];       // layer1 output (after relu)
__device__ float g_el1[NN * H1];
__device__ float g_er1[NN * H1];
__device__ float g_e1[EE * H1];       // edge scores layer1
__device__ float g_feat2[NN * OUTD];
__device__ float g_res2[NN * OUTD];   // y @ resW2
__device__ float g_el2[NN];
__device__ float g_er2[NN];
__device__ float g_e2[EE];
__device__ int   g_deg[NN];
__device__ int   g_rowoff[NN + 1];
__device__ int   g_cursor[NN];
__device__ int   g_csr_eid[EE];
__device__ int   g_csr_src[EE];

// ---------------- CSR build ----------------
__global__ void zero_deg_kernel() {
    int i = blockIdx.x * blockDim.x + threadIdx.x;
    if (i < NN) g_deg[i] = 0;
}

__global__ void hist_kernel(const int* __restrict__ dst) {
    int e = blockIdx.x * blockDim.x + threadIdx.x;
    if (e < EE) atomicAdd(&g_deg[dst[e]], 1);
}

__global__ void scan_kernel() {
    __shared__ int sm[1024];
    __shared__ int carry;
    int tid = threadIdx.x;
    if (tid == 0) carry = 0;
    __syncthreads();
    for (int base = 0; base < NN; base += 1024) {
        int i = base + tid;
        int v = (i < NN) ? g_deg[i] : 0;
        sm[tid] = v;
        __syncthreads();
        #pragma unroll
        for (int off = 1; off < 1024; off <<= 1) {
            int t2 = (tid >= off) ? sm[tid - off] : 0;
            __syncthreads();
            sm[tid] += t2;
            __syncthreads();
        }
        if (i < NN) g_rowoff[i] = carry + sm[tid] - v;   // exclusive
        __syncthreads();
        if (tid == 0) carry += sm[1023];
        __syncthreads();
    }
    if (tid == 0) g_rowoff[NN] = carry;
}

__global__ void cursor_copy_kernel() {
    int i = blockIdx.x * blockDim.x + threadIdx.x;
    if (i < NN) g_cursor[i] = g_rowoff[i];
}

__global__ void scatter_kernel(const int* __restrict__ src, const int* __restrict__ dst) {
    int e = blockIdx.x * blockDim.x + threadIdx.x;
    if (e < EE) {
        int d = dst[e];
        int slot = atomicAdd(&g_cursor[d], 1);
        g_csr_eid[slot] = e;
        g_csr_src[slot] = src[e];
    }
}

// ---------------- fp32 tiled GEMM: C[M,N] = A[M,K] @ B[K,N] ----------------
// BM=64 BN=64 BK=16, 256 threads, 4x4 per thread. K % 16 == 0, N % 4 == 0.
__global__ void gemm_kernel(const float* __restrict__ A, const float* __restrict__ B,
                            float* __restrict__ C, int M, int N, int K) {
    __shared__ float As[16][65];
    __shared__ float Bs[16][64];
    int tid  = threadIdx.x;
    int row0 = blockIdx.y * 64;
    int col0 = blockIdx.x * 64;
    int tr = tid / 16;       // 0..15
    int tc = tid % 16;       // 0..15
    float acc[4][4] = {};
    for (int k0 = 0; k0 < K; k0 += 16) {
        {   // load A tile: 64 rows x 16 cols
            int r = tid / 4;
            int c = (tid % 4) * 4;
            int gr = row0 + r;
            float4 v = make_float4(0.f, 0.f, 0.f, 0.f);
            if (gr < M) v = *(const float4*)&A[(size_t)gr * K + k0 + c];
            As[c + 0][r] = v.x; As[c + 1][r] = v.y; As[c + 2][r] = v.z; As[c + 3][r] = v.w;
        }
        {   // load B tile: 16 rows x 64 cols
            int r = tid / 16;
            int c = (tid % 16) * 4;
            float4 v = make_float4(0.f, 0.f, 0.f, 0.f);
            if (col0 + c < N) v = *(const float4*)&B[(size_t)(k0 + r) * N + col0 + c];
            *(float4*)&Bs[r][c] = v;
        }
        __syncthreads();
        #pragma unroll
        for (int k = 0; k < 16; k++) {
            float a0 = As[k][tr * 4 + 0];
            float a1 = As[k][tr * 4 + 1];
            float a2 = As[k][tr * 4 + 2];
            float a3 = As[k][tr * 4 + 3];
            float4 bv = *(float4*)&Bs[k][tc * 4];
            acc[0][0] += a0 * bv.x; acc[0][1] += a0 * bv.y; acc[0][2] += a0 * bv.z; acc[0][3] += a0 * bv.w;
            acc[1][0] += a1 * bv.x; acc[1][1] += a1 * bv.y; acc[1][2] += a1 * bv.z; acc[1][3] += a1 * bv.w;
            acc[2][0] += a2 * bv.x; acc[2][1] += a2 * bv.y; acc[2][2] += a2 * bv.z; acc[2][3] += a2 * bv.w;
            acc[3][0] += a3 * bv.x; acc[3][1] += a3 * bv.y; acc[3][2] += a3 * bv.z; acc[3][3] += a3 * bv.w;
        }
        __syncthreads();
    }
    #pragma unroll
    for (int i = 0; i < 4; i++) {
        int gr = row0 + tr * 4 + i;
        if (gr >= M) continue;
        #pragma unroll
        for (int j = 0; j < 4; j++) {
            int gc = col0 + tc * 4 + j;
            if (gc < N) C[(size_t)gr * N + gc] = acc[i][j];
        }
    }
}

// ---------------- attention logits: el/er per (node, head), D=32 ----------------
__global__ void attn_kernel(const float* __restrict__ feat, const float* __restrict__ al,
                            const float* __restrict__ ar, float* __restrict__ el,
                            float* __restrict__ er, int NH, int H) {
    int t = blockIdx.x * blockDim.x + threadIdx.x;
    int w = t >> 5;
    if (w >= NH) return;
    int lane = t & 31;
    int h = w % H;
    float f  = feat[(size_t)w * 32 + lane];
    float s1 = f * al[h * 32 + lane];
    float s2 = f * ar[h * 32 + lane];
    #pragma unroll
    for (int o = 16; o; o >>= 1) {
        s1 += __shfl_xor_sync(0xffffffffu, s1, o);
        s2 += __shfl_xor_sync(0xffffffffu, s2, o);
    }
    if (lane == 0) { el[w] = s1; er[w] = s2; }
}

// ---------------- edge score: leaky_relu(el[src]+er[dst]) ----------------
__global__ void escore_kernel(const int* __restrict__ src, const int* __restrict__ dst,
                              const float* __restrict__ el, const float* __restrict__ er,
                              float* __restrict__ eo, int EH, int H) {
    int i = blockIdx.x * blockDim.x + threadIdx.x;
    if (i >= EH) return;
    int e = i / H;
    int h = i - e * H;
    float v = el[src[e] * H + h] + er[dst[e] * H + h];
    eo[i] = v > 0.f ? v : NEG_SLOPE * v;
}

// ---------------- layer1 softmax+aggregate: 1 block per node, warp = head ----------------
__global__ void agg1_kernel(const float* __restrict__ x, const float* __restrict__ b1) {
    int n = blockIdx.x;
    int h = threadIdx.x >> 5;
    int lane = threadIdx.x & 31;
    int beg = g_rowoff[n], end = g_rowoff[n + 1];
    // pass 1: max (lane-strided + warp reduce)
    float m = -INFINITY;
    for (int i = beg + lane; i < end; i += 32) m = fmaxf(m, g_e1[g_csr_eid[i] * H1 + h]);
    #pragma unroll
    for (int o = 16; o; o >>= 1) m = fmaxf(m, __shfl_xor_sync(0xffffffffu, m, o));
    // pass 2: sum exp
    float s = 0.f;
    for (int i = beg + lane; i < end; i += 32) s += __expf(g_e1[g_csr_eid[i] * H1 + h] - m);
    #pragma unroll
    for (int o = 16; o; o >>= 1) s += __shfl_xor_sync(0xffffffffu, s, o);
    float inv = (end > beg) ? 1.0f / s : 0.f;
    // pass 3: weighted aggregation (w uniform per warp; feat read is one 128B line)
    float acc = 0.f;
    for (int i = beg; i < end; i++) {
        int eid = g_csr_eid[i];
        int sn  = g_csr_src[i];
        float w = __expf(g_e1[eid * H1 + h] - m) * inv;
        acc += g_feat1[(size_t)sn * 256 + h * 32 + lane] * w;
    }
    int o = n * 256 + h * 32 + lane;
    float r = acc + x[o] + b1[h * 32 + lane];     // identity residual + bias
    g_y[o] = fmaxf(r, 0.f);                        // relu between layers
}

// ---------------- layer2 softmax+aggregate: warp per node (H=1, D=32) ----------------
__global__ void agg2_kernel(const float* __restrict__ b2, float* __restrict__ out) {
    int t = blockIdx.x * blockDim.x + threadIdx.x;
    int n = t >> 5;
    if (n >= NN) return;
    int lane = t & 31;
    int beg = g_rowoff[n], end = g_rowoff[n + 1];
    float m = -INFINITY;
    for (int i = beg + lane; i < end; i += 32) m = fmaxf(m, g_e2[g_csr_eid[i]]);
    #pragma unroll
    for (int o = 16; o; o >>= 1) m = fmaxf(m, __shfl_xor_sync(0xffffffffu, m, o));
    float s = 0.f;
    for (int i = beg + lane; i < end; i += 32) s += __expf(g_e2[g_csr_eid[i]] - m);
    #pragma unroll
    for (int o = 16; o; o >>= 1) s += __shfl_xor_sync(0xffffffffu, s, o);
    float inv = (end > beg) ? 1.0f / s : 0.f;
    float acc = 0.f;
    for (int i = beg; i < end; i++) {
        int eid = g_csr_eid[i];
        int sn  = g_csr_src[i];
        float w = __expf(g_e2[eid] - m) * inv;
        acc += g_feat2[(size_t)sn * 32 + lane] * w;
    }
    out[n * 32 + lane] = acc + g_res2[n * 32 + lane] + b2[lane];
}

// ---------------- launch ----------------
extern "C" void kernel_launch(void* const* d_in, const int* in_sizes, int n_in,
                              void* d_out, int out_size) {
    const float* x     = (const float*)d_in[0];
    const int*   src   = (const int*)d_in[1];
    const int*   dst   = (const int*)d_in[2];
    const float* W1    = (const float*)d_in[3];
    const float* al1   = (const float*)d_in[4];
    const float* ar1   = (const float*)d_in[5];
    const float* b1    = (const float*)d_in[6];
    const float* W2    = (const float*)d_in[7];
    const float* al2   = (const float*)d_in[8];
    const float* ar2   = (const float*)d_in[9];
    const float* resW2 = (const float*)d_in[10];
    const float* b2    = (const float*)d_in[11];
    float* out = (float*)d_out;

    float *feat1, *yb, *el1, *er1, *e1, *feat2, *res2, *el2, *er2, *e2;
    cudaGetSymbolAddress((void**)&feat1, g_feat1);
    cudaGetSymbolAddress((void**)&yb,    g_y);
    cudaGetSymbolAddress((void**)&el1,   g_el1);
    cudaGetSymbolAddress((void**)&er1,   g_er1);
    cudaGetSymbolAddress((void**)&e1,    g_e1);
    cudaGetSymbolAddress((void**)&feat2, g_feat2);
    cudaGetSymbolAddress((void**)&res2,  g_res2);
    cudaGetSymbolAddress((void**)&el2,   g_el2);
    cudaGetSymbolAddress((void**)&er2,   g_er2);
    cudaGetSymbolAddress((void**)&e2,    g_e2);

    // CSR by dst (shared by both layers)
    zero_deg_kernel<<<(NN + 255) / 256, 256>>>();
    hist_kernel<<<(EE + 255) / 256, 256>>>(dst);
    scan_kernel<<<1, 1024>>>();
    cursor_copy_kernel<<<(NN + 255) / 256, 256>>>();
    scatter_kernel<<<(EE + 255) / 256, 256>>>(src, dst);

    // layer 1
    gemm_kernel<<<dim3(4, (NN + 63) / 64), 256>>>(x, W1, feat1, NN, 256, 256);
    attn_kernel<<<(NN * H1 * 32 + 255) / 256, 256>>>(feat1, al1, ar1, el1, er1, NN * H1, H1);
    escore_kernel<<<(EE * H1 + 255) / 256, 256>>>(src, dst, el1, er1, e1, EE * H1, H1);
    agg1_kernel<<<NN, 256>>>(x, b1);

    // layer 2
    gemm_kernel<<<dim3(1, (NN + 63) / 64), 256>>>(yb, W2, feat2, NN, 32, 256);
    gemm_kernel<<<dim3(1, (NN + 63) / 64), 256>>>(yb, resW2, res2, NN, 32, 256);
    attn_kernel<<<(NN * 32 + 255) / 256, 256>>>(feat2, al2, ar2, el2, er2, NN, 1);
    escore_kernel<<<(EE + 255) / 256, 256>>>(src, dst, el2, er2, e2, EE, 1);
    agg2_kernel<<<(NN * 32 + 255) / 256, 256>>>(b2, out);
}

// round 4
// speedup vs baseline: 1.0005x; 1.0004x over previous
#include <cuda_runtime.h>
#include <math.h>

#define NN 50000
#define EE 800000
#define INF_DIM 256
#define H1 8
#define D1 32
#define OUTD 32
#define NEG_SLOPE 0.2f

// ---------------- scratch (device globals; no allocation allowed) ----------------
__device__ float g_feat1[NN * 256];   // layer1 transformed features
__device__ float g_y[NN * 256];       // layer1 output (after relu)
__device__ float g_el1[NN * H1];
__device__ float g_er1[NN * H1];
__device__ float g_e1[EE * H1];       // edge scores layer1
__device__ float g_feat2[NN * OUTD];
__device__ float g_res2[NN * OUTD];   // y @ resW2
__device__ float g_el2[NN];
__device__ float g_er2[NN];
__device__ float g_e2[EE];
__device__ int   g_deg[NN];
__device__ int   g_rowoff[NN + 1];
__device__ int   g_cursor[NN];
__device__ int   g_csr_eid[EE];
__device__ int   g_csr_src[EE];

// ---------------- CSR build ----------------
__global__ void zero_deg_kernel() {
    int i = blockIdx.x * blockDim.x + threadIdx.x;
    if (i < NN) g_deg[i] = 0;
}

__global__ void hist_kernel(const int* __restrict__ dst) {
    int e = blockIdx.x * blockDim.x + threadIdx.x;
    if (e < EE) atomicAdd(&g_deg[dst[e]], 1);
}

__global__ void scan_kernel() {
    __shared__ int sm[1024];
    __shared__ int carry;
    int tid = threadIdx.x;
    if (tid == 0) carry = 0;
    __syncthreads();
    for (int base = 0; base < NN; base += 1024) {
        int i = base + tid;
        int v = (i < NN) ? g_deg[i] : 0;
        sm[tid] = v;
        __syncthreads();
        #pragma unroll
        for (int off = 1; off < 1024; off <<= 1) {
            int t2 = (tid >= off) ? sm[tid - off] : 0;
            __syncthreads();
            sm[tid] += t2;
            __syncthreads();
        }
        if (i < NN) g_rowoff[i] = carry + sm[tid] - v;   // exclusive
        __syncthreads();
        if (tid == 0) carry += sm[1023];
        __syncthreads();
    }
    if (tid == 0) g_rowoff[NN] = carry;
}

__global__ void cursor_copy_kernel() {
    int i = blockIdx.x * blockDim.x + threadIdx.x;
    if (i < NN) g_cursor[i] = g_rowoff[i];
}

__global__ void scatter_kernel(const int* __restrict__ src, const int* __restrict__ dst) {
    int e = blockIdx.x * blockDim.x + threadIdx.x;
    if (e < EE) {
        int d = dst[e];
        int slot = atomicAdd(&g_cursor[d], 1);
        g_csr_eid[slot] = e;
        g_csr_src[slot] = src[e];
    }
}

// ---------------- fp32 tiled GEMM: C[M,N] = A[M,K] @ B[K,N] ----------------
// BM=64 BN=64 BK=16, 256 threads, 4x4 per thread. K % 16 == 0, N % 4 == 0.
__global__ void gemm_kernel(const float* __restrict__ A, const float* __restrict__ B,
                            float* __restrict__ C, int M, int N, int K) {
    __shared__ float As[16][65];
    __shared__ float Bs[16][64];
    int tid  = threadIdx.x;
    int row0 = blockIdx.y * 64;
    int col0 = blockIdx.x * 64;
    int tr = tid / 16;       // 0..15
    int tc = tid % 16;       // 0..15
    float acc[4][4] = {};
    for (int k0 = 0; k0 < K; k0 += 16) {
        {   // load A tile: 64 rows x 16 cols
            int r = tid / 4;
            int c = (tid % 4) * 4;
            int gr = row0 + r;
            float4 v = make_float4(0.f, 0.f, 0.f, 0.f);
            if (gr < M) v = *(const float4*)&A[(size_t)gr * K + k0 + c];
            As[c + 0][r] = v.x; As[c + 1][r] = v.y; As[c + 2][r] = v.z; As[c + 3][r] = v.w;
        }
        {   // load B tile: 16 rows x 64 cols
            int r = tid / 16;
            int c = (tid % 16) * 4;
            float4 v = make_float4(0.f, 0.f, 0.f, 0.f);
            if (col0 + c < N) v = *(const float4*)&B[(size_t)(k0 + r) * N + col0 + c];
            *(float4*)&Bs[r][c] = v;
        }
        __syncthreads();
        #pragma unroll
        for (int k = 0; k < 16; k++) {
            float a0 = As[k][tr * 4 + 0];
            float a1 = As[k][tr * 4 + 1];
            float a2 = As[k][tr * 4 + 2];
            float a3 = As[k][tr * 4 + 3];
            float4 bv = *(float4*)&Bs[k][tc * 4];
            acc[0][0] += a0 * bv.x; acc[0][1] += a0 * bv.y; acc[0][2] += a0 * bv.z; acc[0][3] += a0 * bv.w;
            acc[1][0] += a1 * bv.x; acc[1][1] += a1 * bv.y; acc[1][2] += a1 * bv.z; acc[1][3] += a1 * bv.w;
            acc[2][0] += a2 * bv.x; acc[2][1] += a2 * bv.y; acc[2][2] += a2 * bv.z; acc[2][3] += a2 * bv.w;
            acc[3][0] += a3 * bv.x; acc[3][1] += a3 * bv.y; acc[3][2] += a3 * bv.z; acc[3][3] += a3 * bv.w;
        }
        __syncthreads();
    }
    #pragma unroll
    for (int i = 0; i < 4; i++) {
        int gr = row0 + tr * 4 + i;
        if (gr >= M) continue;
        #pragma unroll
        for (int j = 0; j < 4; j++) {
            int gc = col0 + tc * 4 + j;
            if (gc < N) C[(size_t)gr * N + gc] = acc[i][j];
        }
    }
}

// ---------------- attention logits: el/er per (node, head), D=32 ----------------
__global__ void attn_kernel(const float* __restrict__ feat, const float* __restrict__ al,
                            const float* __restrict__ ar, float* __restrict__ el,
                            float* __restrict__ er, int NH, int H) {
    int t = blockIdx.x * blockDim.x + threadIdx.x;
    int w = t >> 5;
    if (w >= NH) return;
    int lane = t & 31;
    int h = w % H;
    float f  = feat[(size_t)w * 32 + lane];
    float s1 = f * al[h * 32 + lane];
    float s2 = f * ar[h * 32 + lane];
    #pragma unroll
    for (int o = 16; o; o >>= 1) {
        s1 += __shfl_xor_sync(0xffffffffu, s1, o);
        s2 += __shfl_xor_sync(0xffffffffu, s2, o);
    }
    if (lane == 0) { el[w] = s1; er[w] = s2; }
}

// ---------------- edge score: leaky_relu(el[src]+er[dst]) ----------------
__global__ void escore_kernel(const int* __restrict__ src, const int* __restrict__ dst,
                              const float* __restrict__ el, const float* __restrict__ er,
                              float* __restrict__ eo, int EH, int H) {
    int i = blockIdx.x * blockDim.x + threadIdx.x;
    if (i >= EH) return;
    int e = i / H;
    int h = i - e * H;
    float v = el[src[e] * H + h] + er[dst[e] * H + h];
    eo[i] = v > 0.f ? v : NEG_SLOPE * v;
}

// ---------------- layer1 softmax+aggregate: 1 block per node, warp = head ----------------
__global__ void agg1_kernel(const float* __restrict__ x, const float* __restrict__ b1) {
    int n = blockIdx.x;
    int h = threadIdx.x >> 5;
    int lane = threadIdx.x & 31;
    int beg = g_rowoff[n], end = g_rowoff[n + 1];
    // pass 1: max (lane-strided + warp reduce)
    float m = -INFINITY;
    for (int i = beg + lane; i < end; i += 32) m = fmaxf(m, g_e1[g_csr_eid[i] * H1 + h]);
    #pragma unroll
    for (int o = 16; o; o >>= 1) m = fmaxf(m, __shfl_xor_sync(0xffffffffu, m, o));
    // pass 2: sum exp
    float s = 0.f;
    for (int i = beg + lane; i < end; i += 32) s += __expf(g_e1[g_csr_eid[i] * H1 + h] - m);
    #pragma unroll
    for (int o = 16; o; o >>= 1) s += __shfl_xor_sync(0xffffffffu, s, o);
    float inv = (end > beg) ? 1.0f / s : 0.f;
    // pass 3: weighted aggregation (w uniform per warp; feat read is one 128B line)
    float acc = 0.f;
    for (int i = beg; i < end; i++) {
        int eid = g_csr_eid[i];
        int sn  = g_csr_src[i];
        float w = __expf(g_e1[eid * H1 + h] - m) * inv;
        acc += g_feat1[(size_t)sn * 256 + h * 32 + lane] * w;
    }
    int o = n * 256 + h * 32 + lane;
    float r = acc + x[o] + b1[h * 32 + lane];     // identity residual + bias
    g_y[o] = fmaxf(r, 0.f);                        // relu between layers
}

// ---------------- layer2 softmax+aggregate: warp per node (H=1, D=32) ----------------
__global__ void agg2_kernel(const float* __restrict__ b2, float* __restrict__ out) {
    int t = blockIdx.x * blockDim.x + threadIdx.x;
    int n = t >> 5;
    if (n >= NN) return;
    int lane = t & 31;
    int beg = g_rowoff[n], end = g_rowoff[n + 1];
    float m = -INFINITY;
    for (int i = beg + lane; i < end; i += 32) m = fmaxf(m, g_e2[g_csr_eid[i]]);
    #pragma unroll
    for (int o = 16; o; o >>= 1) m = fmaxf(m, __shfl_xor_sync(0xffffffffu, m, o));
    float s = 0.f;
    for (int i = beg + lane; i < end; i += 32) s += __expf(g_e2[g_csr_eid[i]] - m);
    #pragma unroll
    for (int o = 16; o; o >>= 1) s += __shfl_xor_sync(0xffffffffu, s, o);
    float inv = (end > beg) ? 1.0f / s : 0.f;
    float acc = 0.f;
    for (int i = beg; i < end; i++) {
        int eid = g_csr_eid[i];
        int sn  = g_csr_src[i];
        float w = __expf(g_e2[eid] - m) * inv;
        acc += g_feat2[(size_t)sn * 32 + lane] * w;
    }
    out[n * 32 + lane] = acc + g_res2[n * 32 + lane] + b2[lane];
}

// ---------------- launch ----------------
extern "C" void kernel_launch(void* const* d_in, const int* in_sizes, int n_in,
                              void* d_out, int out_size) {
    const float* x     = (const float*)d_in[0];
    const int*   src   = (const int*)d_in[1];
    const int*   dst   = (const int*)d_in[2];
    const float* W1    = (const float*)d_in[3];
    const float* al1   = (const float*)d_in[4];
    const float* ar1   = (const float*)d_in[5];
    const float* b1    = (const float*)d_in[6];
    const float* W2    = (const float*)d_in[7];
    const float* al2   = (const float*)d_in[8];
    const float* ar2   = (const float*)d_in[9];
    const float* resW2 = (const float*)d_in[10];
    const float* b2    = (const float*)d_in[11];
    float* out = (float*)d_out;

    float *feat1, *yb, *el1, *er1, *e1, *feat2, *res2, *el2, *er2, *e2;
    cudaGetSymbolAddress((void**)&feat1, g_feat1);
    cudaGetSymbolAddress((void**)&yb,    g_y);
    cudaGetSymbolAddress((void**)&el1,   g_el1);
    cudaGetSymbolAddress((void**)&er1,   g_er1);
    cudaGetSymbolAddress((void**)&e1,    g_e1);
    cudaGetSymbolAddress((void**)&feat2, g_feat2);
    cudaGetSymbolAddress((void**)&res2,  g_res2);
    cudaGetSymbolAddress((void**)&el2,   g_el2);
    cudaGetSymbolAddress((void**)&er2,   g_er2);
    cudaGetSymbolAddress((void**)&e2,    g_e2);

    // CSR by dst (shared by both layers)
    zero_deg_kernel<<<(NN + 255) / 256, 256>>>();
    hist_kernel<<<(EE + 255) / 256, 256>>>(dst);
    scan_kernel<<<1, 1024>>>();
    cursor_copy_kernel<<<(NN + 255) / 256, 256>>>();
    scatter_kernel<<<(EE + 255) / 256, 256>>>(src, dst);

    // layer 1
    gemm_kernel<<<dim3(4, (NN + 63) / 64), 256>>>(x, W1, feat1, NN, 256, 256);
    attn_kernel<<<(NN * H1 * 32 + 255) / 256, 256>>>(feat1, al1, ar1, el1, er1, NN * H1, H1);
    escore_kernel<<<(EE * H1 + 255) / 256, 256>>>(src, dst, el1, er1, e1, EE * H1, H1);
    agg1_kernel<<<NN, 256>>>(x, b1);

    // layer 2
    gemm_kernel<<<dim3(1, (NN + 63) / 64), 256>>>(yb, W2, feat2, NN, 32, 256);
    gemm_kernel<<<dim3(1, (NN + 63) / 64), 256>>>(yb, resW2, res2, NN, 32, 256);
    attn_kernel<<<(NN * 32 + 255) / 256, 256>>>(feat2, al2, ar2, el2, er2, NN, 1);
    escore_kernel<<<(EE + 255) / 256, 256>>>(src, dst, el2, er2, e2, EE, 1);
    agg2_kernel<<<(NN * 32 + 255) / 256, 256>>>(b2, out);
}

// round 5
// speedup vs baseline: 1.3228x; 1.3221x over previous
#include <cuda_runtime.h>
#include <math.h>

#define NN 50000
#define EE 800000
#define H1 8
#define OUTD 32
#define NEG_SLOPE 0.2f

// ---------------- scratch (device globals; no allocation allowed) ----------------
__device__ float g_feat1[NN * 256];   // layer1 transformed features
__device__ float g_y[NN * 256];       // layer1 output (after relu)
__device__ float g_el1[NN * H1];
__device__ float g_er1[NN * H1];
__device__ float g_f2[NN * 64];       // [ feat2 (cols 0..31) | res2 (cols 32..63) ]
__device__ float g_el2[NN];
__device__ float g_er2[NN];
__device__ float g_wcat[256 * 64];    // [ W2 | resW2 ] concatenated
__device__ int   g_deg[NN];
__device__ int   g_rowoff[NN + 1];
__device__ int   g_cursor[NN];
__device__ int   g_csr_src[EE];

// ---------------- CSR build ----------------
__global__ void zero_deg_kernel() {
    int i = blockIdx.x * blockDim.x + threadIdx.x;
    if (i < NN) g_deg[i] = 0;
}

__global__ void hist_kernel(const int* __restrict__ dst) {
    int e = blockIdx.x * blockDim.x + threadIdx.x;
    if (e < EE) atomicAdd(&g_deg[dst[e]], 1);
}

__global__ void scan_kernel() {
    __shared__ int sm[1024];
    __shared__ int carry;
    int tid = threadIdx.x;
    if (tid == 0) carry = 0;
    __syncthreads();
    for (int base = 0; base < NN; base += 1024) {
        int i = base + tid;
        int v = (i < NN) ? g_deg[i] : 0;
        sm[tid] = v;
        __syncthreads();
        #pragma unroll
        for (int off = 1; off < 1024; off <<= 1) {
            int t2 = (tid >= off) ? sm[tid - off] : 0;
            __syncthreads();
            sm[tid] += t2;
            __syncthreads();
        }
        if (i < NN) g_rowoff[i] = carry + sm[tid] - v;   // exclusive
        __syncthreads();
        if (tid == 0) carry += sm[1023];
        __syncthreads();
    }
    if (tid == 0) g_rowoff[NN] = carry;
}

__global__ void cursor_copy_kernel() {
    int i = blockIdx.x * blockDim.x + threadIdx.x;
    if (i < NN) g_cursor[i] = g_rowoff[i];
}

__global__ void scatter_kernel(const int* __restrict__ src, const int* __restrict__ dst) {
    int e = blockIdx.x * blockDim.x + threadIdx.x;
    if (e < EE) {
        int d = dst[e];
        int slot = atomicAdd(&g_cursor[d], 1);
        g_csr_src[slot] = src[e];
    }
}

// ---------------- weight concat: g_wcat[r][c] = c<32 ? W2[r][c] : resW2[r][c-32] ----------------
__global__ void wcat_kernel(const float* __restrict__ W2, const float* __restrict__ resW2) {
    int i = blockIdx.x * blockDim.x + threadIdx.x;
    if (i < 256 * 64) {
        int r = i >> 6, c = i & 63;
        g_wcat[i] = (c < 32) ? W2[r * 32 + c] : resW2[r * 32 + (c - 32)];
    }
}

// ---------------- fp32 tiled GEMM: C[M,N] = A[M,K] @ B[K,N] ----------------
// 256 threads, (BM/TM)*(BN/TN)==256, BK=16, K%16==0, N%BN==0.
template<int BM, int BN, int TM, int TN>
__global__ void gemm_tile_kernel(const float* __restrict__ A, const float* __restrict__ B,
                                 float* __restrict__ C, int M, int N, int K) {
    constexpr int BK = 16;
    __shared__ float As[BK][BM + 4];
    __shared__ float Bs[BK][BN];
    constexpr int TX = BN / TN;
    constexpr int A_F4 = BM * BK / (256 * 4);
    constexpr int B_F4 = BK * BN / (256 * 4);
    int tid = threadIdx.x;
    int ty = tid / TX, tx = tid % TX;
    int row0 = blockIdx.y * BM, col0 = blockIdx.x * BN;
    float acc[TM][TN] = {};
    for (int k0 = 0; k0 < K; k0 += BK) {
        #pragma unroll
        for (int u = 0; u < A_F4; u++) {   // A tile [BM][BK], stored transposed
            int idx = (u * 256 + tid) * 4;
            int r = idx / BK, c = idx % BK;
            float4 v = make_float4(0.f, 0.f, 0.f, 0.f);
            if (row0 + r < M) v = *(const float4*)&A[(size_t)(row0 + r) * K + k0 + c];
            As[c + 0][r] = v.x; As[c + 1][r] = v.y; As[c + 2][r] = v.z; As[c + 3][r] = v.w;
        }
        #pragma unroll
        for (int u = 0; u < B_F4; u++) {   // B tile [BK][BN]
            int idx = (u * 256 + tid) * 4;
            int r = idx / BN, c = idx % BN;
            *(float4*)&Bs[r][c] = *(const float4*)&B[(size_t)(k0 + r) * N + col0 + c];
        }
        __syncthreads();
        #pragma unroll
        for (int k = 0; k < BK; k++) {
            float a[TM], b[TN];
            #pragma unroll
            for (int i = 0; i < TM; i++) a[i] = As[k][ty * TM + i];
            #pragma unroll
            for (int j = 0; j < TN; j++) b[j] = Bs[k][tx * TN + j];
            #pragma unroll
            for (int i = 0; i < TM; i++)
                #pragma unroll
                for (int j = 0; j < TN; j++) acc[i][j] += a[i] * b[j];
        }
        __syncthreads();
    }
    #pragma unroll
    for (int i = 0; i < TM; i++) {
        int gr = row0 + ty * TM + i;
        if (gr >= M) continue;
        #pragma unroll
        for (int j = 0; j < TN; j += 4)
            *(float4*)&C[(size_t)gr * N + col0 + tx * TN + j] =
                make_float4(acc[i][j], acc[i][j + 1], acc[i][j + 2], acc[i][j + 3]);
    }
}

// ---------------- attention logits: el/er per (node, head), D=32 ----------------
__global__ void attn_kernel(const float* __restrict__ feat, const float* __restrict__ al,
                            const float* __restrict__ ar, float* __restrict__ el,
                            float* __restrict__ er, int NH, int H, int stride) {
    int t = blockIdx.x * blockDim.x + threadIdx.x;
    int w = t >> 5;
    if (w >= NH) return;
    int lane = t & 31;
    int node = w / H;
    int h = w - node * H;
    float f  = feat[(size_t)node * stride + h * 32 + lane];
    float s1 = f * al[h * 32 + lane];
    float s2 = f * ar[h * 32 + lane];
    #pragma unroll
    for (int o = 16; o; o >>= 1) {
        s1 += __shfl_xor_sync(0xffffffffu, s1, o);
        s2 += __shfl_xor_sync(0xffffffffu, s2, o);
    }
    if (lane == 0) { el[w] = s1; er[w] = s2; }
}

// ---------------- layer1 fused softmax+aggregate: 1 block/node, warp=head, ONE pass ----------------
// Softmax without max-subtraction: logits bounded (|e| ~ O(3)), exp(e)/sum exp(e)
// is mathematically identical to the max-shifted reference formula.
__global__ void agg1_kernel(const float* __restrict__ x, const float* __restrict__ b1) {
    int n = blockIdx.x;
    int h = threadIdx.x >> 5;
    int lane = threadIdx.x & 31;
    int beg = g_rowoff[n], end = g_rowoff[n + 1];
    float ern = g_er1[n * H1 + h];
    float s = 0.f, acc = 0.f;
    int i = beg;
    for (; i + 1 < end; i += 2) {          // 2x unroll for gather MLP
        int s0 = g_csr_src[i], s1 = g_csr_src[i + 1];
        float e0 = g_el1[s0 * H1 + h] + ern;
        float e1 = g_el1[s1 * H1 + h] + ern;
        e0 = e0 > 0.f ? e0 : NEG_SLOPE * e0;
        e1 = e1 > 0.f ? e1 : NEG_SLOPE * e1;
        float w0 = __expf(e0), w1 = __expf(e1);
        float f0 = g_feat1[(size_t)s0 * 256 + h * 32 + lane];
        float f1 = g_feat1[(size_t)s1 * 256 + h * 32 + lane];
        s   += w0 + w1;
        acc += w0 * f0 + w1 * f1;
    }
    if (i < end) {
        int s0 = g_csr_src[i];
        float e0 = g_el1[s0 * H1 + h] + ern;
        e0 = e0 > 0.f ? e0 : NEG_SLOPE * e0;
        float w0 = __expf(e0);
        s   += w0;
        acc += w0 * g_feat1[(size_t)s0 * 256 + h * 32 + lane];
    }
    float inv = (end > beg) ? 1.0f / s : 0.f;
    int o = n * 256 + h * 32 + lane;
    float r = acc * inv + x[o] + b1[h * 32 + lane];   // identity residual + bias
    g_y[o] = fmaxf(r, 0.f);                            // inter-layer relu
}

// ---------------- layer2 fused softmax+aggregate: warp per node (H=1, D=32), ONE pass ----------------
__global__ void agg2_kernel(const float* __restrict__ b2, float* __restrict__ out) {
    int t = blockIdx.x * blockDim.x + threadIdx.x;
    int n = t >> 5;
    if (n >= NN) return;
    int lane = t & 31;
    int beg = g_rowoff[n], end = g_rowoff[n + 1];
    float ern = g_er2[n];
    float s = 0.f, acc = 0.f;
    int i = beg;
    for (; i + 1 < end; i += 2) {
        int s0 = g_csr_src[i], s1 = g_csr_src[i + 1];
        float e0 = g_el2[s0] + ern;
        float e1 = g_el2[s1] + ern;
        e0 = e0 > 0.f ? e0 : NEG_SLOPE * e0;
        e1 = e1 > 0.f ? e1 : NEG_SLOPE * e1;
        float w0 = __expf(e0), w1 = __expf(e1);
        float f0 = g_f2[(size_t)s0 * 64 + lane];
        float f1 = g_f2[(size_t)s1 * 64 + lane];
        s   += w0 + w1;
        acc += w0 * f0 + w1 * f1;
    }
    if (i < end) {
        int s0 = g_csr_src[i];
        float e0 = g_el2[s0] + ern;
        e0 = e0 > 0.f ? e0 : NEG_SLOPE * e0;
        float w0 = __expf(e0);
        s   += w0;
        acc += w0 * g_f2[(size_t)s0 * 64 + lane];
    }
    float inv = (end > beg) ? 1.0f / s : 0.f;
    // res2 lives in cols 32..63 of g_f2
    out[n * 32 + lane] = acc * inv + g_f2[(size_t)n * 64 + 32 + lane] + b2[lane];
}

// ---------------- launch ----------------
extern "C" void kernel_launch(void* const* d_in, const int* in_sizes, int n_in,
                              void* d_out, int out_size) {
    const float* x     = (const float*)d_in[0];
    const int*   src   = (const int*)d_in[1];
    const int*   dst   = (const int*)d_in[2];
    const float* W1    = (const float*)d_in[3];
    const float* al1   = (const float*)d_in[4];
    const float* ar1   = (const float*)d_in[5];
    const float* b1    = (const float*)d_in[6];
    const float* W2    = (const float*)d_in[7];
    const float* al2   = (const float*)d_in[8];
    const float* ar2   = (const float*)d_in[9];
    const float* resW2 = (const float*)d_in[10];
    const float* b2    = (const float*)d_in[11];
    float* out = (float*)d_out;

    float *feat1, *yb, *el1, *er1, *f2, *el2, *er2, *wcat;
    cudaGetSymbolAddress((void**)&feat1, g_feat1);
    cudaGetSymbolAddress((void**)&yb,    g_y);
    cudaGetSymbolAddress((void**)&el1,   g_el1);
    cudaGetSymbolAddress((void**)&er1,   g_er1);
    cudaGetSymbolAddress((void**)&f2,    g_f2);
    cudaGetSymbolAddress((void**)&el2,   g_el2);
    cudaGetSymbolAddress((void**)&er2,   g_er2);
    cudaGetSymbolAddress((void**)&wcat,  g_wcat);

    // CSR by dst (shared by both layers) + weight concat
    zero_deg_kernel<<<(NN + 255) / 256, 256>>>();
    hist_kernel<<<(EE + 255) / 256, 256>>>(dst);
    scan_kernel<<<1, 1024>>>();
    cursor_copy_kernel<<<(NN + 255) / 256, 256>>>();
    scatter_kernel<<<(EE + 255) / 256, 256>>>(src, dst);
    wcat_kernel<<<(256 * 64 + 255) / 256, 256>>>(W2, resW2);

    // layer 1
    gemm_tile_kernel<128, 128, 8, 8><<<dim3(2, (NN + 127) / 128), 256>>>(x, W1, feat1, NN, 256, 256);
    attn_kernel<<<(NN * H1 * 32 + 255) / 256, 256>>>(feat1, al1, ar1, el1, er1, NN * H1, H1, 256);
    agg1_kernel<<<NN, 256>>>(x, b1);

    // layer 2 (W2 and resW2 fused into one N=64 GEMM)
    gemm_tile_kernel<128, 64, 8, 4><<<dim3(1, (NN + 127) / 128), 256>>>(yb, wcat, f2, NN, 64, 256);
    attn_kernel<<<(NN * 32 + 255) / 256, 256>>>(f2, al2, ar2, el2, er2, NN, 1, 64);
    agg2_kernel<<<(NN * 32 + 255) / 256, 256>>>(b2, out);
}

// round 7
// speedup vs baseline: 1.5135x; 1.1441x over previous
#include <cuda_runtime.h>
#include <cuda_bf16.h>
#include <math.h>
#include <stdint.h>

#define NN 50000
#define EE 800000
#define H1 8
#define NEG_SLOPE 0.2f

// ---------------- scratch (device globals; no allocation allowed) ----------------
__device__ float g_feat1[NN * 256];           // layer1 transformed features (fp32)
__device__ __nv_bfloat16 g_ah[NN * 256];      // split-bf16 hi of GEMM A (x, then y)
__device__ __nv_bfloat16 g_al[NN * 256];      // split-bf16 lo
__device__ float g_el1[NN * H1];
__device__ float g_er1[NN * H1];
__device__ float g_f2[NN * 64];               // [ feat2 (0..31) | res2 (32..63) ]
__device__ float g_el2[NN];
__device__ float g_er2[NN];
__device__ __nv_bfloat16 g_w1t_h[256 * 256];  // W1^T [n][k] bf16 hi/lo
__device__ __nv_bfloat16 g_w1t_l[256 * 256];
__device__ __nv_bfloat16 g_wct_h[64 * 256];   // [W2|resW2]^T [n][k] bf16 hi/lo
__device__ __nv_bfloat16 g_wct_l[64 * 256];
__device__ int   g_deg[NN];
__device__ int   g_rowoff[NN + 1];
__device__ int   g_cursor[NN];
__device__ int   g_csr_src[EE];

// ---------------- helpers ----------------
__device__ __forceinline__ uint32_t smem_u32(const void* p) {
    uint32_t a;
    asm("{ .reg .u64 t; cvta.to.shared.u64 t, %1; cvt.u32.u64 %0, t; }" : "=r"(a) : "l"(p));
    return a;
}
__device__ __forceinline__ void ldsm_x4(uint32_t (&r)[4], const void* p) {
    uint32_t a = smem_u32(p);
    asm volatile("ldmatrix.sync.aligned.m8n8.x4.shared.b16 {%0,%1,%2,%3}, [%4];"
                 : "=r"(r[0]), "=r"(r[1]), "=r"(r[2]), "=r"(r[3]) : "r"(a));
}
__device__ __forceinline__ void mma_bf16(float (&d)[4], const uint32_t (&a)[4],
                                         uint32_t b0, uint32_t b1) {
    asm volatile("mma.sync.aligned.m16n8k16.row.col.f32.bf16.bf16.f32 "
                 "{%0,%1,%2,%3},{%4,%5,%6,%7},{%8,%9},{%0,%1,%2,%3};"
                 : "+f"(d[0]), "+f"(d[1]), "+f"(d[2]), "+f"(d[3])
                 : "r"(a[0]), "r"(a[1]), "r"(a[2]), "r"(a[3]), "r"(b0), "r"(b1));
}
__device__ __forceinline__ void split_bf16(float v, __nv_bfloat16& h, __nv_bfloat16& l) {
    h = __float2bfloat16(v);
    l = __float2bfloat16(v - __bfloat162float(h));
}

// ============ split-bf16 tensor-core GEMM: C[M,N] = A[M,256] @ B[256,N] ============
// A given as bf16 hi/lo [M][256]; B given TRANSPOSED bf16 hi/lo [N][256].
// 3-term split: D = AhBh + AlBh + AhBl (AlBl ~2^-16 rel, dropped).
// BM=128, BK=32, 8 warps as 4(M) x 2(N); warp tile 32 x BN/2.
template<int BN>
__global__ void __launch_bounds__(256) mma_gemm_kernel(
        const __nv_bfloat16* __restrict__ Ah, const __nv_bfloat16* __restrict__ Al,
        const __nv_bfloat16* __restrict__ Bth, const __nv_bfloat16* __restrict__ Btl,
        float* __restrict__ C, int M, int N) {
    constexpr int LDS = 40;          // 32 + 8 pad -> 80B rows, LDSM conflict-free
    constexpr int WN  = BN / 2;      // warp n tile
    constexpr int NJ  = WN / 16;     // n16 groups per warp
    __shared__ __nv_bfloat16 sAh[128][LDS], sAl[128][LDS];
    __shared__ __nv_bfloat16 sBh[BN][LDS], sBl[BN][LDS];

    int tid = threadIdx.x, lane = tid & 31, wid = tid >> 5;
    int wm = wid & 3, wn = wid >> 2;
    int row0 = blockIdx.y * 128, col0 = blockIdx.x * BN;
    float acc[2][2 * NJ][4] = {};

    for (int k0 = 0; k0 < 256; k0 += 32) {
        // ---- load A tile (128 x 32), 16B per thread-iter, zero-pad rows >= M ----
        #pragma unroll
        for (int t = 0; t < 2; t++) {
            int v = tid + t * 256;
            int r = v >> 2, c = (v & 3) * 8;
            uint4 vh = make_uint4(0, 0, 0, 0), vl = make_uint4(0, 0, 0, 0);
            if (row0 + r < M) {
                vh = *(const uint4*)&Ah[(size_t)(row0 + r) * 256 + k0 + c];
                vl = *(const uint4*)&Al[(size_t)(row0 + r) * 256 + k0 + c];
            }
            *(uint4*)&sAh[r][c] = vh;
            *(uint4*)&sAl[r][c] = vl;
        }
        // ---- load B^T tile (BN x 32); N always multiple of BN ----
        #pragma unroll
        for (int t = 0; t < BN / 64; t++) {
            int v = tid + t * 256;
            int r = v >> 2, c = (v & 3) * 8;
            *(uint4*)&sBh[r][c] = *(const uint4*)&Bth[(size_t)(col0 + r) * 256 + k0 + c];
            *(uint4*)&sBl[r][c] = *(const uint4*)&Btl[(size_t)(col0 + r) * 256 + k0 + c];
        }
        __syncthreads();

        #pragma unroll
        for (int kk = 0; kk < 2; kk++) {
            int kc = kk * 16 + (lane >> 4) * 8;
            uint32_t ah[2][4], al[2][4];
            #pragma unroll
            for (int mi = 0; mi < 2; mi++) {
                int r = wm * 32 + mi * 16 + (lane & 15);
                ldsm_x4(ah[mi], &sAh[r][kc]);
                ldsm_x4(al[mi], &sAl[r][kc]);
            }
            #pragma unroll
            for (int nj = 0; nj < NJ; nj++) {
                uint32_t bh[4], bl[4];
                int r = wn * WN + nj * 16 + (lane & 15);
                ldsm_x4(bh, &sBh[r][kc]);
                ldsm_x4(bl, &sBl[r][kc]);
                #pragma unroll
                for (int half = 0; half < 2; half++) {
                    #pragma unroll
                    for (int mi = 0; mi < 2; mi++) {
                        float (&d)[4] = acc[mi][nj * 2 + half];
                        mma_bf16(d, ah[mi], bh[half], bh[2 + half]);
                        mma_bf16(d, al[mi], bh[half], bh[2 + half]);
                        mma_bf16(d, ah[mi], bl[half], bl[2 + half]);
                    }
                }
            }
        }
        __syncthreads();
    }

    // ---- epilogue: m16n8 fragment -> thread holds (row lane/4 [+8], cols (lane%3)*2..) ----
    #pragma unroll
    for (int mi = 0; mi < 2; mi++) {
        #pragma unroll
        for (int f = 0; f < 2 * NJ; f++) {
            int r0 = row0 + wm * 32 + mi * 16 + (lane >> 2);
            int c  = col0 + wn * WN + f * 8 + (lane & 3) * 2;
            if (r0 < M)
                *(float2*)&C[(size_t)r0 * N + c] = make_float2(acc[mi][f][0], acc[mi][f][1]);
            if (r0 + 8 < M)
                *(float2*)&C[(size_t)(r0 + 8) * N + c] = make_float2(acc[mi][f][2], acc[mi][f][3]);
        }
    }
}

// ---------------- conversion prepasses ----------------
__global__ void convert_x_kernel(const float* __restrict__ x) {
    int i = blockIdx.x * blockDim.x + threadIdx.x;
    if (i < NN * 256) split_bf16(x[i], g_ah[i], g_al[i]);
}
__global__ void convert_w1_kernel(const float* __restrict__ W1) {
    int i = blockIdx.x * blockDim.x + threadIdx.x;   // i = n*256 + k
    if (i < 256 * 256) {
        int n = i >> 8, k = i & 255;
        split_bf16(W1[k * 256 + n], g_w1t_h[i], g_w1t_l[i]);
    }
}
__global__ void convert_wcat_kernel(const float* __restrict__ W2, const float* __restrict__ resW2) {
    int i = blockIdx.x * blockDim.x + threadIdx.x;   // i = n*256 + k, n < 64
    if (i < 64 * 256) {
        int n = i >> 8, k = i & 255;
        float v = (n < 32) ? W2[k * 32 + n] : resW2[k * 32 + (n - 32)];
        split_bf16(v, g_wct_h[i], g_wct_l[i]);
    }
}

// ---------------- CSR build ----------------
__global__ void zero_deg_kernel() {
    int i = blockIdx.x * blockDim.x + threadIdx.x;
    if (i < NN) g_deg[i] = 0;
}
__global__ void hist_kernel(const int* __restrict__ dst) {
    int e = blockIdx.x * blockDim.x + threadIdx.x;
    if (e < EE) atomicAdd(&g_deg[dst[e]], 1);
}
__global__ void scan_kernel() {
    __shared__ int sm[1024];
    __shared__ int carry;
    int tid = threadIdx.x;
    if (tid == 0) carry = 0;
    __syncthreads();
    for (int base = 0; base < NN; base += 1024) {
        int i = base + tid;
        int v = (i < NN) ? g_deg[i] : 0;
        sm[tid] = v;
        __syncthreads();
        #pragma unroll
        for (int off = 1; off < 1024; off <<= 1) {
            int t2 = (tid >= off) ? sm[tid - off] : 0;
            __syncthreads();
            sm[tid] += t2;
            __syncthreads();
        }
        if (i < NN) g_rowoff[i] = carry + sm[tid] - v;   // exclusive
        __syncthreads();
        if (tid == 0) carry += sm[1023];
        __syncthreads();
    }
    if (tid == 0) g_rowoff[NN] = carry;
}
__global__ void cursor_copy_kernel() {
    int i = blockIdx.x * blockDim.x + threadIdx.x;
    if (i < NN) g_cursor[i] = g_rowoff[i];
}
__global__ void scatter_kernel(const int* __restrict__ src, const int* __restrict__ dst) {
    int e = blockIdx.x * blockDim.x + threadIdx.x;
    if (e < EE) {
        int d = dst[e];
        int slot = atomicAdd(&g_cursor[d], 1);
        g_csr_src[slot] = src[e];
    }
}

// ---------------- attention logits: el/er per (node, head), D=32 ----------------
__global__ void attn_kernel(const float* __restrict__ feat, const float* __restrict__ al,
                            const float* __restrict__ ar, float* __restrict__ el,
                            float* __restrict__ er, int NH, int H, int stride) {
    int t = blockIdx.x * blockDim.x + threadIdx.x;
    int w = t >> 5;
    if (w >= NH) return;
    int lane = t & 31;
    int node = w / H;
    int h = w - node * H;
    float f  = feat[(size_t)node * stride + h * 32 + lane];
    float s1 = f * al[h * 32 + lane];
    float s2 = f * ar[h * 32 + lane];
    #pragma unroll
    for (int o = 16; o; o >>= 1) {
        s1 += __shfl_xor_sync(0xffffffffu, s1, o);
        s2 += __shfl_xor_sync(0xffffffffu, s2, o);
    }
    if (lane == 0) { el[w] = s1; er[w] = s2; }
}

// ---------------- layer1 fused softmax+aggregate: 1 block/node, warp=head, one pass ----
// Output written directly as split-bf16 (feeds layer2 GEMM without a convert pass).
__global__ void agg1_kernel(const float* __restrict__ x, const float* __restrict__ b1) {
    int n = blockIdx.x;
    int h = threadIdx.x >> 5;
    int lane = threadIdx.x & 31;
    int beg = g_rowoff[n], end = g_rowoff[n + 1];
    float ern = g_er1[n * H1 + h];
    float s = 0.f, acc = 0.f;
    int i = beg;
    for (; i + 1 < end; i += 2) {
        int s0 = g_csr_src[i], s1 = g_csr_src[i + 1];
        float e0 = g_el1[s0 * H1 + h] + ern;
        float e1 = g_el1[s1 * H1 + h] + ern;
        e0 = e0 > 0.f ? e0 : NEG_SLOPE * e0;
        e1 = e1 > 0.f ? e1 : NEG_SLOPE * e1;
        float w0 = __expf(e0), w1 = __expf(e1);
        float f0 = g_feat1[(size_t)s0 * 256 + h * 32 + lane];
        float f1 = g_feat1[(size_t)s1 * 256 + h * 32 + lane];
        s   += w0 + w1;
        acc += w0 * f0 + w1 * f1;
    }
    if (i < end) {
        int s0 = g_csr_src[i];
        float e0 = g_el1[s0 * H1 + h] + ern;
        e0 = e0 > 0.f ? e0 : NEG_SLOPE * e0;
        float w0 = __expf(e0);
        s   += w0;
        acc += w0 * g_feat1[(size_t)s0 * 256 + h * 32 + lane];
    }
    float inv = (end > beg) ? 1.0f / s : 0.f;
    int o = n * 256 + h * 32 + lane;
    float r = fmaxf(acc * inv + x[o] + b1[h * 32 + lane], 0.f);   // residual + bias + relu
    split_bf16(r, g_ah[o], g_al[o]);                               // overwrite x-split (done with it)
}

// ---------------- layer2 fused softmax+aggregate: warp per node ----------------
__global__ void agg2_kernel(const float* __restrict__ b2, float* __restrict__ out) {
    int t = blockIdx.x * blockDim.x + threadIdx.x;
    int n = t >> 5;
    if (n >= NN) return;
    int lane = t & 31;
    int beg = g_rowoff[n], end = g_rowoff[n + 1];
    float ern = g_er2[n];
    float s = 0.f, acc = 0.f;
    int i = beg;
    for (; i + 1 < end; i += 2) {
        int s0 = g_csr_src[i], s1 = g_csr_src[i + 1];
        float e0 = g_el2[s0] + ern;
        float e1 = g_el2[s1] + ern;
        e0 = e0 > 0.f ? e0 : NEG_SLOPE * e0;
        e1 = e1 > 0.f ? e1 : NEG_SLOPE * e1;
        float w0 = __expf(e0), w1 = __expf(e1);
        float f0 = g_f2[(size_t)s0 * 64 + lane];
        float f1 = g_f2[(size_t)s1 * 64 + lane];
        s   += w0 + w1;
        acc += w0 * f0 + w1 * f1;
    }
    if (i < end) {
        int s0 = g_csr_src[i];
        float e0 = g_el2[s0] + ern;
        e0 = e0 > 0.f ? e0 : NEG_SLOPE * e0;
        float w0 = __expf(e0);
        s   += w0;
        acc += w0 * g_f2[(size_t)s0 * 64 + lane];
    }
    float inv = (end > beg) ? 1.0f / s : 0.f;
    out[n * 32 + lane] = acc * inv + g_f2[(size_t)n * 64 + 32 + lane] + b2[lane];
}

// ---------------- launch ----------------
extern "C" void kernel_launch(void* const* d_in, const int* in_sizes, int n_in,
                              void* d_out, int out_size) {
    const float* x     = (const float*)d_in[0];
    const int*   src   = (const int*)d_in[1];
    const int*   dst   = (const int*)d_in[2];
    const float* W1    = (const float*)d_in[3];
    const float* al1   = (const float*)d_in[4];
    const float* ar1   = (const float*)d_in[5];
    const float* b1    = (const float*)d_in[6];
    const float* W2    = (const float*)d_in[7];
    const float* al2   = (const float*)d_in[8];
    const float* ar2   = (const float*)d_in[9];
    const float* resW2 = (const float*)d_in[10];
    const float* b2    = (const float*)d_in[11];
    float* out = (float*)d_out;

    float *feat1, *el1, *er1, *f2, *el2, *er2;
    __nv_bfloat16 *ah, *al, *w1h, *w1l, *wch, *wcl;
    cudaGetSymbolAddress((void**)&feat1, g_feat1);
    cudaGetSymbolAddress((void**)&el1,   g_el1);
    cudaGetSymbolAddress((void**)&er1,   g_er1);
    cudaGetSymbolAddress((void**)&f2,    g_f2);
    cudaGetSymbolAddress((void**)&el2,   g_el2);
    cudaGetSymbolAddress((void**)&er2,   g_er2);
    cudaGetSymbolAddress((void**)&ah,    g_ah);
    cudaGetSymbolAddress((void**)&al,    g_al);
    cudaGetSymbolAddress((void**)&w1h,   g_w1t_h);
    cudaGetSymbolAddress((void**)&w1l,   g_w1t_l);
    cudaGetSymbolAddress((void**)&wch,   g_wct_h);
    cudaGetSymbolAddress((void**)&wcl,   g_wct_l);

    // CSR build + weight/input conversion (independent of each other)
    zero_deg_kernel<<<(NN + 255) / 256, 256>>>();
    hist_kernel<<<(EE + 255) / 256, 256>>>(dst);
    scan_kernel<<<1, 1024>>>();
    cursor_copy_kernel<<<(NN + 255) / 256, 256>>>();
    scatter_kernel<<<(EE + 255) / 256, 256>>>(src, dst);
    convert_x_kernel<<<(NN * 256 + 255) / 256, 256>>>(x);
    convert_w1_kernel<<<(256 * 256 + 255) / 256, 256>>>(W1);
    convert_wcat_kernel<<<(64 * 256 + 255) / 256, 256>>>(W2, resW2);

    // layer 1: feat1 = x @ W1 (tensor-core split-bf16)
    mma_gemm_kernel<128><<<dim3(2, (NN + 127) / 128), 256>>>(ah, al, w1h, w1l, feat1, NN, 256);
    attn_kernel<<<(NN * H1 * 32 + 255) / 256, 256>>>(feat1, al1, ar1, el1, er1, NN * H1, H1, 256);
    agg1_kernel<<<NN, 256>>>(x, b1);   // writes y as split-bf16 into g_ah/g_al

    // layer 2: f2 = y @ [W2|resW2]
    mma_gemm_kernel<64><<<dim3(1, (NN + 127) / 128), 256>>>(ah, al, wch, wcl, f2, NN, 64);
    attn_kernel<<<(NN * 32 + 255) / 256, 256>>>(f2, al2, ar2, el2, er2, NN, 1, 64);
    agg2_kernel<<<(NN * 32 + 255) / 256, 256>>>(b2, out);
}

// round 8
// speedup vs baseline: 1.7738x; 1.1720x over previous
#include <cuda_runtime.h>
#include <cuda_bf16.h>
#include <math.h>
#include <stdint.h>

#define NN 50000
#define EE 800000
#define H1 8
#define NEG_SLOPE 0.2f
#define SCAN_BC ((NN + 1023) / 1024)   // 49

// ---------------- scratch (device globals; no allocation allowed) ----------------
__device__ float g_feat1[NN * 256];           // layer1 transformed features (fp32)
__device__ float g_y[NN * 256];               // layer1 output (fp32, after relu)
__device__ float g_el1[NN * H1];
__device__ float g_er1[NN * H1];
__device__ float g_f2[NN * 64];               // [ feat2 (0..31) | res2 (32..63) ]
__device__ float g_el2[NN];
__device__ float g_er2[NN];
__device__ __nv_bfloat16 g_w1t_h[256 * 256];  // W1^T [n][k] bf16 hi/lo
__device__ __nv_bfloat16 g_w1t_l[256 * 256];
__device__ __nv_bfloat16 g_wct_h[64 * 256];   // [W2|resW2]^T [n][k] bf16 hi/lo
__device__ __nv_bfloat16 g_wct_l[64 * 256];
__device__ int   g_deg[NN];
__device__ int   g_rowoff[NN + 1];
__device__ int   g_cursor[NN];
__device__ int   g_csr_src[EE];
__device__ int   g_bsum[SCAN_BC];
__device__ int   g_boff[SCAN_BC];

// ---------------- helpers ----------------
__device__ __forceinline__ uint32_t smem_u32(const void* p) {
    uint32_t a;
    asm("{ .reg .u64 t; cvta.to.shared.u64 t, %1; cvt.u32.u64 %0, t; }" : "=r"(a) : "l"(p));
    return a;
}
__device__ __forceinline__ void ldsm_x4(uint32_t (&r)[4], const void* p) {
    uint32_t a = smem_u32(p);
    asm volatile("ldmatrix.sync.aligned.m8n8.x4.shared.b16 {%0,%1,%2,%3}, [%4];"
                 : "=r"(r[0]), "=r"(r[1]), "=r"(r[2]), "=r"(r[3]) : "r"(a));
}
__device__ __forceinline__ void mma_bf16(float (&d)[4], const uint32_t (&a)[4],
                                         uint32_t b0, uint32_t b1) {
    asm volatile("mma.sync.aligned.m16n8k16.row.col.f32.bf16.bf16.f32 "
                 "{%0,%1,%2,%3},{%4,%5,%6,%7},{%8,%9},{%0,%1,%2,%3};"
                 : "+f"(d[0]), "+f"(d[1]), "+f"(d[2]), "+f"(d[3])
                 : "r"(a[0]), "r"(a[1]), "r"(a[2]), "r"(a[3]), "r"(b0), "r"(b1));
}
__device__ __forceinline__ void split_bf16(float v, __nv_bfloat16& h, __nv_bfloat16& l) {
    h = __float2bfloat16(v);
    l = __float2bfloat16(v - __bfloat162float(h));
}

// ============ split-bf16 tensor-core GEMM: C[M,N] = A[M,256] @ B[256,N] ============
// A is fp32 [M][256] (split to bf16 hi/lo in-register while staging to smem).
// B given TRANSPOSED as precomputed bf16 hi/lo [N][256].
// 3-term split: D = AhBh + AlBh + AhBl.  BM=128, BK=32, 8 warps as 4(M) x 2(N).
template<int BN>
__global__ void __launch_bounds__(256) mma_gemm_kernel(
        const float* __restrict__ A,
        const __nv_bfloat16* __restrict__ Bth, const __nv_bfloat16* __restrict__ Btl,
        float* __restrict__ C, int M, int N) {
    constexpr int LDS = 40;          // 32 + 8 pad -> 80B rows, LDSM conflict-free
    constexpr int WN  = BN / 2;      // warp n tile
    constexpr int NJ  = WN / 16;     // n16 groups per warp
    __shared__ __nv_bfloat16 sAh[128][LDS], sAl[128][LDS];
    __shared__ __nv_bfloat16 sBh[BN][LDS], sBl[BN][LDS];

    int tid = threadIdx.x, lane = tid & 31, wid = tid >> 5;
    int wm = wid & 3, wn = wid >> 2;
    int row0 = blockIdx.y * 128, col0 = blockIdx.x * BN;
    float acc[2][2 * NJ][4] = {};

    for (int k0 = 0; k0 < 256; k0 += 32) {
        // ---- load A tile fp32 (128 x 32) and split to hi/lo bf16 in-register ----
        #pragma unroll
        for (int t = 0; t < 2; t++) {
            int v = tid + t * 256;
            int r = v >> 2, c = (v & 3) * 8;
            float4 f0 = make_float4(0.f, 0.f, 0.f, 0.f), f1 = f0;
            if (row0 + r < M) {
                const float* ap = &A[(size_t)(row0 + r) * 256 + k0 + c];
                f0 = *(const float4*)ap;
                f1 = *(const float4*)(ap + 4);
            }
            float fv[8] = {f0.x, f0.y, f0.z, f0.w, f1.x, f1.y, f1.z, f1.w};
            union { __nv_bfloat16 b[8]; uint4 u; } uh, ul;
            #pragma unroll
            for (int e = 0; e < 8; e++) split_bf16(fv[e], uh.b[e], ul.b[e]);
            *(uint4*)&sAh[r][c] = uh.u;
            *(uint4*)&sAl[r][c] = ul.u;
        }
        // ---- load B^T tile (BN x 32) bf16 hi/lo ----
        #pragma unroll
        for (int t = 0; t < BN / 64; t++) {
            int v = tid + t * 256;
            int r = v >> 2, c = (v & 3) * 8;
            *(uint4*)&sBh[r][c] = *(const uint4*)&Bth[(size_t)(col0 + r) * 256 + k0 + c];
            *(uint4*)&sBl[r][c] = *(const uint4*)&Btl[(size_t)(col0 + r) * 256 + k0 + c];
        }
        __syncthreads();

        #pragma unroll
        for (int kk = 0; kk < 2; kk++) {
            int kc = kk * 16 + (lane >> 4) * 8;
            uint32_t ah[2][4], al[2][4];
            #pragma unroll
            for (int mi = 0; mi < 2; mi++) {
                int r = wm * 32 + mi * 16 + (lane & 15);
                ldsm_x4(ah[mi], &sAh[r][kc]);
                ldsm_x4(al[mi], &sAl[r][kc]);
            }
            #pragma unroll
            for (int nj = 0; nj < NJ; nj++) {
                uint32_t bh[4], bl[4];
                int r = wn * WN + nj * 16 + (lane & 15);
                ldsm_x4(bh, &sBh[r][kc]);
                ldsm_x4(bl, &sBl[r][kc]);
                #pragma unroll
                for (int half = 0; half < 2; half++) {
                    #pragma unroll
                    for (int mi = 0; mi < 2; mi++) {
                        float (&d)[4] = acc[mi][nj * 2 + half];
                        mma_bf16(d, ah[mi], bh[half], bh[2 + half]);
                        mma_bf16(d, al[mi], bh[half], bh[2 + half]);
                        mma_bf16(d, ah[mi], bl[half], bl[2 + half]);
                    }
                }
            }
        }
        __syncthreads();
    }

    // ---- epilogue ----
    #pragma unroll
    for (int mi = 0; mi < 2; mi++) {
        #pragma unroll
        for (int f = 0; f < 2 * NJ; f++) {
            int r0 = row0 + wm * 32 + mi * 16 + (lane >> 2);
            int c  = col0 + wn * WN + f * 8 + (lane & 3) * 2;
            if (r0 < M)
                *(float2*)&C[(size_t)r0 * N + c] = make_float2(acc[mi][f][0], acc[mi][f][1]);
            if (r0 + 8 < M)
                *(float2*)&C[(size_t)(r0 + 8) * N + c] = make_float2(acc[mi][f][2], acc[mi][f][3]);
        }
    }
}

// ---------------- weight conversion prepasses ----------------
__global__ void convert_w1_kernel(const float* __restrict__ W1) {
    int i = blockIdx.x * blockDim.x + threadIdx.x;   // i = n*256 + k
    if (i < 256 * 256) {
        int n = i >> 8, k = i & 255;
        split_bf16(W1[k * 256 + n], g_w1t_h[i], g_w1t_l[i]);
    }
}
__global__ void convert_wcat_kernel(const float* __restrict__ W2, const float* __restrict__ resW2) {
    int i = blockIdx.x * blockDim.x + threadIdx.x;   // i = n*256 + k, n < 64
    if (i < 64 * 256) {
        int n = i >> 8, k = i & 255;
        float v = (n < 32) ? W2[k * 32 + n] : resW2[k * 32 + (n - 32)];
        split_bf16(v, g_wct_h[i], g_wct_l[i]);
    }
}

// ---------------- CSR build ----------------
__global__ void zero_deg_kernel() {
    int i = blockIdx.x * blockDim.x + threadIdx.x;
    if (i < NN) g_deg[i] = 0;
}
__global__ void hist_kernel(const int* __restrict__ dst) {
    int e = blockIdx.x * blockDim.x + threadIdx.x;
    if (e < EE) atomicAdd(&g_deg[dst[e]], 1);
}
// 3-phase multi-block exclusive scan of g_deg -> g_rowoff (+ g_cursor)
__global__ void scan1_kernel() {          // grid SCAN_BC, block 1024
    __shared__ int sm[1024];
    int b = blockIdx.x, tid = threadIdx.x;
    int i = b * 1024 + tid;
    int v = (i < NN) ? g_deg[i] : 0;
    sm[tid] = v;
    __syncthreads();
    #pragma unroll
    for (int off = 1; off < 1024; off <<= 1) {
        int t2 = (tid >= off) ? sm[tid - off] : 0;
        __syncthreads();
        sm[tid] += t2;
        __syncthreads();
    }
    if (i < NN) g_rowoff[i] = sm[tid] - v;       // block-local exclusive
    if (tid == 1023) g_bsum[b] = sm[1023];
}
__global__ void scan2_kernel() {          // 1 block, 64 threads
    __shared__ int sm[64];
    int tid = threadIdx.x;
    int v = (tid < SCAN_BC) ? g_bsum[tid] : 0;
    sm[tid] = v;
    __syncthreads();
    #pragma unroll
    for (int off = 1; off < 64; off <<= 1) {
        int t2 = (tid >= off) ? sm[tid - off] : 0;
        __syncthreads();
        sm[tid] += t2;
        __syncthreads();
    }
    if (tid < SCAN_BC) g_boff[tid] = sm[tid] - v;
    if (tid == SCAN_BC - 1) g_rowoff[NN] = sm[tid];   // total = EE
}
__global__ void scan3_kernel() {          // grid SCAN_BC, block 1024; fuses cursor init
    int b = blockIdx.x;
    int i = b * 1024 + threadIdx.x;
    if (i < NN) {
        int r = g_rowoff[i] + g_boff[b];
        g_rowoff[i] = r;
        g_cursor[i] = r;
    }
}
__global__ void scatter_kernel(const int* __restrict__ src, const int* __restrict__ dst) {
    int e = blockIdx.x * blockDim.x + threadIdx.x;
    if (e < EE) {
        int d = dst[e];
        int slot = atomicAdd(&g_cursor[d], 1);
        g_csr_src[slot] = src[e];
    }
}

// ---------------- attention logits: el/er per (node, head), D=32 ----------------
__global__ void attn_kernel(const float* __restrict__ feat, const float* __restrict__ al,
                            const float* __restrict__ ar, float* __restrict__ el,
                            float* __restrict__ er, int NH, int H, int stride) {
    int t = blockIdx.x * blockDim.x + threadIdx.x;
    int w = t >> 5;
    if (w >= NH) return;
    int lane = t & 31;
    int node = w / H;
    int h = w - node * H;
    float f  = feat[(size_t)node * stride + h * 32 + lane];
    float s1 = f * al[h * 32 + lane];
    float s2 = f * ar[h * 32 + lane];
    #pragma unroll
    for (int o = 16; o; o >>= 1) {
        s1 += __shfl_xor_sync(0xffffffffu, s1, o);
        s2 += __shfl_xor_sync(0xffffffffu, s2, o);
    }
    if (lane == 0) { el[w] = s1; er[w] = s2; }
}

// ---------------- layer1 fused softmax+aggregate (chunked, cooperative weights) ----
// Phase A: 256 threads compute all 8 head-weights per edge coalesced into smem
//          (1 x 32B sector per edge for el1 instead of 8; exp deduped 32x).
// Phase B: warp h aggregates its head with broadcast smem weights.
#define CHUNK 128
__global__ void __launch_bounds__(256) agg1_kernel(const float* __restrict__ x,
                                                   const float* __restrict__ b1) {
    __shared__ float sw[CHUNK][H1];
    __shared__ int   sj[CHUNK];
    int n = blockIdx.x;
    int tid = threadIdx.x;
    int h = tid >> 5, lane = tid & 31;
    int beg = g_rowoff[n], end = g_rowoff[n + 1];
    float s = 0.f, acc = 0.f;
    for (int cb = beg; cb < end; cb += CHUNK) {
        int cnt = min(CHUNK, end - cb);
        // phase A: weights for all heads of this chunk
        for (int idx = tid; idx < cnt * H1; idx += 256) {
            int j = idx >> 3, ha = idx & 7;
            int sn = g_csr_src[cb + j];
            if (ha == 0) sj[j] = sn;
            float e = g_el1[sn * H1 + ha] + g_er1[n * H1 + ha];
            e = e > 0.f ? e : NEG_SLOPE * e;
            sw[j][ha] = __expf(e);
        }
        __syncthreads();
        // phase B: per-warp aggregation
        int j = 0;
        for (; j + 1 < cnt; j += 2) {
            float w0 = sw[j][h], w1 = sw[j + 1][h];
            int s0 = sj[j], s1 = sj[j + 1];
            float f0 = g_feat1[(size_t)s0 * 256 + h * 32 + lane];
            float f1 = g_feat1[(size_t)s1 * 256 + h * 32 + lane];
            s   += w0 + w1;
            acc += w0 * f0 + w1 * f1;
        }
        if (j < cnt) {
            float w0 = sw[j][h];
            int s0 = sj[j];
            s   += w0;
            acc += w0 * g_feat1[(size_t)s0 * 256 + h * 32 + lane];
        }
        __syncthreads();
    }
    float inv = (end > beg) ? 1.0f / s : 0.f;
    int o = n * 256 + h * 32 + lane;
    g_y[o] = fmaxf(acc * inv + x[o] + b1[h * 32 + lane], 0.f);   // residual + bias + relu
}

// ---------------- layer2 fused softmax+aggregate: warp per node ----------------
__global__ void agg2_kernel(const float* __restrict__ b2, float* __restrict__ out) {
    int t = blockIdx.x * blockDim.x + threadIdx.x;
    int n = t >> 5;
    if (n >= NN) return;
    int lane = t & 31;
    int beg = g_rowoff[n], end = g_rowoff[n + 1];
    float ern = g_er2[n];
    float s = 0.f, acc = 0.f;
    int i = beg;
    for (; i + 1 < end; i += 2) {
        int s0 = g_csr_src[i], s1 = g_csr_src[i + 1];
        float e0 = g_el2[s0] + ern;
        float e1 = g_el2[s1] + ern;
        e0 = e0 > 0.f ? e0 : NEG_SLOPE * e0;
        e1 = e1 > 0.f ? e1 : NEG_SLOPE * e1;
        float w0 = __expf(e0), w1 = __expf(e1);
        float f0 = g_f2[(size_t)s0 * 64 + lane];
        float f1 = g_f2[(size_t)s1 * 64 + lane];
        s   += w0 + w1;
        acc += w0 * f0 + w1 * f1;
    }
    if (i < end) {
        int s0 = g_csr_src[i];
        float e0 = g_el2[s0] + ern;
        e0 = e0 > 0.f ? e0 : NEG_SLOPE * e0;
        float w0 = __expf(e0);
        s   += w0;
        acc += w0 * g_f2[(size_t)s0 * 64 + lane];
    }
    float inv = (end > beg) ? 1.0f / s : 0.f;
    out[n * 32 + lane] = acc * inv + g_f2[(size_t)n * 64 + 32 + lane] + b2[lane];
}

// ---------------- launch ----------------
extern "C" void kernel_launch(void* const* d_in, const int* in_sizes, int n_in,
                              void* d_out, int out_size) {
    const float* x     = (const float*)d_in[0];
    const int*   src   = (const int*)d_in[1];
    const int*   dst   = (const int*)d_in[2];
    const float* W1    = (const float*)d_in[3];
    const float* al1   = (const float*)d_in[4];
    const float* ar1   = (const float*)d_in[5];
    const float* b1    = (const float*)d_in[6];
    const float* W2    = (const float*)d_in[7];
    const float* al2   = (const float*)d_in[8];
    const float* ar2   = (const float*)d_in[9];
    const float* resW2 = (const float*)d_in[10];
    const float* b2    = (const float*)d_in[11];
    float* out = (float*)d_out;

    float *feat1, *yb, *el1, *er1, *f2, *el2, *er2;
    __nv_bfloat16 *w1h, *w1l, *wch, *wcl;
    cudaGetSymbolAddress((void**)&feat1, g_feat1);
    cudaGetSymbolAddress((void**)&yb,    g_y);
    cudaGetSymbolAddress((void**)&el1,   g_el1);
    cudaGetSymbolAddress((void**)&er1,   g_er1);
    cudaGetSymbolAddress((void**)&f2,    g_f2);
    cudaGetSymbolAddress((void**)&el2,   g_el2);
    cudaGetSymbolAddress((void**)&er2,   g_er2);
    cudaGetSymbolAddress((void**)&w1h,   g_w1t_h);
    cudaGetSymbolAddress((void**)&w1l,   g_w1t_l);
    cudaGetSymbolAddress((void**)&wch,   g_wct_h);
    cudaGetSymbolAddress((void**)&wcl,   g_wct_l);

    // slots 1-3: weight conversion + deg zero (gemm1 lands in profiled slot 4)
    convert_w1_kernel<<<(256 * 256 + 255) / 256, 256>>>(W1);
    convert_wcat_kernel<<<(64 * 256 + 255) / 256, 256>>>(W2, resW2);
    zero_deg_kernel<<<(NN + 255) / 256, 256>>>();

    // slot 4: layer-1 GEMM (A conversion fused in-kernel)
    mma_gemm_kernel<128><<<dim3(2, (NN + 127) / 128), 256>>>(x, w1h, w1l, feat1, NN, 256);

    // CSR build (multi-block scan; cursor fused into scan3)
    hist_kernel<<<(EE + 255) / 256, 256>>>(dst);
    scan1_kernel<<<SCAN_BC, 1024>>>();
    scan2_kernel<<<1, 64>>>();
    scan3_kernel<<<SCAN_BC, 1024>>>();
    scatter_kernel<<<(EE + 255) / 256, 256>>>(src, dst);

    // layer 1 attention + aggregation
    attn_kernel<<<(NN * H1 * 32 + 255) / 256, 256>>>(feat1, al1, ar1, el1, er1, NN * H1, H1, 256);
    agg1_kernel<<<NN, 256>>>(x, b1);

    // layer 2
    mma_gemm_kernel<64><<<dim3(1, (NN + 127) / 128), 256>>>(yb, wch, wcl, f2, NN, 64);
    attn_kernel<<<(NN * 32 + 255) / 256, 256>>>(f2, al2, ar2, el2, er2, NN, 1, 64);
    agg2_kernel<<<(NN * 32 + 255) / 256, 256>>>(b2, out);
}

// round 9
// speedup vs baseline: 1.8481x; 1.0419x over previous
#include <cuda_runtime.h>
#include <cuda_bf16.h>
#include <math.h>
#include <stdint.h>

#define NN 50000
#define EE 800000
#define H1 8
#define NEG_SLOPE 0.2f
#define SCAN_BC ((NN + 1023) / 1024)   // 49

// ---------------- scratch (device globals; no allocation allowed) ----------------
__device__ float g_feat1[NN * 256];           // layer1 transformed features (fp32)
__device__ float g_y[NN * 256];               // layer1 output (fp32, after relu)
__device__ float g_el1[NN * H1];
__device__ float g_er1[NN * H1];
__device__ float g_f2[NN * 64];               // [ feat2 (0..31) | res2 (32..63) ]
__device__ float g_el2[NN];
__device__ float g_er2[NN];
__device__ __nv_bfloat16 g_w1t_h[256 * 256];  // W1^T [n][k] bf16 hi/lo
__device__ __nv_bfloat16 g_w1t_l[256 * 256];
__device__ __nv_bfloat16 g_wct_h[64 * 256];   // [W2|resW2]^T [n][k] bf16 hi/lo
__device__ __nv_bfloat16 g_wct_l[64 * 256];
__device__ int   g_deg[NN];
__device__ int   g_rowoff[NN + 1];
__device__ int   g_cursor[NN];
__device__ int   g_csr_src[EE];
__device__ int   g_bsum[SCAN_BC];
__device__ int   g_boff[SCAN_BC];

// ---------------- helpers ----------------
__device__ __forceinline__ uint32_t smem_u32(const void* p) {
    uint32_t a;
    asm("{ .reg .u64 t; cvta.to.shared.u64 t, %1; cvt.u32.u64 %0, t; }" : "=r"(a) : "l"(p));
    return a;
}
__device__ __forceinline__ void ldsm_x4(uint32_t (&r)[4], const void* p) {
    uint32_t a = smem_u32(p);
    asm volatile("ldmatrix.sync.aligned.m8n8.x4.shared.b16 {%0,%1,%2,%3}, [%4];"
                 : "=r"(r[0]), "=r"(r[1]), "=r"(r[2]), "=r"(r[3]) : "r"(a));
}
__device__ __forceinline__ void mma_bf16(float (&d)[4], const uint32_t (&a)[4],
                                         uint32_t b0, uint32_t b1) {
    asm volatile("mma.sync.aligned.m16n8k16.row.col.f32.bf16.bf16.f32 "
                 "{%0,%1,%2,%3},{%4,%5,%6,%7},{%8,%9},{%0,%1,%2,%3};"
                 : "+f"(d[0]), "+f"(d[1]), "+f"(d[2]), "+f"(d[3])
                 : "r"(a[0]), "r"(a[1]), "r"(a[2]), "r"(a[3]), "r"(b0), "r"(b1));
}
__device__ __forceinline__ void split_bf16(float v, __nv_bfloat16& h, __nv_bfloat16& l) {
    h = __float2bfloat16(v);
    l = __float2bfloat16(v - __bfloat162float(h));
}

// ============ split-bf16 tensor-core GEMM: C[M,N] = A[M,256] @ B[256,N] ============
// A is fp32 [M][256] (split to bf16 hi/lo in-register while staging to smem).
// B given TRANSPOSED as precomputed bf16 hi/lo [N][256].
// 3-term split: D = AhBh + AlBh + AhBl.
// BM=64, BK=32, 8 warps as 2(M) x 4(N); warp tile 32 x (BN/4). 2 CTAs/SM.
template<int BN>
__global__ void __launch_bounds__(256, 2) mma_gemm_kernel(
        const float* __restrict__ A,
        const __nv_bfloat16* __restrict__ Bth, const __nv_bfloat16* __restrict__ Btl,
        float* __restrict__ C, int M, int N) {
    constexpr int LDS = 40;          // 32 + 8 pad -> 80B rows, LDSM conflict-free
    constexpr int WN  = BN / 4;      // warp n tile (32 for BN=128, 16 for BN=64)
    constexpr int NJ  = WN / 16;     // n16 groups per warp
    __shared__ __nv_bfloat16 sAh[64][LDS], sAl[64][LDS];
    __shared__ __nv_bfloat16 sBh[BN][LDS], sBl[BN][LDS];

    int tid = threadIdx.x, lane = tid & 31, wid = tid >> 5;
    int wm = wid & 1, wn = wid >> 1;
    int row0 = blockIdx.y * 64, col0 = blockIdx.x * BN;
    float acc[2][2 * NJ][4] = {};

    for (int k0 = 0; k0 < 256; k0 += 32) {
        // ---- load A tile fp32 (64 x 32) and split to hi/lo bf16 in-register ----
        {
            int r = tid >> 2, c = (tid & 3) * 8;
            float4 f0 = make_float4(0.f, 0.f, 0.f, 0.f), f1 = f0;
            if (row0 + r < M) {
                const float* ap = &A[(size_t)(row0 + r) * 256 + k0 + c];
                f0 = *(const float4*)ap;
                f1 = *(const float4*)(ap + 4);
            }
            float fv[8] = {f0.x, f0.y, f0.z, f0.w, f1.x, f1.y, f1.z, f1.w};
            union { __nv_bfloat16 b[8]; uint4 u; } uh, ul;
            #pragma unroll
            for (int e = 0; e < 8; e++) split_bf16(fv[e], uh.b[e], ul.b[e]);
            *(uint4*)&sAh[r][c] = uh.u;
            *(uint4*)&sAl[r][c] = ul.u;
        }
        // ---- load B^T tile (BN x 32) bf16 hi/lo ----
        #pragma unroll
        for (int t = 0; t < BN / 64; t++) {
            int v = tid + t * 256;
            int r = v >> 2, c = (v & 3) * 8;
            *(uint4*)&sBh[r][c] = *(const uint4*)&Bth[(size_t)(col0 + r) * 256 + k0 + c];
            *(uint4*)&sBl[r][c] = *(const uint4*)&Btl[(size_t)(col0 + r) * 256 + k0 + c];
        }
        __syncthreads();

        #pragma unroll
        for (int kk = 0; kk < 2; kk++) {
            int kc = kk * 16 + (lane >> 4) * 8;
            uint32_t ah[2][4], al[2][4];
            #pragma unroll
            for (int mi = 0; mi < 2; mi++) {
                int r = wm * 32 + mi * 16 + (lane & 15);
                ldsm_x4(ah[mi], &sAh[r][kc]);
                ldsm_x4(al[mi], &sAl[r][kc]);
            }
            #pragma unroll
            for (int nj = 0; nj < NJ; nj++) {
                uint32_t bh[4], bl[4];
                int r = wn * WN + nj * 16 + (lane & 15);
                ldsm_x4(bh, &sBh[r][kc]);
                ldsm_x4(bl, &sBl[r][kc]);
                #pragma unroll
                for (int half = 0; half < 2; half++) {
                    #pragma unroll
                    for (int mi = 0; mi < 2; mi++) {
                        float (&d)[4] = acc[mi][nj * 2 + half];
                        mma_bf16(d, ah[mi], bh[half], bh[2 + half]);
                        mma_bf16(d, al[mi], bh[half], bh[2 + half]);
                        mma_bf16(d, ah[mi], bl[half], bl[2 + half]);
                    }
                }
            }
        }
        __syncthreads();
    }

    // ---- epilogue ----
    #pragma unroll
    for (int mi = 0; mi < 2; mi++) {
        #pragma unroll
        for (int f = 0; f < 2 * NJ; f++) {
            int r0 = row0 + wm * 32 + mi * 16 + (lane >> 2);
            int c  = col0 + wn * WN + f * 8 + (lane & 3) * 2;
            if (r0 < M)
                *(float2*)&C[(size_t)r0 * N + c] = make_float2(acc[mi][f][0], acc[mi][f][1]);
            if (r0 + 8 < M)
                *(float2*)&C[(size_t)(r0 + 8) * N + c] = make_float2(acc[mi][f][2], acc[mi][f][3]);
        }
    }
}

// ---------------- weight conversion prepasses ----------------
__global__ void convert_w1_kernel(const float* __restrict__ W1) {
    int i = blockIdx.x * blockDim.x + threadIdx.x;   // i = n*256 + k
    if (i < 256 * 256) {
        int n = i >> 8, k = i & 255;
        split_bf16(W1[k * 256 + n], g_w1t_h[i], g_w1t_l[i]);
    }
}
__global__ void convert_wcat_kernel(const float* __restrict__ W2, const float* __restrict__ resW2) {
    int i = blockIdx.x * blockDim.x + threadIdx.x;   // i = n*256 + k, n < 64
    if (i < 64 * 256) {
        int n = i >> 8, k = i & 255;
        float v = (n < 32) ? W2[k * 32 + n] : resW2[k * 32 + (n - 32)];
        split_bf16(v, g_wct_h[i], g_wct_l[i]);
    }
}

// ---------------- CSR build ----------------
__global__ void zero_deg_kernel() {
    int i = blockIdx.x * blockDim.x + threadIdx.x;
    if (i < NN) g_deg[i] = 0;
}
__global__ void hist_kernel(const int* __restrict__ dst) {
    int e = blockIdx.x * blockDim.x + threadIdx.x;
    if (e < EE) atomicAdd(&g_deg[dst[e]], 1);
}
// 3-phase multi-block exclusive scan of g_deg -> g_rowoff (+ g_cursor)
__global__ void scan1_kernel() {          // grid SCAN_BC, block 1024
    __shared__ int sm[1024];
    int b = blockIdx.x, tid = threadIdx.x;
    int i = b * 1024 + tid;
    int v = (i < NN) ? g_deg[i] : 0;
    sm[tid] = v;
    __syncthreads();
    #pragma unroll
    for (int off = 1; off < 1024; off <<= 1) {
        int t2 = (tid >= off) ? sm[tid - off] : 0;
        __syncthreads();
        sm[tid] += t2;
        __syncthreads();
    }
    if (i < NN) g_rowoff[i] = sm[tid] - v;       // block-local exclusive
    if (tid == 1023) g_bsum[b] = sm[1023];
}
__global__ void scan2_kernel() {          // 1 block, 64 threads
    __shared__ int sm[64];
    int tid = threadIdx.x;
    int v = (tid < SCAN_BC) ? g_bsum[tid] : 0;
    sm[tid] = v;
    __syncthreads();
    #pragma unroll
    for (int off = 1; off < 64; off <<= 1) {
        int t2 = (tid >= off) ? sm[tid - off] : 0;
        __syncthreads();
        sm[tid] += t2;
        __syncthreads();
    }
    if (tid < SCAN_BC) g_boff[tid] = sm[tid] - v;
    if (tid == SCAN_BC - 1) g_rowoff[NN] = sm[tid];   // total = EE
}
__global__ void scan3_kernel() {          // grid SCAN_BC, block 1024; fuses cursor init
    int b = blockIdx.x;
    int i = b * 1024 + threadIdx.x;
    if (i < NN) {
        int r = g_rowoff[i] + g_boff[b];
        g_rowoff[i] = r;
        g_cursor[i] = r;
    }
}
__global__ void scatter_kernel(const int* __restrict__ src, const int* __restrict__ dst) {
    int e = blockIdx.x * blockDim.x + threadIdx.x;
    if (e < EE) {
        int d = dst[e];
        int slot = atomicAdd(&g_cursor[d], 1);
        g_csr_src[slot] = src[e];
    }
}

// ---------------- attention logits: el/er per (node, head), D=32 ----------------
__global__ void attn_kernel(const float* __restrict__ feat, const float* __restrict__ al,
                            const float* __restrict__ ar, float* __restrict__ el,
                            float* __restrict__ er, int NH, int H, int stride) {
    int t = blockIdx.x * blockDim.x + threadIdx.x;
    int w = t >> 5;
    if (w >= NH) return;
    int lane = t & 31;
    int node = w / H;
    int h = w - node * H;
    float f  = feat[(size_t)node * stride + h * 32 + lane];
    float s1 = f * al[h * 32 + lane];
    float s2 = f * ar[h * 32 + lane];
    #pragma unroll
    for (int o = 16; o; o >>= 1) {
        s1 += __shfl_xor_sync(0xffffffffu, s1, o);
        s2 += __shfl_xor_sync(0xffffffffu, s2, o);
    }
    if (lane == 0) { el[w] = s1; er[w] = s2; }
}

// ---------------- layer1 fused softmax+aggregate (chunked, cooperative weights) ----
#define CHUNK 128
__global__ void __launch_bounds__(256) agg1_kernel(const float* __restrict__ x,
                                                   const float* __restrict__ b1) {
    __shared__ float sw[CHUNK][H1];
    __shared__ int   sj[CHUNK];
    int n = blockIdx.x;
    int tid = threadIdx.x;
    int h = tid >> 5, lane = tid & 31;
    int beg = g_rowoff[n], end = g_rowoff[n + 1];
    float s = 0.f, acc = 0.f;
    for (int cb = beg; cb < end; cb += CHUNK) {
        int cnt = min(CHUNK, end - cb);
        // phase A: weights for all heads of this chunk (coalesced, exp deduped)
        for (int idx = tid; idx < cnt * H1; idx += 256) {
            int j = idx >> 3, ha = idx & 7;
            int sn = g_csr_src[cb + j];
            if (ha == 0) sj[j] = sn;
            float e = g_el1[sn * H1 + ha] + g_er1[n * H1 + ha];
            e = e > 0.f ? e : NEG_SLOPE * e;
            sw[j][ha] = __expf(e);
        }
        __syncthreads();
        // phase B: per-warp aggregation
        int j = 0;
        for (; j + 1 < cnt; j += 2) {
            float w0 = sw[j][h], w1 = sw[j + 1][h];
            int s0 = sj[j], s1 = sj[j + 1];
            float f0 = g_feat1[(size_t)s0 * 256 + h * 32 + lane];
            float f1 = g_feat1[(size_t)s1 * 256 + h * 32 + lane];
            s   += w0 + w1;
            acc += w0 * f0 + w1 * f1;
        }
        if (j < cnt) {
            float w0 = sw[j][h];
            int s0 = sj[j];
            s   += w0;
            acc += w0 * g_feat1[(size_t)s0 * 256 + h * 32 + lane];
        }
        __syncthreads();
    }
    float inv = (end > beg) ? 1.0f / s : 0.f;
    int o = n * 256 + h * 32 + lane;
    g_y[o] = fmaxf(acc * inv + x[o] + b1[h * 32 + lane], 0.f);   // residual + bias + relu
}

// ---------------- layer2 fused softmax+aggregate: warp per node ----------------
__global__ void agg2_kernel(const float* __restrict__ b2, float* __restrict__ out) {
    int t = blockIdx.x * blockDim.x + threadIdx.x;
    int n = t >> 5;
    if (n >= NN) return;
    int lane = t & 31;
    int beg = g_rowoff[n], end = g_rowoff[n + 1];
    float ern = g_er2[n];
    float s = 0.f, acc = 0.f;
    int i = beg;
    for (; i + 1 < end; i += 2) {
        int s0 = g_csr_src[i], s1 = g_csr_src[i + 1];
        float e0 = g_el2[s0] + ern;
        float e1 = g_el2[s1] + ern;
        e0 = e0 > 0.f ? e0 : NEG_SLOPE * e0;
        e1 = e1 > 0.f ? e1 : NEG_SLOPE * e1;
        float w0 = __expf(e0), w1 = __expf(e1);
        float f0 = g_f2[(size_t)s0 * 64 + lane];
        float f1 = g_f2[(size_t)s1 * 64 + lane];
        s   += w0 + w1;
        acc += w0 * f0 + w1 * f1;
    }
    if (i < end) {
        int s0 = g_csr_src[i];
        float e0 = g_el2[s0] + ern;
        e0 = e0 > 0.f ? e0 : NEG_SLOPE * e0;
        float w0 = __expf(e0);
        s   += w0;
        acc += w0 * g_f2[(size_t)s0 * 64 + lane];
    }
    float inv = (end > beg) ? 1.0f / s : 0.f;
    out[n * 32 + lane] = acc * inv + g_f2[(size_t)n * 64 + 32 + lane] + b2[lane];
}

// ---------------- launch ----------------
extern "C" void kernel_launch(void* const* d_in, const int* in_sizes, int n_in,
                              void* d_out, int out_size) {
    const float* x     = (const float*)d_in[0];
    const int*   src   = (const int*)d_in[1];
    const int*   dst   = (const int*)d_in[2];
    const float* W1    = (const float*)d_in[3];
    const float* al1   = (const float*)d_in[4];
    const float* ar1   = (const float*)d_in[5];
    const float* b1    = (const float*)d_in[6];
    const float* W2    = (const float*)d_in[7];
    const float* al2   = (const float*)d_in[8];
    const float* ar2   = (const float*)d_in[9];
    const float* resW2 = (const float*)d_in[10];
    const float* b2    = (const float*)d_in[11];
    float* out = (float*)d_out;

    float *feat1, *yb, *el1, *er1, *f2, *el2, *er2;
    __nv_bfloat16 *w1h, *w1l, *wch, *wcl;
    cudaGetSymbolAddress((void**)&feat1, g_feat1);
    cudaGetSymbolAddress((void**)&yb,    g_y);
    cudaGetSymbolAddress((void**)&el1,   g_el1);
    cudaGetSymbolAddress((void**)&er1,   g_er1);
    cudaGetSymbolAddress((void**)&f2,    g_f2);
    cudaGetSymbolAddress((void**)&el2,   g_el2);
    cudaGetSymbolAddress((void**)&er2,   g_er2);
    cudaGetSymbolAddress((void**)&w1h,   g_w1t_h);
    cudaGetSymbolAddress((void**)&w1l,   g_w1t_l);
    cudaGetSymbolAddress((void**)&wch,   g_wct_h);
    cudaGetSymbolAddress((void**)&wcl,   g_wct_l);

    // slots 1-3: weight conversion + deg zero (gemm1 lands in profiled slot 4)
    convert_w1_kernel<<<(256 * 256 + 255) / 256, 256>>>(W1);
    convert_wcat_kernel<<<(64 * 256 + 255) / 256, 256>>>(W2, resW2);
    zero_deg_kernel<<<(NN + 255) / 256, 256>>>();

    // slot 4: layer-1 GEMM (A conversion fused in-kernel)
    mma_gemm_kernel<128><<<dim3(2, (NN + 63) / 64), 256>>>(x, w1h, w1l, feat1, NN, 256);

    // CSR build (multi-block scan; cursor fused into scan3)
    hist_kernel<<<(EE + 255) / 256, 256>>>(dst);
    scan1_kernel<<<SCAN_BC, 1024>>>();
    scan2_kernel<<<1, 64>>>();
    scan3_kernel<<<SCAN_BC, 1024>>>();
    scatter_kernel<<<(EE + 255) / 256, 256>>>(src, dst);

    // layer 1 attention + aggregation
    attn_kernel<<<(NN * H1 * 32 + 255) / 256, 256>>>(feat1, al1, ar1, el1, er1, NN * H1, H1, 256);
    agg1_kernel<<<NN, 256>>>(x, b1);

    // layer 2
    mma_gemm_kernel<64><<<dim3(1, (NN + 63) / 64), 256>>>(yb, wch, wcl, f2, NN, 64);
    attn_kernel<<<(NN * 32 + 255) / 256, 256>>>(f2, al2, ar2, el2, er2, NN, 1, 64);
    agg2_kernel<<<(NN * 32 + 255) / 256, 256>>>(b2, out);
}

// round 10
// speedup vs baseline: 1.9140x; 1.0357x over previous
#include <cuda_runtime.h>
#include <cuda_bf16.h>
#include <cuda_fp16.h>
#include <math.h>
#include <stdint.h>

#define NN 50000
#define EE 800000
#define H1 8
#define NEG_SLOPE 0.2f
#define SCAN_BC ((NN + 1023) / 1024)   // 49

// ---------------- scratch (device globals; no allocation allowed) ----------------
__device__ float  g_feat1[NN * 256];          // layer1 transformed features (fp32, for attn)
__device__ __half g_feat1h[NN * 256];         // fp16 copy (for agg1 gather)
__device__ float  g_y[NN * 256];              // layer1 output (fp32, after relu)
__device__ float  g_el1[NN * H1];
__device__ float  g_er1[NN * H1];
__device__ float  g_f2[NN * 64];              // [ feat2 (0..31) | res2 (32..63) ]
__device__ float  g_el2[NN];
__device__ float  g_er2[NN];
__device__ __nv_bfloat16 g_w1t_h[256 * 256];  // W1^T [n][k] bf16 hi/lo
__device__ __nv_bfloat16 g_w1t_l[256 * 256];
__device__ __nv_bfloat16 g_wct_h[64 * 256];   // [W2|resW2]^T [n][k] bf16 hi/lo
__device__ __nv_bfloat16 g_wct_l[64 * 256];
__device__ int   g_deg[NN];
__device__ int   g_rowoff[NN + 1];
__device__ int   g_cursor[NN];
__device__ int   g_csr_src[EE];
__device__ int   g_bsum[SCAN_BC];
__device__ int   g_boff[SCAN_BC];

// ---------------- helpers ----------------
__device__ __forceinline__ uint32_t smem_u32(const void* p) {
    uint32_t a;
    asm("{ .reg .u64 t; cvta.to.shared.u64 t, %1; cvt.u32.u64 %0, t; }" : "=r"(a) : "l"(p));
    return a;
}
__device__ __forceinline__ void ldsm_x4(uint32_t (&r)[4], const void* p) {
    uint32_t a = smem_u32(p);
    asm volatile("ldmatrix.sync.aligned.m8n8.x4.shared.b16 {%0,%1,%2,%3}, [%4];"
                 : "=r"(r[0]), "=r"(r[1]), "=r"(r[2]), "=r"(r[3]) : "r"(a));
}
__device__ __forceinline__ void mma_bf16(float (&d)[4], const uint32_t (&a)[4],
                                         uint32_t b0, uint32_t b1) {
    asm volatile("mma.sync.aligned.m16n8k16.row.col.f32.bf16.bf16.f32 "
                 "{%0,%1,%2,%3},{%4,%5,%6,%7},{%8,%9},{%0,%1,%2,%3};"
                 : "+f"(d[0]), "+f"(d[1]), "+f"(d[2]), "+f"(d[3])
                 : "r"(a[0]), "r"(a[1]), "r"(a[2]), "r"(a[3]), "r"(b0), "r"(b1));
}
__device__ __forceinline__ void split_bf16(float v, __nv_bfloat16& h, __nv_bfloat16& l) {
    h = __float2bfloat16(v);
    l = __float2bfloat16(v - __bfloat162float(h));
}
__device__ __forceinline__ void cp16(uint32_t dst, const void* src) {
    asm volatile("cp.async.cg.shared.global [%0], [%1], 16;" :: "r"(dst), "l"(src));
}
#define CP_COMMIT() asm volatile("cp.async.commit_group;" ::: "memory")
#define CP_WAIT0()  asm volatile("cp.async.wait_group 0;" ::: "memory")

// ============ split-bf16 tensor-core GEMM, cp.async double-buffered ============
// C[M,N] = A[M,256] @ B[256,N]; A fp32 (in-register split), B^T precomputed bf16 hi/lo.
// 3-term: D = AhBh + AlBh + AhBl.  BM=64, BK=32, 8 warps 2(M)x4(N), 2 CTAs/SM.
// WH: also write fp16 copy of C to g_feat1h.
template<int BN, bool WH>
__global__ void __launch_bounds__(256, 2) mma_gemm_kernel(
        const float* __restrict__ A,
        const __nv_bfloat16* __restrict__ Bth, const __nv_bfloat16* __restrict__ Btl,
        float* __restrict__ C, int M, int N) {
    constexpr int LDS = 40;          // 80B rows: 16B-aligned, LDSM conflict-free
    constexpr int WN  = BN / 4;
    constexpr int NJ  = WN / 16;
    extern __shared__ __nv_bfloat16 dyn[];
    __nv_bfloat16* pAh = dyn;                        // [2][64][LDS]
    __nv_bfloat16* pAl = dyn + 2 * 64 * LDS;
    __nv_bfloat16* pBh = dyn + 4 * 64 * LDS;         // [2][BN][LDS]
    __nv_bfloat16* pBl = dyn + 4 * 64 * LDS + 2 * BN * LDS;

    int tid = threadIdx.x, lane = tid & 31, wid = tid >> 5;
    int wm = wid & 1, wn = wid >> 1;
    int row0 = blockIdx.y * 64, col0 = blockIdx.x * BN;
    float acc[2][2 * NJ][4] = {};

    int rA = tid >> 2, cA = (tid & 3) * 8;           // A tile coords (64 x 32)
    const float* aBase = &A[(size_t)(row0 + rA) * 256 + cA];
    bool aValid = (row0 + rA < M);

    // ---- B async load for chunk into buffer b ----
    auto loadB = [&](int k0, int b) {
        #pragma unroll
        for (int t = 0; t < BN / 64; t++) {
            int v = tid + t * 256;
            int r = v >> 2, c = (v & 3) * 8;
            size_t go = (size_t)(col0 + r) * 256 + k0 + c;
            cp16(smem_u32(pBh + (b * BN + r) * LDS + c), &Bth[go]);
            cp16(smem_u32(pBl + (b * BN + r) * LDS + c), &Btl[go]);
        }
        CP_COMMIT();
    };
    // ---- A: split 8 fp32 -> smem buffer b ----
    auto storeA = [&](const float* fv, int b) {
        union { __nv_bfloat16 bb[8]; uint4 u; } uh, ul;
        #pragma unroll
        for (int e = 0; e < 8; e++) split_bf16(fv[e], uh.bb[e], ul.bb[e]);
        *(uint4*)(pAh + (b * 64 + rA) * LDS + cA) = uh.u;
        *(uint4*)(pAl + (b * 64 + rA) * LDS + cA) = ul.u;
    };

    // ---- prologue: chunk 0 into buf 0 ----
    loadB(0, 0);
    {
        float fv[8] = {};
        if (aValid) { *(float4*)fv = *(const float4*)aBase; *(float4*)(fv + 4) = *(const float4*)(aBase + 4); }
        storeA(fv, 0);
    }
    CP_WAIT0();
    __syncthreads();

    for (int chunk = 0; chunk < 8; chunk++) {
        int cur = chunk & 1, nxt = chunk + 1;
        float fv[8] = {};
        if (nxt < 8) {
            loadB(nxt * 32, nxt & 1);
            if (aValid) {
                const float* ap = aBase + nxt * 32;
                *(float4*)fv = *(const float4*)ap;
                *(float4*)(fv + 4) = *(const float4*)(ap + 4);
            }
        }
        // ---- compute on buf cur ----
        #pragma unroll
        for (int kk = 0; kk < 2; kk++) {
            int kc = kk * 16 + (lane >> 4) * 8;
            uint32_t ah[2][4], al[2][4];
            #pragma unroll
            for (int mi = 0; mi < 2; mi++) {
                int r = wm * 32 + mi * 16 + (lane & 15);
                ldsm_x4(ah[mi], pAh + (cur * 64 + r) * LDS + kc);
                ldsm_x4(al[mi], pAl + (cur * 64 + r) * LDS + kc);
            }
            #pragma unroll
            for (int nj = 0; nj < NJ; nj++) {
                uint32_t bh[4], bl[4];
                int r = wn * WN + nj * 16 + (lane & 15);
                ldsm_x4(bh, pBh + (cur * BN + r) * LDS + kc);
                ldsm_x4(bl, pBl + (cur * BN + r) * LDS + kc);
                #pragma unroll
                for (int half = 0; half < 2; half++) {
                    #pragma unroll
                    for (int mi = 0; mi < 2; mi++) {
                        float (&d)[4] = acc[mi][nj * 2 + half];
                        mma_bf16(d, ah[mi], bh[half], bh[2 + half]);
                        mma_bf16(d, al[mi], bh[half], bh[2 + half]);
                        mma_bf16(d, ah[mi], bl[half], bl[2 + half]);
                    }
                }
            }
        }
        if (nxt < 8) storeA(fv, nxt & 1);   // write other buffer (consumed 2 chunks ago)
        CP_WAIT0();
        __syncthreads();
    }

    // ---- epilogue ----
    #pragma unroll
    for (int mi = 0; mi < 2; mi++) {
        #pragma unroll
        for (int f = 0; f < 2 * NJ; f++) {
            int r0 = row0 + wm * 32 + mi * 16 + (lane >> 2);
            int c  = col0 + wn * WN + f * 8 + (lane & 3) * 2;
            #pragma unroll
            for (int half = 0; half < 2; half++) {
                int r = r0 + half * 8;
                if (r < M) {
                    float v0 = acc[mi][f][half * 2], v1 = acc[mi][f][half * 2 + 1];
                    *(float2*)&C[(size_t)r * N + c] = make_float2(v0, v1);
                    if (WH)
                        *(__half2*)&g_feat1h[(size_t)r * 256 + c] =
                            __floats2half2_rn(v0, v1);
                }
            }
        }
    }
}

// ---------------- weight conversion prepasses ----------------
__global__ void convert_w1_kernel(const float* __restrict__ W1) {
    int i = blockIdx.x * blockDim.x + threadIdx.x;   // i = n*256 + k
    if (i < 256 * 256) {
        int n = i >> 8, k = i & 255;
        split_bf16(W1[k * 256 + n], g_w1t_h[i], g_w1t_l[i]);
    }
}
__global__ void convert_wcat_kernel(const float* __restrict__ W2, const float* __restrict__ resW2) {
    int i = blockIdx.x * blockDim.x + threadIdx.x;   // i = n*256 + k, n < 64
    if (i < 64 * 256) {
        int n = i >> 8, k = i & 255;
        float v = (n < 32) ? W2[k * 32 + n] : resW2[k * 32 + (n - 32)];
        split_bf16(v, g_wct_h[i], g_wct_l[i]);
    }
}

// ---------------- CSR build ----------------
__global__ void zero_deg_kernel() {
    int i = blockIdx.x * blockDim.x + threadIdx.x;
    if (i < NN) g_deg[i] = 0;
}
__global__ void hist_kernel(const int* __restrict__ dst) {
    int e = blockIdx.x * blockDim.x + threadIdx.x;
    if (e < EE) atomicAdd(&g_deg[dst[e]], 1);
}
__global__ void scan1_kernel() {          // grid SCAN_BC, block 1024
    __shared__ int sm[1024];
    int b = blockIdx.x, tid = threadIdx.x;
    int i = b * 1024 + tid;
    int v = (i < NN) ? g_deg[i] : 0;
    sm[tid] = v;
    __syncthreads();
    #pragma unroll
    for (int off = 1; off < 1024; off <<= 1) {
        int t2 = (tid >= off) ? sm[tid - off] : 0;
        __syncthreads();
        sm[tid] += t2;
        __syncthreads();
    }
    if (i < NN) g_rowoff[i] = sm[tid] - v;       // block-local exclusive
    if (tid == 1023) g_bsum[b] = sm[1023];
}
__global__ void scan2_kernel() {          // 1 block, 64 threads
    __shared__ int sm[64];
    int tid = threadIdx.x;
    int v = (tid < SCAN_BC) ? g_bsum[tid] : 0;
    sm[tid] = v;
    __syncthreads();
    #pragma unroll
    for (int off = 1; off < 64; off <<= 1) {
        int t2 = (tid >= off) ? sm[tid - off] : 0;
        __syncthreads();
        sm[tid] += t2;
        __syncthreads();
    }
    if (tid < SCAN_BC) g_boff[tid] = sm[tid] - v;
    if (tid == SCAN_BC - 1) g_rowoff[NN] = sm[tid];   // total = EE
}
__global__ void scan3_kernel() {          // grid SCAN_BC; fuses cursor init
    int b = blockIdx.x;
    int i = b * 1024 + threadIdx.x;
    if (i < NN) {
        int r = g_rowoff[i] + g_boff[b];
        g_rowoff[i] = r;
        g_cursor[i] = r;
    }
}
__global__ void scatter_kernel(const int* __restrict__ src, const int* __restrict__ dst) {
    int e = blockIdx.x * blockDim.x + threadIdx.x;
    if (e < EE) {
        int d = dst[e];
        int slot = atomicAdd(&g_cursor[d], 1);
        g_csr_src[slot] = src[e];
    }
}

// ---------------- attention logits: el/er per (node, head), D=32 (fp32 feat) ----
__global__ void attn_kernel(const float* __restrict__ feat, const float* __restrict__ al,
                            const float* __restrict__ ar, float* __restrict__ el,
                            float* __restrict__ er, int NH, int H, int stride) {
    int t = blockIdx.x * blockDim.x + threadIdx.x;
    int w = t >> 5;
    if (w >= NH) return;
    int lane = t & 31;
    int node = w / H;
    int h = w - node * H;
    float f  = feat[(size_t)node * stride + h * 32 + lane];
    float s1 = f * al[h * 32 + lane];
    float s2 = f * ar[h * 32 + lane];
    #pragma unroll
    for (int o = 16; o; o >>= 1) {
        s1 += __shfl_xor_sync(0xffffffffu, s1, o);
        s2 += __shfl_xor_sync(0xffffffffu, s2, o);
    }
    if (lane == 0) { el[w] = s1; er[w] = s2; }
}

// ---------------- layer1 fused softmax+aggregate (fp16 gather) ----------------
#define CHUNK 128
__global__ void __launch_bounds__(256) agg1_kernel(const float* __restrict__ x,
                                                   const float* __restrict__ b1) {
    __shared__ float sw[CHUNK][H1];
    __shared__ int   sj[CHUNK];
    int n = blockIdx.x;
    int tid = threadIdx.x;
    int h = tid >> 5, lane = tid & 31;
    int beg = g_rowoff[n], end = g_rowoff[n + 1];
    float s = 0.f, acc = 0.f;
    for (int cb = beg; cb < end; cb += CHUNK) {
        int cnt = min(CHUNK, end - cb);
        // phase A: weights for all heads of this chunk (coalesced, exp deduped)
        for (int idx = tid; idx < cnt * H1; idx += 256) {
            int j = idx >> 3, ha = idx & 7;
            int sn = g_csr_src[cb + j];
            if (ha == 0) sj[j] = sn;
            float e = g_el1[sn * H1 + ha] + g_er1[n * H1 + ha];
            e = e > 0.f ? e : NEG_SLOPE * e;
            sw[j][ha] = __expf(e);
        }
        __syncthreads();
        // phase B: per-warp aggregation (fp16 feature gather: 64B/warp/edge)
        int j = 0;
        for (; j + 1 < cnt; j += 2) {
            float w0 = sw[j][h], w1 = sw[j + 1][h];
            int s0 = sj[j], s1 = sj[j + 1];
            float f0 = __half2float(g_feat1h[(size_t)s0 * 256 + h * 32 + lane]);
            float f1 = __half2float(g_feat1h[(size_t)s1 * 256 + h * 32 + lane]);
            s   += w0 + w1;
            acc += w0 * f0 + w1 * f1;
        }
        if (j < cnt) {
            float w0 = sw[j][h];
            int s0 = sj[j];
            s   += w0;
            acc += w0 * __half2float(g_feat1h[(size_t)s0 * 256 + h * 32 + lane]);
        }
        __syncthreads();
    }
    float inv = (end > beg) ? 1.0f / s : 0.f;
    int o = n * 256 + h * 32 + lane;
    g_y[o] = fmaxf(acc * inv + x[o] + b1[h * 32 + lane], 0.f);   // residual + bias + relu
}

// ---------------- layer2 fused softmax+aggregate: warp per node ----------------
__global__ void agg2_kernel(const float* __restrict__ b2, float* __restrict__ out) {
    int t = blockIdx.x * blockDim.x + threadIdx.x;
    int n = t >> 5;
    if (n >= NN) return;
    int lane = t & 31;
    int beg = g_rowoff[n], end = g_rowoff[n + 1];
    float ern = g_er2[n];
    float s = 0.f, acc = 0.f;
    int i = beg;
    for (; i + 1 < end; i += 2) {
        int s0 = g_csr_src[i], s1 = g_csr_src[i + 1];
        float e0 = g_el2[s0] + ern;
        float e1 = g_el2[s1] + ern;
        e0 = e0 > 0.f ? e0 : NEG_SLOPE * e0;
        e1 = e1 > 0.f ? e1 : NEG_SLOPE * e1;
        float w0 = __expf(e0), w1 = __expf(e1);
        float f0 = g_f2[(size_t)s0 * 64 + lane];
        float f1 = g_f2[(size_t)s1 * 64 + lane];
        s   += w0 + w1;
        acc += w0 * f0 + w1 * f1;
    }
    if (i < end) {
        int s0 = g_csr_src[i];
        float e0 = g_el2[s0] + ern;
        e0 = e0 > 0.f ? e0 : NEG_SLOPE * e0;
        float w0 = __expf(e0);
        s   += w0;
        acc += w0 * g_f2[(size_t)s0 * 64 + lane];
    }
    float inv = (end > beg) ? 1.0f / s : 0.f;
    out[n * 32 + lane] = acc * inv + g_f2[(size_t)n * 64 + 32 + lane] + b2[lane];
}

// ---------------- launch ----------------
extern "C" void kernel_launch(void* const* d_in, const int* in_sizes, int n_in,
                              void* d_out, int out_size) {
    const float* x     = (const float*)d_in[0];
    const int*   src   = (const int*)d_in[1];
    const int*   dst   = (const int*)d_in[2];
    const float* W1    = (const float*)d_in[3];
    const float* al1   = (const float*)d_in[4];
    const float* ar1   = (const float*)d_in[5];
    const float* b1    = (const float*)d_in[6];
    const float* W2    = (const float*)d_in[7];
    const float* al2   = (const float*)d_in[8];
    const float* ar2   = (const float*)d_in[9];
    const float* resW2 = (const float*)d_in[10];
    const float* b2    = (const float*)d_in[11];
    float* out = (float*)d_out;

    float *feat1, *yb, *el1, *er1, *f2, *el2, *er2;
    __nv_bfloat16 *w1h, *w1l, *wch, *wcl;
    cudaGetSymbolAddress((void**)&feat1, g_feat1);
    cudaGetSymbolAddress((void**)&yb,    g_y);
    cudaGetSymbolAddress((void**)&el1,   g_el1);
    cudaGetSymbolAddress((void**)&er1,   g_er1);
    cudaGetSymbolAddress((void**)&f2,    g_f2);
    cudaGetSymbolAddress((void**)&el2,   g_el2);
    cudaGetSymbolAddress((void**)&er2,   g_er2);
    cudaGetSymbolAddress((void**)&w1h,   g_w1t_h);
    cudaGetSymbolAddress((void**)&w1l,   g_w1t_l);
    cudaGetSymbolAddress((void**)&wch,   g_wct_h);
    cudaGetSymbolAddress((void**)&wcl,   g_wct_l);

    const int LDSC = 40;
    const int smem128 = (4 * 64 * LDSC + 4 * 128 * LDSC) * 2;   // 61440 B
    const int smem64  = (4 * 64 * LDSC + 4 * 64 * LDSC) * 2;    // 40960 B
    static bool attrDone = false;
    if (!attrDone) {
        cudaFuncSetAttribute(mma_gemm_kernel<128, true>,
                             cudaFuncAttributeMaxDynamicSharedMemorySize, smem128);
        cudaFuncSetAttribute(mma_gemm_kernel<64, false>,
                             cudaFuncAttributeMaxDynamicSharedMemorySize, smem64);
        attrDone = true;
    }

    // slots 1-3: weight conversion + deg zero (gemm1 lands in profiled slot 4)
    convert_w1_kernel<<<(256 * 256 + 255) / 256, 256>>>(W1);
    convert_wcat_kernel<<<(64 * 256 + 255) / 256, 256>>>(W2, resW2);
    zero_deg_kernel<<<(NN + 255) / 256, 256>>>();

    // slot 4: layer-1 GEMM (fp32->split fused, fp16 copy written in epilogue)
    mma_gemm_kernel<128, true><<<dim3(2, (NN + 63) / 64), 256, smem128>>>(x, w1h, w1l, feat1, NN, 256);

    // CSR build (multi-block scan; cursor fused into scan3)
    hist_kernel<<<(EE + 255) / 256, 256>>>(dst);
    scan1_kernel<<<SCAN_BC, 1024>>>();
    scan2_kernel<<<1, 64>>>();
    scan3_kernel<<<SCAN_BC, 1024>>>();
    scatter_kernel<<<(EE + 255) / 256, 256>>>(src, dst);

    // layer 1 attention + aggregation
    attn_kernel<<<(NN * H1 * 32 + 255) / 256, 256>>>(feat1, al1, ar1, el1, er1, NN * H1, H1, 256);
    agg1_kernel<<<NN, 256>>>(x, b1);

    // layer 2
    mma_gemm_kernel<64, false><<<dim3(1, (NN + 63) / 64), 256, smem64>>>(yb, wch, wcl, f2, NN, 64);
    attn_kernel<<<(NN * 32 + 255) / 256, 256>>>(f2, al2, ar2, el2, er2, NN, 1, 64);
    agg2_kernel<<<(NN * 32 + 255) / 256, 256>>>(b2, out);
}

// round 11
// speedup vs baseline: 2.2783x; 1.1903x over previous
#include <cuda_runtime.h>
#include <cuda_fp16.h>
#include <math.h>
#include <stdint.h>

#define NN 50000
#define EE 800000
#define H1 8
#define NEG_SLOPE 0.2f
#define SCAN_BC ((NN + 1023) / 1024)   // 49

// ---------------- scratch (device globals; no allocation allowed) ----------------
__device__ __half g_feat1h[NN * 256];        // layer1 features (fp16: attn + gather)
__device__ float  g_y[NN * 256];             // layer1 output (fp32, after relu)
__device__ float  g_el1[NN * H1];
__device__ float  g_er1[NN * H1];
__device__ float  g_f2[NN * 64];             // [ feat2 (0..31) | res2 (32..63) ] fp32
__device__ __half g_f2h[NN * 32];            // fp16 copy of feat2 (agg2 gather)
__device__ float  g_el2[NN];
__device__ float  g_er2[NN];
__device__ __half g_w1t[256 * 256];          // W1^T [n][k] fp16
__device__ __half g_wct[64 * 256];           // [W2|resW2]^T [n][k] fp16
__device__ int   g_deg[NN];
__device__ int   g_rowoff[NN + 1];
__device__ int   g_cursor[NN];
__device__ int   g_csr_src[EE];
__device__ int   g_bsum[SCAN_BC];
__device__ int   g_boff[SCAN_BC];

// ---------------- helpers ----------------
__device__ __forceinline__ uint32_t smem_u32(const void* p) {
    uint32_t a;
    asm("{ .reg .u64 t; cvta.to.shared.u64 t, %1; cvt.u32.u64 %0, t; }" : "=r"(a) : "l"(p));
    return a;
}
__device__ __forceinline__ void ldsm_x4(uint32_t (&r)[4], const void* p) {
    uint32_t a = smem_u32(p);
    asm volatile("ldmatrix.sync.aligned.m8n8.x4.shared.b16 {%0,%1,%2,%3}, [%4];"
                 : "=r"(r[0]), "=r"(r[1]), "=r"(r[2]), "=r"(r[3]) : "r"(a));
}
__device__ __forceinline__ void mma_f16(float (&d)[4], const uint32_t (&a)[4],
                                        uint32_t b0, uint32_t b1) {
    asm volatile("mma.sync.aligned.m16n8k16.row.col.f32.f16.f16.f32 "
                 "{%0,%1,%2,%3},{%4,%5,%6,%7},{%8,%9},{%0,%1,%2,%3};"
                 : "+f"(d[0]), "+f"(d[1]), "+f"(d[2]), "+f"(d[3])
                 : "r"(a[0]), "r"(a[1]), "r"(a[2]), "r"(a[3]), "r"(b0), "r"(b1));
}
__device__ __forceinline__ void cp16(uint32_t dst, const void* src) {
    asm volatile("cp.async.cg.shared.global [%0], [%1], 16;" :: "r"(dst), "l"(src));
}
#define CP_COMMIT() asm volatile("cp.async.commit_group;" ::: "memory")
#define CP_WAIT0()  asm volatile("cp.async.wait_group 0;" ::: "memory")

// ============ fp16 tensor-core GEMM, cp.async double-buffered ============
// C = A[M,256] @ B[256,N]; A fp32 (converted in-register), B^T precomputed fp16 [N][256].
// BM=64, BK=32, 8 warps 2(M)x4(N).  MODE 1: write fp16 feat1h only.
// MODE 2: write fp32 C (N=64) + fp16 copy of cols 0..31 into g_f2h.
template<int BN, int MODE>
__global__ void __launch_bounds__(256, 3) mma_gemm_kernel(
        const float* __restrict__ A, const __half* __restrict__ Bt,
        float* __restrict__ C, int M, int N) {
    constexpr int LDS = 40;          // 80B rows: LDSM conflict-free
    constexpr int WN  = BN / 4;
    constexpr int NJ  = WN / 16;
    extern __shared__ __half dyn[];
    __half* pA = dyn;                         // [2][64][LDS]
    __half* pB = dyn + 2 * 64 * LDS;          // [2][BN][LDS]

    int tid = threadIdx.x, lane = tid & 31, wid = tid >> 5;
    int wm = wid & 1, wn = wid >> 1;
    int row0 = blockIdx.y * 64, col0 = blockIdx.x * BN;
    float acc[2][2 * NJ][4] = {};

    int rA = tid >> 2, cA = (tid & 3) * 8;    // A tile coords (64 x 32)
    const float* aBase = &A[(size_t)(row0 + rA) * 256 + cA];
    bool aValid = (row0 + rA < M);

    auto loadB = [&](int k0, int b) {
        #pragma unroll
        for (int t = 0; t < BN / 64; t++) {
            int v = tid + t * 256;
            int r = v >> 2, c = (v & 3) * 8;
            cp16(smem_u32(pB + (b * BN + r) * LDS + c), &Bt[(size_t)(col0 + r) * 256 + k0 + c]);
        }
        CP_COMMIT();
    };
    auto storeA = [&](const float* fv, int b) {
        union { __half hh[8]; uint4 u; } uc;
        #pragma unroll
        for (int e = 0; e < 8; e++) uc.hh[e] = __float2half_rn(fv[e]);
        *(uint4*)(pA + (b * 64 + rA) * LDS + cA) = uc.u;
    };

    // ---- prologue ----
    loadB(0, 0);
    {
        float fv[8] = {};
        if (aValid) { *(float4*)fv = *(const float4*)aBase; *(float4*)(fv + 4) = *(const float4*)(aBase + 4); }
        storeA(fv, 0);
    }
    CP_WAIT0();
    __syncthreads();

    for (int chunk = 0; chunk < 8; chunk++) {
        int cur = chunk & 1, nxt = chunk + 1;
        float fv[8] = {};
        if (nxt < 8) {
            loadB(nxt * 32, nxt & 1);
            if (aValid) {
                const float* ap = aBase + nxt * 32;
                *(float4*)fv = *(const float4*)ap;
                *(float4*)(fv + 4) = *(const float4*)(ap + 4);
            }
        }
        #pragma unroll
        for (int kk = 0; kk < 2; kk++) {
            int kc = kk * 16 + (lane >> 4) * 8;
            uint32_t af[2][4];
            #pragma unroll
            for (int mi = 0; mi < 2; mi++) {
                int r = wm * 32 + mi * 16 + (lane & 15);
                ldsm_x4(af[mi], pA + (cur * 64 + r) * LDS + kc);
            }
            #pragma unroll
            for (int nj = 0; nj < NJ; nj++) {
                uint32_t bf[4];
                int r = wn * WN + nj * 16 + (lane & 15);
                ldsm_x4(bf, pB + (cur * BN + r) * LDS + kc);
                #pragma unroll
                for (int half_ = 0; half_ < 2; half_++)
                    #pragma unroll
                    for (int mi = 0; mi < 2; mi++)
                        mma_f16(acc[mi][nj * 2 + half_], af[mi], bf[half_], bf[2 + half_]);
            }
        }
        if (nxt < 8) storeA(fv, nxt & 1);
        CP_WAIT0();
        __syncthreads();
    }

    // ---- epilogue ----
    #pragma unroll
    for (int mi = 0; mi < 2; mi++) {
        #pragma unroll
        for (int f = 0; f < 2 * NJ; f++) {
            int r0 = row0 + wm * 32 + mi * 16 + (lane >> 2);
            int c  = col0 + wn * WN + f * 8 + (lane & 3) * 2;
            #pragma unroll
            for (int hh = 0; hh < 2; hh++) {
                int r = r0 + hh * 8;
                if (r >= M) continue;
                float v0 = acc[mi][f][hh * 2], v1 = acc[mi][f][hh * 2 + 1];
                if (MODE == 1) {
                    *(__half2*)&g_feat1h[(size_t)r * 256 + c] = __floats2half2_rn(v0, v1);
                } else {
                    *(float2*)&C[(size_t)r * N + c] = make_float2(v0, v1);
                    if (c < 32)
                        *(__half2*)&g_f2h[(size_t)r * 32 + c] = __floats2half2_rn(v0, v1);
                }
            }
        }
    }
}

// ---------------- weight conversion prepasses (zero_deg fused into w1) ----------------
__global__ void convert_w1_kernel(const float* __restrict__ W1) {
    int i = blockIdx.x * blockDim.x + threadIdx.x;   // i = n*256 + k
    if (i < 256 * 256) {
        int n = i >> 8, k = i & 255;
        g_w1t[i] = __float2half_rn(W1[k * 256 + n]);
    }
    if (i < NN) g_deg[i] = 0;
}
__global__ void convert_wcat_kernel(const float* __restrict__ W2, const float* __restrict__ resW2) {
    int i = blockIdx.x * blockDim.x + threadIdx.x;   // i = n*256 + k, n < 64
    if (i < 64 * 256) {
        int n = i >> 8, k = i & 255;
        float v = (n < 32) ? W2[k * 32 + n] : resW2[k * 32 + (n - 32)];
        g_wct[i] = __float2half_rn(v);
    }
}

// ---------------- CSR build ----------------
__global__ void hist_kernel(const int* __restrict__ dst) {
    int e = blockIdx.x * blockDim.x + threadIdx.x;
    if (e < EE) atomicAdd(&g_deg[dst[e]], 1);
}
__global__ void scan1_kernel() {          // grid SCAN_BC, block 1024
    __shared__ int sm[1024];
    int b = blockIdx.x, tid = threadIdx.x;
    int i = b * 1024 + tid;
    int v = (i < NN) ? g_deg[i] : 0;
    sm[tid] = v;
    __syncthreads();
    #pragma unroll
    for (int off = 1; off < 1024; off <<= 1) {
        int t2 = (tid >= off) ? sm[tid - off] : 0;
        __syncthreads();
        sm[tid] += t2;
        __syncthreads();
    }
    if (i < NN) g_rowoff[i] = sm[tid] - v;
    if (tid == 1023) g_bsum[b] = sm[1023];
}
__global__ void scan2_kernel() {          // 1 block, 64 threads
    __shared__ int sm[64];
    int tid = threadIdx.x;
    int v = (tid < SCAN_BC) ? g_bsum[tid] : 0;
    sm[tid] = v;
    __syncthreads();
    #pragma unroll
    for (int off = 1; off < 64; off <<= 1) {
        int t2 = (tid >= off) ? sm[tid - off] : 0;
        __syncthreads();
        sm[tid] += t2;
        __syncthreads();
    }
    if (tid < SCAN_BC) g_boff[tid] = sm[tid] - v;
    if (tid == SCAN_BC - 1) g_rowoff[NN] = sm[tid];
}
__global__ void scan3_kernel() {          // grid SCAN_BC; fuses cursor init
    int b = blockIdx.x;
    int i = b * 1024 + threadIdx.x;
    if (i < NN) {
        int r = g_rowoff[i] + g_boff[b];
        g_rowoff[i] = r;
        g_cursor[i] = r;
    }
}
__global__ void scatter_kernel(const int* __restrict__ src, const int* __restrict__ dst) {
    int e = blockIdx.x * blockDim.x + threadIdx.x;
    if (e < EE) {
        int d = dst[e];
        int slot = atomicAdd(&g_cursor[d], 1);
        g_csr_src[slot] = src[e];
    }
}

// ---------------- attention logits from fp16 features ----------------
__global__ void attn_kernel(const __half* __restrict__ feat, const float* __restrict__ al,
                            const float* __restrict__ ar, float* __restrict__ el,
                            float* __restrict__ er, int NH, int H, int stride) {
    int t = blockIdx.x * blockDim.x + threadIdx.x;
    int w = t >> 5;
    if (w >= NH) return;
    int lane = t & 31;
    int node = w / H;
    int h = w - node * H;
    float f  = __half2float(feat[(size_t)node * stride + h * 32 + lane]);
    float s1 = f * al[h * 32 + lane];
    float s2 = f * ar[h * 32 + lane];
    #pragma unroll
    for (int o = 16; o; o >>= 1) {
        s1 += __shfl_xor_sync(0xffffffffu, s1, o);
        s2 += __shfl_xor_sync(0xffffffffu, s2, o);
    }
    if (lane == 0) { el[w] = s1; er[w] = s2; }
}

// ---------------- layer1 fused softmax+aggregate (fp16 gather) ----------------
#define CHUNK 128
__global__ void __launch_bounds__(256) agg1_kernel(const float* __restrict__ x,
                                                   const float* __restrict__ b1) {
    __shared__ float sw[CHUNK][H1];
    __shared__ int   sj[CHUNK];
    int n = blockIdx.x;
    int tid = threadIdx.x;
    int h = tid >> 5, lane = tid & 31;
    int beg = g_rowoff[n], end = g_rowoff[n + 1];
    float s = 0.f, acc = 0.f;
    for (int cb = beg; cb < end; cb += CHUNK) {
        int cnt = min(CHUNK, end - cb);
        for (int idx = tid; idx < cnt * H1; idx += 256) {
            int j = idx >> 3, ha = idx & 7;
            int sn = g_csr_src[cb + j];
            if (ha == 0) sj[j] = sn;
            float e = g_el1[sn * H1 + ha] + g_er1[n * H1 + ha];
            e = e > 0.f ? e : NEG_SLOPE * e;
            sw[j][ha] = __expf(e);
        }
        __syncthreads();
        int j = 0;
        for (; j + 1 < cnt; j += 2) {
            float w0 = sw[j][h], w1 = sw[j + 1][h];
            int s0 = sj[j], s1 = sj[j + 1];
            float f0 = __half2float(g_feat1h[(size_t)s0 * 256 + h * 32 + lane]);
            float f1 = __half2float(g_feat1h[(size_t)s1 * 256 + h * 32 + lane]);
            s   += w0 + w1;
            acc += w0 * f0 + w1 * f1;
        }
        if (j < cnt) {
            float w0 = sw[j][h];
            s   += w0;
            acc += w0 * __half2float(g_feat1h[(size_t)sj[j] * 256 + h * 32 + lane]);
        }
        __syncthreads();
    }
    float inv = (end > beg) ? 1.0f / s : 0.f;
    int o = n * 256 + h * 32 + lane;
    g_y[o] = fmaxf(acc * inv + x[o] + b1[h * 32 + lane], 0.f);   // residual + bias + relu
}

// ---------------- layer2 fused softmax+aggregate: warp per node (fp16 gather) ----
__global__ void agg2_kernel(const float* __restrict__ b2, float* __restrict__ out) {
    int t = blockIdx.x * blockDim.x + threadIdx.x;
    int n = t >> 5;
    if (n >= NN) return;
    int lane = t & 31;
    int beg = g_rowoff[n], end = g_rowoff[n + 1];
    float ern = g_er2[n];
    float s = 0.f, acc = 0.f;
    int i = beg;
    for (; i + 1 < end; i += 2) {
        int s0 = g_csr_src[i], s1 = g_csr_src[i + 1];
        float e0 = g_el2[s0] + ern;
        float e1 = g_el2[s1] + ern;
        e0 = e0 > 0.f ? e0 : NEG_SLOPE * e0;
        e1 = e1 > 0.f ? e1 : NEG_SLOPE * e1;
        float w0 = __expf(e0), w1 = __expf(e1);
        float f0 = __half2float(g_f2h[(size_t)s0 * 32 + lane]);
        float f1 = __half2float(g_f2h[(size_t)s1 * 32 + lane]);
        s   += w0 + w1;
        acc += w0 * f0 + w1 * f1;
    }
    if (i < end) {
        int s0 = g_csr_src[i];
        float e0 = g_el2[s0] + ern;
        e0 = e0 > 0.f ? e0 : NEG_SLOPE * e0;
        float w0 = __expf(e0);
        s   += w0;
        acc += w0 * __half2float(g_f2h[(size_t)s0 * 32 + lane]);
    }
    float inv = (end > beg) ? 1.0f / s : 0.f;
    out[n * 32 + lane] = acc * inv + g_f2[(size_t)n * 64 + 32 + lane] + b2[lane];
}

// ---------------- launch ----------------
extern "C" void kernel_launch(void* const* d_in, const int* in_sizes, int n_in,
                              void* d_out, int out_size) {
    const float* x     = (const float*)d_in[0];
    const int*   src   = (const int*)d_in[1];
    const int*   dst   = (const int*)d_in[2];
    const float* W1    = (const float*)d_in[3];
    const float* al1   = (const float*)d_in[4];
    const float* ar1   = (const float*)d_in[5];
    const float* b1    = (const float*)d_in[6];
    const float* W2    = (const float*)d_in[7];
    const float* al2   = (const float*)d_in[8];
    const float* ar2   = (const float*)d_in[9];
    const float* resW2 = (const float*)d_in[10];
    const float* b2    = (const float*)d_in[11];
    float* out = (float*)d_out;

    float *yb, *el1, *er1, *f2, *el2, *er2;
    __half *f1h, *f2h, *w1t, *wct;
    cudaGetSymbolAddress((void**)&yb,   g_y);
    cudaGetSymbolAddress((void**)&el1,  g_el1);
    cudaGetSymbolAddress((void**)&er1,  g_er1);
    cudaGetSymbolAddress((void**)&f2,   g_f2);
    cudaGetSymbolAddress((void**)&el2,  g_el2);
    cudaGetSymbolAddress((void**)&er2,  g_er2);
    cudaGetSymbolAddress((void**)&f1h,  g_feat1h);
    cudaGetSymbolAddress((void**)&f2h,  g_f2h);
    cudaGetSymbolAddress((void**)&w1t,  g_w1t);
    cudaGetSymbolAddress((void**)&wct,  g_wct);

    const int LDSC = 40;
    const int smem128 = (2 * 64 * LDSC + 2 * 128 * LDSC) * 2;   // 30720 B
    const int smem64  = (2 * 64 * LDSC + 2 * 64 * LDSC) * 2;    // 20480 B
    cudaFuncSetAttribute(mma_gemm_kernel<128, 1>,
                         cudaFuncAttributeMaxDynamicSharedMemorySize, smem128);
    cudaFuncSetAttribute(mma_gemm_kernel<64, 2>,
                         cudaFuncAttributeMaxDynamicSharedMemorySize, smem64);

    // slots 1-3 (gemm1 lands in profiled slot 4)
    convert_w1_kernel<<<(256 * 256 + 255) / 256, 256>>>(W1);    // + zero_deg fused
    convert_wcat_kernel<<<(64 * 256 + 255) / 256, 256>>>(W2, resW2);
    hist_kernel<<<(EE + 255) / 256, 256>>>(dst);

    // slot 4: layer-1 GEMM (fp16 single-term; writes fp16 feat only)
    mma_gemm_kernel<128, 1><<<dim3(2, (NN + 63) / 64), 256, smem128>>>(x, w1t, nullptr, NN, 256);

    // CSR finish
    scan1_kernel<<<SCAN_BC, 1024>>>();
    scan2_kernel<<<1, 64>>>();
    scan3_kernel<<<SCAN_BC, 1024>>>();
    scatter_kernel<<<(EE + 255) / 256, 256>>>(src, dst);

    // layer 1 attention + aggregation
    attn_kernel<<<(NN * H1 * 32 + 255) / 256, 256>>>(f1h, al1, ar1, el1, er1, NN * H1, H1, 256);
    agg1_kernel<<<NN, 256>>>(x, b1);

    // layer 2
    mma_gemm_kernel<64, 2><<<dim3(1, (NN + 63) / 64), 256, smem64>>>(yb, wct, f2, NN, 64);
    attn_kernel<<<(NN * 32 + 255) / 256, 256>>>(f2h, al2, ar2, el2, er2, NN, 1, 32);
    agg2_kernel<<<(NN * 32 + 255) / 256, 256>>>(b2, out);
}

// round 12
// speedup vs baseline: 3.0937x; 1.3579x over previous
#include <cuda_runtime.h>
#include <cuda_fp16.h>
#include <math.h>
#include <stdint.h>

#define NN 50000
#define EE 800000
#define H1 8
#define NEG_SLOPE 0.2f
#define SCAN_BC ((NN + 1023) / 1024)   // 49

// ---------------- scratch (device globals; no allocation allowed) ----------------
__device__ __half g_feat1h[NN * 256];        // layer1 features (fp16 gather)
__device__ float  g_y[NN * 256];             // layer1 output (fp32, after relu)
__device__ float  g_el1[NN * H1];
__device__ float  g_er1[NN * H1];
__device__ float  g_f2[NN * 64];             // [ feat2 (0..31) | res2 (32..63) ] fp32
__device__ __half g_f2h[NN * 32];            // fp16 copy of feat2 (agg2 gather)
__device__ float  g_el2[NN];
__device__ float  g_er2[NN];
__device__ __half g_w1t[256 * 256];          // W1^T [n][k] fp16
__device__ __half g_wct[64 * 256];           // [W2|resW2]^T [n][k] fp16
__device__ int   g_deg[NN];
__device__ int   g_rowoff[NN + 1];
__device__ int   g_cursor[NN];
__device__ int   g_csr_src[EE];
__device__ int   g_bsum[SCAN_BC];
__device__ int   g_boff[SCAN_BC];

// ---------------- helpers ----------------
__device__ __forceinline__ uint32_t smem_u32(const void* p) {
    uint32_t a;
    asm("{ .reg .u64 t; cvta.to.shared.u64 t, %1; cvt.u32.u64 %0, t; }" : "=r"(a) : "l"(p));
    return a;
}
__device__ __forceinline__ void ldsm_x4(uint32_t (&r)[4], const void* p) {
    uint32_t a = smem_u32(p);
    asm volatile("ldmatrix.sync.aligned.m8n8.x4.shared.b16 {%0,%1,%2,%3}, [%4];"
                 : "=r"(r[0]), "=r"(r[1]), "=r"(r[2]), "=r"(r[3]) : "r"(a));
}
__device__ __forceinline__ void mma_f16(float (&d)[4], const uint32_t (&a)[4],
                                        uint32_t b0, uint32_t b1) {
    asm volatile("mma.sync.aligned.m16n8k16.row.col.f32.f16.f16.f32 "
                 "{%0,%1,%2,%3},{%4,%5,%6,%7},{%8,%9},{%0,%1,%2,%3};"
                 : "+f"(d[0]), "+f"(d[1]), "+f"(d[2]), "+f"(d[3])
                 : "r"(a[0]), "r"(a[1]), "r"(a[2]), "r"(a[3]), "r"(b0), "r"(b1));
}
__device__ __forceinline__ void cp16(uint32_t dst, const void* src) {
    asm volatile("cp.async.cg.shared.global [%0], [%1], 16;" :: "r"(dst), "l"(src));
}
#define CP_COMMIT() asm volatile("cp.async.commit_group;" ::: "memory")
#define CP_WAIT0()  asm volatile("cp.async.wait_group 0;" ::: "memory")

// ============ fp16 tensor-core GEMM + fused attention epilogue ============
// C = A[M,256] @ B[256,N]; A fp32 (converted in-register), B^T fp16 [N][256].
// BM=64, BK=32, 8 warps 2(M)x4(N), cp.async double-buffered.
// MODE 1 (layer1, BN=128): write fp16 feat1h; epilogue computes el1/er1
//   (each warp-col group wn owns ONE head; exclusive store, no atomics).
// MODE 2 (layer2, BN=64): write fp32 C + fp16 copy of cols 0..31; epilogue
//   accumulates el2/er2 for head 0 (cols<32) via atomicAdd (zeroed upstream).
template<int BN, int MODE>
__global__ void __launch_bounds__(256, 3) mma_gemm_kernel(
        const float* __restrict__ A, const __half* __restrict__ Bt,
        float* __restrict__ C, const float* __restrict__ av,
        const float* __restrict__ rv, int M, int N) {
    constexpr int LDS = 40;
    constexpr int WN  = BN / 4;
    constexpr int NJ  = WN / 16;
    extern __shared__ __half dyn[];
    __half* pA = dyn;                         // [2][64][LDS]
    __half* pB = dyn + 2 * 64 * LDS;          // [2][BN][LDS]

    int tid = threadIdx.x, lane = tid & 31, wid = tid >> 5;
    int wm = wid & 1, wn = wid >> 1;
    int row0 = blockIdx.y * 64, col0 = blockIdx.x * BN;
    float acc[2][2 * NJ][4] = {};

    int rA = tid >> 2, cA = (tid & 3) * 8;
    const float* aBase = &A[(size_t)(row0 + rA) * 256 + cA];
    bool aValid = (row0 + rA < M);

    auto loadB = [&](int k0, int b) {
        #pragma unroll
        for (int t = 0; t < BN / 64; t++) {
            int v = tid + t * 256;
            int r = v >> 2, c = (v & 3) * 8;
            cp16(smem_u32(pB + (b * BN + r) * LDS + c), &Bt[(size_t)(col0 + r) * 256 + k0 + c]);
        }
        CP_COMMIT();
    };
    auto storeA = [&](const float* fv, int b) {
        union { __half hh[8]; uint4 u; } uc;
        #pragma unroll
        for (int e = 0; e < 8; e++) uc.hh[e] = __float2half_rn(fv[e]);
        *(uint4*)(pA + (b * 64 + rA) * LDS + cA) = uc.u;
    };

    loadB(0, 0);
    {
        float fv[8] = {};
        if (aValid) { *(float4*)fv = *(const float4*)aBase; *(float4*)(fv + 4) = *(const float4*)(aBase + 4); }
        storeA(fv, 0);
    }
    CP_WAIT0();
    __syncthreads();

    for (int chunk = 0; chunk < 8; chunk++) {
        int cur = chunk & 1, nxt = chunk + 1;
        float fv[8] = {};
        if (nxt < 8) {
            loadB(nxt * 32, nxt & 1);
            if (aValid) {
                const float* ap = aBase + nxt * 32;
                *(float4*)fv = *(const float4*)ap;
                *(float4*)(fv + 4) = *(const float4*)(ap + 4);
            }
        }
        #pragma unroll
        for (int kk = 0; kk < 2; kk++) {
            int kc = kk * 16 + (lane >> 4) * 8;
            uint32_t af[2][4];
            #pragma unroll
            for (int mi = 0; mi < 2; mi++) {
                int r = wm * 32 + mi * 16 + (lane & 15);
                ldsm_x4(af[mi], pA + (cur * 64 + r) * LDS + kc);
            }
            #pragma unroll
            for (int nj = 0; nj < NJ; nj++) {
                uint32_t bf[4];
                int r = wn * WN + nj * 16 + (lane & 15);
                ldsm_x4(bf, pB + (cur * BN + r) * LDS + kc);
                #pragma unroll
                for (int half_ = 0; half_ < 2; half_++)
                    #pragma unroll
                    for (int mi = 0; mi < 2; mi++)
                        mma_f16(acc[mi][nj * 2 + half_], af[mi], bf[half_], bf[2 + half_]);
            }
        }
        if (nxt < 8) storeA(fv, nxt & 1);
        CP_WAIT0();
        __syncthreads();
    }

    // ---- epilogue: store + fused attention partials ----
    float elp[4] = {}, erp[4] = {};           // ri = mi*2+hh -> row q + {0,8,16,24}
    #pragma unroll
    for (int mi = 0; mi < 2; mi++) {
        #pragma unroll
        for (int f = 0; f < 2 * NJ; f++) {
            int r0 = row0 + wm * 32 + mi * 16 + (lane >> 2);
            int c  = col0 + wn * WN + f * 8 + (lane & 3) * 2;
            #pragma unroll
            for (int hh = 0; hh < 2; hh++) {
                int r = r0 + hh * 8;
                if (r >= M) continue;
                float v0 = acc[mi][f][hh * 2], v1 = acc[mi][f][hh * 2 + 1];
                int ri = mi * 2 + hh;
                if (MODE == 1) {
                    *(__half2*)&g_feat1h[(size_t)r * 256 + c] = __floats2half2_rn(v0, v1);
                    elp[ri] += v0 * av[c] + v1 * av[c + 1];
                    erp[ri] += v0 * rv[c] + v1 * rv[c + 1];
                } else {
                    *(float2*)&C[(size_t)r * N + c] = make_float2(v0, v1);
                    if (c < 32) {
                        *(__half2*)&g_f2h[(size_t)r * 32 + c] = __floats2half2_rn(v0, v1);
                        elp[ri] += v0 * av[c] + v1 * av[c + 1];
                        erp[ri] += v0 * rv[c] + v1 * rv[c + 1];
                    }
                }
            }
        }
    }
    // reduce over the 4-lane column group
    #pragma unroll
    for (int ri = 0; ri < 4; ri++) {
        #pragma unroll
        for (int o = 1; o <= 2; o <<= 1) {
            elp[ri] += __shfl_xor_sync(0xffffffffu, elp[ri], o);
            erp[ri] += __shfl_xor_sync(0xffffffffu, erp[ri], o);
        }
    }
    if ((lane & 3) == 0) {
        int q = row0 + wm * 32 + (lane >> 2);
        if (MODE == 1) {
            int head = (col0 >> 5) + wn;          // WN==32: one head per wn
            #pragma unroll
            for (int ri = 0; ri < 4; ri++) {
                int r = q + (ri & 1) * 8 + (ri >> 1) * 16;
                if (r < M) {
                    g_el1[r * H1 + head] = elp[ri];
                    g_er1[r * H1 + head] = erp[ri];
                }
            }
        } else if (wn < 2) {                      // cols 0..31 only
            #pragma unroll
            for (int ri = 0; ri < 4; ri++) {
                int r = q + (ri & 1) * 8 + (ri >> 1) * 16;
                if (r < M) {
                    atomicAdd(&g_el2[r], elp[ri]);
                    atomicAdd(&g_er2[r], erp[ri]);
                }
            }
        }
    }
}

// ---------------- fused conversions: W1^T, [W2|resW2]^T, zero deg ----------------
__global__ void convert_w_kernel(const float* __restrict__ W1, const float* __restrict__ W2,
                                 const float* __restrict__ resW2) {
    int i = blockIdx.x * blockDim.x + threadIdx.x;   // i = n*256 + k
    if (i < 256 * 256) {
        int n = i >> 8, k = i & 255;
        g_w1t[i] = __float2half_rn(W1[k * 256 + n]);
        if (n < 64) {
            float v = (n < 32) ? W2[k * 32 + n] : resW2[k * 32 + (n - 32)];
            g_wct[i] = __float2half_rn(v);       // i = n*256+k valid for n<64
        }
    }
    if (i < NN) g_deg[i] = 0;
}

// ---------------- CSR build (+ el2/er2 zeroing) ----------------
__global__ void hist_kernel(const int* __restrict__ dst) {
    int e = blockIdx.x * blockDim.x + threadIdx.x;
    if (e < EE) atomicAdd(&g_deg[dst[e]], 1);
    if (e < NN) { g_el2[e] = 0.f; g_er2[e] = 0.f; }
}
__global__ void scan1_kernel() {
    __shared__ int sm[1024];
    int b = blockIdx.x, tid = threadIdx.x;
    int i = b * 1024 + tid;
    int v = (i < NN) ? g_deg[i] : 0;
    sm[tid] = v;
    __syncthreads();
    #pragma unroll
    for (int off = 1; off < 1024; off <<= 1) {
        int t2 = (tid >= off) ? sm[tid - off] : 0;
        __syncthreads();
        sm[tid] += t2;
        __syncthreads();
    }
    if (i < NN) g_rowoff[i] = sm[tid] - v;
    if (tid == 1023) g_bsum[b] = sm[1023];
}
__global__ void scan2_kernel() {
    __shared__ int sm[64];
    int tid = threadIdx.x;
    int v = (tid < SCAN_BC) ? g_bsum[tid] : 0;
    sm[tid] = v;
    __syncthreads();
    #pragma unroll
    for (int off = 1; off < 64; off <<= 1) {
        int t2 = (tid >= off) ? sm[tid - off] : 0;
        __syncthreads();
        sm[tid] += t2;
        __syncthreads();
    }
    if (tid < SCAN_BC) g_boff[tid] = sm[tid] - v;
    if (tid == SCAN_BC - 1) g_rowoff[NN] = sm[tid];
}
__global__ void scan3_kernel() {
    int b = blockIdx.x;
    int i = b * 1024 + threadIdx.x;
    if (i < NN) {
        int r = g_rowoff[i] + g_boff[b];
        g_rowoff[i] = r;
        g_cursor[i] = r;
    }
}
__global__ void scatter_kernel(const int* __restrict__ src, const int* __restrict__ dst) {
    int e = blockIdx.x * blockDim.x + threadIdx.x;
    if (e < EE) {
        int d = dst[e];
        int slot = atomicAdd(&g_cursor[d], 1);
        g_csr_src[slot] = src[e];
    }
}

// ---------------- layer1 fused softmax+aggregate (half2 gather) ----------------
// Phase A: weights for all heads coalesced into smem (exp deduped).
// Phase B: 4 column-groups x 2 edge-parities; lane loads half2 (2 cols),
//          per-lane head = 2*grp + (lane>>4); combine parities via smem.
#define CHUNK 128
__global__ void __launch_bounds__(256) agg1_kernel(const float* __restrict__ x,
                                                   const float* __restrict__ b1) {
    __shared__ float sw[CHUNK][H1];
    __shared__ int   sj[CHUNK];
    __shared__ float2 sacc[4][32];
    __shared__ float  ssum[4][32];
    int n = blockIdx.x;
    int tid = threadIdx.x;
    int lane = tid & 31, w = tid >> 5;
    int grp = w & 3, par = w >> 2;            // column group, edge parity
    int ha = 2 * grp + (lane >> 4);           // head for this lane
    int beg = g_rowoff[n], end = g_rowoff[n + 1];
    float2 acc = make_float2(0.f, 0.f);
    float s = 0.f;
    for (int cb = beg; cb < end; cb += CHUNK) {
        int cnt = min(CHUNK, end - cb);
        for (int idx = tid; idx < cnt * H1; idx += 256) {
            int j = idx >> 3, hh = idx & 7;
            int sn = g_csr_src[cb + j];
            if (hh == 0) sj[j] = sn;
            float e = g_el1[sn * H1 + hh] + g_er1[n * H1 + hh];
            e = e > 0.f ? e : NEG_SLOPE * e;
            sw[j][hh] = __expf(e);
        }
        __syncthreads();
        for (int j = par; j < cnt; j += 2) {
            int sn = sj[j];
            float w0 = sw[j][ha];
            __half2 hv = *(const __half2*)&g_feat1h[(size_t)sn * 256 + grp * 64 + lane * 2];
            float2 f = __half22float2(hv);
            s += w0;
            acc.x += w0 * f.x;
            acc.y += w0 * f.y;
        }
        __syncthreads();
    }
    if (par == 1) { sacc[grp][lane] = acc; ssum[grp][lane] = s; }
    __syncthreads();
    if (par == 0) {
        acc.x += sacc[grp][lane].x;
        acc.y += sacc[grp][lane].y;
        s     += ssum[grp][lane];
        float inv = (end > beg) ? 1.0f / s : 0.f;
        int o = n * 256 + grp * 64 + lane * 2;
        float2 xr = *(const float2*)&x[o];
        float2 bb = *(const float2*)&b1[grp * 64 + lane * 2];
        float r0 = fmaxf(acc.x * inv + xr.x + bb.x, 0.f);
        float r1 = fmaxf(acc.y * inv + xr.y + bb.y, 0.f);
        *(float2*)&g_y[o] = make_float2(r0, r1);
    }
}

// ---------------- layer2 fused softmax+aggregate (half-warp parity, half2) ----
__global__ void agg2_kernel(const float* __restrict__ b2, float* __restrict__ out) {
    int t = blockIdx.x * blockDim.x + threadIdx.x;
    int n = t >> 5;
    if (n >= NN) return;
    int lane = t & 31;
    int par = lane >> 4;                       // edge parity
    int cl = (lane & 15) * 2;                  // column pair
    int beg = g_rowoff[n], end = g_rowoff[n + 1];
    float ern = g_er2[n];
    float2 acc = make_float2(0.f, 0.f);
    float s = 0.f;
    for (int i = beg + par; i < end; i += 2) {
        int sn = g_csr_src[i];
        float e0 = g_el2[sn] + ern;
        e0 = e0 > 0.f ? e0 : NEG_SLOPE * e0;
        float w0 = __expf(e0);
        __half2 hv = *(const __half2*)&g_f2h[(size_t)sn * 32 + cl];
        float2 f = __half22float2(hv);
        s += w0;
        acc.x += w0 * f.x;
        acc.y += w0 * f.y;
    }
    acc.x += __shfl_xor_sync(0xffffffffu, acc.x, 16);
    acc.y += __shfl_xor_sync(0xffffffffu, acc.y, 16);
    s     += __shfl_xor_sync(0xffffffffu, s, 16);
    if (par == 0) {
        float inv = (end > beg) ? 1.0f / s : 0.f;
        float2 rr = *(const float2*)&g_f2[(size_t)n * 64 + 32 + cl];
        float2 bb = *(const float2*)&b2[cl];
        *(float2*)&out[n * 32 + cl] =
            make_float2(acc.x * inv + rr.x + bb.x, acc.y * inv + rr.y + bb.y);
    }
}

// ---------------- launch ----------------
extern "C" void kernel_launch(void* const* d_in, const int* in_sizes, int n_in,
                              void* d_out, int out_size) {
    const float* x     = (const float*)d_in[0];
    const int*   src   = (const int*)d_in[1];
    const int*   dst   = (const int*)d_in[2];
    const float* W1    = (const float*)d_in[3];
    const float* al1   = (const float*)d_in[4];
    const float* ar1   = (const float*)d_in[5];
    const float* b1    = (const float*)d_in[6];
    const float* W2    = (const float*)d_in[7];
    const float* al2   = (const float*)d_in[8];
    const float* ar2   = (const float*)d_in[9];
    const float* resW2 = (const float*)d_in[10];
    const float* b2    = (const float*)d_in[11];
    float* out = (float*)d_out;

    float *yb, *f2;
    __half *w1t, *wct;
    cudaGetSymbolAddress((void**)&yb,   g_y);
    cudaGetSymbolAddress((void**)&f2,   g_f2);
    cudaGetSymbolAddress((void**)&w1t,  g_w1t);
    cudaGetSymbolAddress((void**)&wct,  g_wct);

    const int LDSC = 40;
    const int smem128 = (2 * 64 * LDSC + 2 * 128 * LDSC) * 2;   // 30720 B
    const int smem64  = (2 * 64 * LDSC + 2 * 64 * LDSC) * 2;    // 20480 B
    cudaFuncSetAttribute(mma_gemm_kernel<128, 1>,
                         cudaFuncAttributeMaxDynamicSharedMemorySize, smem128);
    cudaFuncSetAttribute(mma_gemm_kernel<64, 2>,
                         cudaFuncAttributeMaxDynamicSharedMemorySize, smem64);

    // slots 1-3 (gemm1 lands in profiled slot 4)
    convert_w_kernel<<<(256 * 256 + 255) / 256, 256>>>(W1, W2, resW2);
    hist_kernel<<<(EE + 255) / 256, 256>>>(dst);
    scan1_kernel<<<SCAN_BC, 1024>>>();

    // slot 4: layer-1 GEMM + fused attn (writes feat1h, el1, er1)
    mma_gemm_kernel<128, 1><<<dim3(2, (NN + 63) / 64), 256, smem128>>>(
        x, w1t, nullptr, al1, ar1, NN, 256);

    // CSR finish
    scan2_kernel<<<1, 64>>>();
    scan3_kernel<<<SCAN_BC, 1024>>>();
    scatter_kernel<<<(EE + 255) / 256, 256>>>(src, dst);

    // layer 1 aggregation
    agg1_kernel<<<NN, 256>>>(x, b1);

    // layer 2: GEMM + fused attn (writes f2, f2h, el2, er2), then aggregate
    mma_gemm_kernel<64, 2><<<dim3(1, (NN + 63) / 64), 256, smem64>>>(
        yb, wct, f2, al2, ar2, NN, 64);
    agg2_kernel<<<(NN * 32 + 255) / 256, 256>>>(b2, out);
}

// round 13
// speedup vs baseline: 3.2107x; 1.0378x over previous
#include <cuda_runtime.h>
#include <cuda_fp16.h>
#include <math.h>
#include <stdint.h>

#define NN 50000
#define EE 800000
#define H1 8
#define NEG_SLOPE 0.2f
#define SCAN_BC ((NN + 1023) / 1024)   // 49

// ---------------- scratch (device globals; no allocation allowed) ----------------
__device__ __half g_feat1h[NN * 256];        // layer1 features (fp16 gather)
__device__ float  g_y[NN * 256];             // layer1 output (fp32, after relu)
__device__ float  g_el1[NN * H1];
__device__ float  g_er1[NN * H1];
__device__ float  g_f2[NN * 64];             // [ feat2 (0..31) | res2 (32..63) ] fp32
__device__ __half g_f2h[NN * 32];            // fp16 copy of feat2 (agg2 gather)
__device__ float  g_el2[NN];
__device__ float  g_er2[NN];
__device__ __half g_w1t[256 * 256];          // W1^T [n][k] fp16
__device__ __half g_wct[64 * 256];           // [W2|resW2]^T [n][k] fp16
__device__ int   g_deg[NN];
__device__ int   g_rowoff[NN + 1];
__device__ int   g_cursor[NN];
__device__ int   g_csr_src[EE];
__device__ int   g_bsum[SCAN_BC];
__device__ int   g_boff[SCAN_BC];

// ---------------- helpers ----------------
__device__ __forceinline__ uint32_t smem_u32(const void* p) {
    uint32_t a;
    asm("{ .reg .u64 t; cvta.to.shared.u64 t, %1; cvt.u32.u64 %0, t; }" : "=r"(a) : "l"(p));
    return a;
}
__device__ __forceinline__ void ldsm_x4(uint32_t (&r)[4], const void* p) {
    uint32_t a = smem_u32(p);
    asm volatile("ldmatrix.sync.aligned.m8n8.x4.shared.b16 {%0,%1,%2,%3}, [%4];"
                 : "=r"(r[0]), "=r"(r[1]), "=r"(r[2]), "=r"(r[3]) : "r"(a));
}
__device__ __forceinline__ void mma_f16(float (&d)[4], const uint32_t (&a)[4],
                                        uint32_t b0, uint32_t b1) {
    asm volatile("mma.sync.aligned.m16n8k16.row.col.f32.f16.f16.f32 "
                 "{%0,%1,%2,%3},{%4,%5,%6,%7},{%8,%9},{%0,%1,%2,%3};"
                 : "+f"(d[0]), "+f"(d[1]), "+f"(d[2]), "+f"(d[3])
                 : "r"(a[0]), "r"(a[1]), "r"(a[2]), "r"(a[3]), "r"(b0), "r"(b1));
}
__device__ __forceinline__ void cp16(uint32_t dst, const void* src) {
    asm volatile("cp.async.cg.shared.global [%0], [%1], 16;" :: "r"(dst), "l"(src));
}
#define CP_COMMIT() asm volatile("cp.async.commit_group;" ::: "memory")
#define CP_WAIT0()  asm volatile("cp.async.wait_group 0;" ::: "memory")

// ============ fp16 tensor-core GEMM + fused attention epilogue ============
// (identical to R12 — unchanged kernels, launch graph restructured only)
template<int BN, int MODE>
__global__ void __launch_bounds__(256, 3) mma_gemm_kernel(
        const float* __restrict__ A, const __half* __restrict__ Bt,
        float* __restrict__ C, const float* __restrict__ av,
        const float* __restrict__ rv, int M, int N) {
    constexpr int LDS = 40;
    constexpr int WN  = BN / 4;
    constexpr int NJ  = WN / 16;
    extern __shared__ __half dyn[];
    __half* pA = dyn;                         // [2][64][LDS]
    __half* pB = dyn + 2 * 64 * LDS;          // [2][BN][LDS]

    int tid = threadIdx.x, lane = tid & 31, wid = tid >> 5;
    int wm = wid & 1, wn = wid >> 1;
    int row0 = blockIdx.y * 64, col0 = blockIdx.x * BN;
    float acc[2][2 * NJ][4] = {};

    int rA = tid >> 2, cA = (tid & 3) * 8;
    const float* aBase = &A[(size_t)(row0 + rA) * 256 + cA];
    bool aValid = (row0 + rA < M);

    auto loadB = [&](int k0, int b) {
        #pragma unroll
        for (int t = 0; t < BN / 64; t++) {
            int v = tid + t * 256;
            int r = v >> 2, c = (v & 3) * 8;
            cp16(smem_u32(pB + (b * BN + r) * LDS + c), &Bt[(size_t)(col0 + r) * 256 + k0 + c]);
        }
        CP_COMMIT();
    };
    auto storeA = [&](const float* fv, int b) {
        union { __half hh[8]; uint4 u; } uc;
        #pragma unroll
        for (int e = 0; e < 8; e++) uc.hh[e] = __float2half_rn(fv[e]);
        *(uint4*)(pA + (b * 64 + rA) * LDS + cA) = uc.u;
    };

    loadB(0, 0);
    {
        float fv[8] = {};
        if (aValid) { *(float4*)fv = *(const float4*)aBase; *(float4*)(fv + 4) = *(const float4*)(aBase + 4); }
        storeA(fv, 0);
    }
    CP_WAIT0();
    __syncthreads();

    for (int chunk = 0; chunk < 8; chunk++) {
        int cur = chunk & 1, nxt = chunk + 1;
        float fv[8] = {};
        if (nxt < 8) {
            loadB(nxt * 32, nxt & 1);
            if (aValid) {
                const float* ap = aBase + nxt * 32;
                *(float4*)fv = *(const float4*)ap;
                *(float4*)(fv + 4) = *(const float4*)(ap + 4);
            }
        }
        #pragma unroll
        for (int kk = 0; kk < 2; kk++) {
            int kc = kk * 16 + (lane >> 4) * 8;
            uint32_t af[2][4];
            #pragma unroll
            for (int mi = 0; mi < 2; mi++) {
                int r = wm * 32 + mi * 16 + (lane & 15);
                ldsm_x4(af[mi], pA + (cur * 64 + r) * LDS + kc);
            }
            #pragma unroll
            for (int nj = 0; nj < NJ; nj++) {
                uint32_t bf[4];
                int r = wn * WN + nj * 16 + (lane & 15);
                ldsm_x4(bf, pB + (cur * BN + r) * LDS + kc);
                #pragma unroll
                for (int half_ = 0; half_ < 2; half_++)
                    #pragma unroll
                    for (int mi = 0; mi < 2; mi++)
                        mma_f16(acc[mi][nj * 2 + half_], af[mi], bf[half_], bf[2 + half_]);
            }
        }
        if (nxt < 8) storeA(fv, nxt & 1);
        CP_WAIT0();
        __syncthreads();
    }

    // ---- epilogue: store + fused attention partials ----
    float elp[4] = {}, erp[4] = {};
    #pragma unroll
    for (int mi = 0; mi < 2; mi++) {
        #pragma unroll
        for (int f = 0; f < 2 * NJ; f++) {
            int r0 = row0 + wm * 32 + mi * 16 + (lane >> 2);
            int c  = col0 + wn * WN + f * 8 + (lane & 3) * 2;
            #pragma unroll
            for (int hh = 0; hh < 2; hh++) {
                int r = r0 + hh * 8;
                if (r >= M) continue;
                float v0 = acc[mi][f][hh * 2], v1 = acc[mi][f][hh * 2 + 1];
                int ri = mi * 2 + hh;
                if (MODE == 1) {
                    *(__half2*)&g_feat1h[(size_t)r * 256 + c] = __floats2half2_rn(v0, v1);
                    elp[ri] += v0 * av[c] + v1 * av[c + 1];
                    erp[ri] += v0 * rv[c] + v1 * rv[c + 1];
                } else {
                    *(float2*)&C[(size_t)r * N + c] = make_float2(v0, v1);
                    if (c < 32) {
                        *(__half2*)&g_f2h[(size_t)r * 32 + c] = __floats2half2_rn(v0, v1);
                        elp[ri] += v0 * av[c] + v1 * av[c + 1];
                        erp[ri] += v0 * rv[c] + v1 * rv[c + 1];
                    }
                }
            }
        }
    }
    #pragma unroll
    for (int ri = 0; ri < 4; ri++) {
        #pragma unroll
        for (int o = 1; o <= 2; o <<= 1) {
            elp[ri] += __shfl_xor_sync(0xffffffffu, elp[ri], o);
            erp[ri] += __shfl_xor_sync(0xffffffffu, erp[ri], o);
        }
    }
    if ((lane & 3) == 0) {
        int q = row0 + wm * 32 + (lane >> 2);
        if (MODE == 1) {
            int head = (col0 >> 5) + wn;
            #pragma unroll
            for (int ri = 0; ri < 4; ri++) {
                int r = q + (ri & 1) * 8 + (ri >> 1) * 16;
                if (r < M) {
                    g_el1[r * H1 + head] = elp[ri];
                    g_er1[r * H1 + head] = erp[ri];
                }
            }
        } else if (wn < 2) {
            #pragma unroll
            for (int ri = 0; ri < 4; ri++) {
                int r = q + (ri & 1) * 8 + (ri >> 1) * 16;
                if (r < M) {
                    atomicAdd(&g_el2[r], elp[ri]);
                    atomicAdd(&g_er2[r], erp[ri]);
                }
            }
        }
    }
}

// ---------------- weight conversion (GEMM branch) ----------------
__global__ void convert_w_kernel(const float* __restrict__ W1, const float* __restrict__ W2,
                                 const float* __restrict__ resW2) {
    int i = blockIdx.x * blockDim.x + threadIdx.x;   // i = n*256 + k
    if (i < 256 * 256) {
        int n = i >> 8, k = i & 255;
        g_w1t[i] = __float2half_rn(W1[k * 256 + n]);
        if (n < 64) {
            float v = (n < 32) ? W2[k * 32 + n] : resW2[k * 32 + (n - 32)];
            g_wct[i] = __float2half_rn(v);
        }
    }
}

// ---------------- CSR branch ----------------
__global__ void zero_kernel() {                      // head of CSR branch
    int i = blockIdx.x * blockDim.x + threadIdx.x;
    if (i < NN) { g_deg[i] = 0; g_el2[i] = 0.f; g_er2[i] = 0.f; }
}
__global__ void hist_kernel(const int* __restrict__ dst) {
    int e = blockIdx.x * blockDim.x + threadIdx.x;
    if (e < EE) atomicAdd(&g_deg[dst[e]], 1);
}
__global__ void scan1_kernel() {
    __shared__ int sm[1024];
    int b = blockIdx.x, tid = threadIdx.x;
    int i = b * 1024 + tid;
    int v = (i < NN) ? g_deg[i] : 0;
    sm[tid] = v;
    __syncthreads();
    #pragma unroll
    for (int off = 1; off < 1024; off <<= 1) {
        int t2 = (tid >= off) ? sm[tid - off] : 0;
        __syncthreads();
        sm[tid] += t2;
        __syncthreads();
    }
    if (i < NN) g_rowoff[i] = sm[tid] - v;
    if (tid == 1023) g_bsum[b] = sm[1023];
}
__global__ void scan2_kernel() {
    __shared__ int sm[64];
    int tid = threadIdx.x;
    int v = (tid < SCAN_BC) ? g_bsum[tid] : 0;
    sm[tid] = v;
    __syncthreads();
    #pragma unroll
    for (int off = 1; off < 64; off <<= 1) {
        int t2 = (tid >= off) ? sm[tid - off] : 0;
        __syncthreads();
        sm[tid] += t2;
        __syncthreads();
    }
    if (tid < SCAN_BC) g_boff[tid] = sm[tid] - v;
    if (tid == SCAN_BC - 1) g_rowoff[NN] = sm[tid];
}
__global__ void scan3_kernel() {
    int b = blockIdx.x;
    int i = b * 1024 + threadIdx.x;
    if (i < NN) {
        int r = g_rowoff[i] + g_boff[b];
        g_rowoff[i] = r;
        g_cursor[i] = r;
    }
}
__global__ void scatter_kernel(const int* __restrict__ src, const int* __restrict__ dst) {
    int e = blockIdx.x * blockDim.x + threadIdx.x;
    if (e < EE) {
        int d = dst[e];
        int slot = atomicAdd(&g_cursor[d], 1);
        g_csr_src[slot] = src[e];
    }
}

// ---------------- layer1 fused softmax+aggregate (half2 gather) ----------------
#define CHUNK 128
__global__ void __launch_bounds__(256) agg1_kernel(const float* __restrict__ x,
                                                   const float* __restrict__ b1) {
    __shared__ float sw[CHUNK][H1];
    __shared__ int   sj[CHUNK];
    __shared__ float2 sacc[4][32];
    __shared__ float  ssum[4][32];
    int n = blockIdx.x;
    int tid = threadIdx.x;
    int lane = tid & 31, w = tid >> 5;
    int grp = w & 3, par = w >> 2;
    int ha = 2 * grp + (lane >> 4);
    int beg = g_rowoff[n], end = g_rowoff[n + 1];
    float2 acc = make_float2(0.f, 0.f);
    float s = 0.f;
    for (int cb = beg; cb < end; cb += CHUNK) {
        int cnt = min(CHUNK, end - cb);
        for (int idx = tid; idx < cnt * H1; idx += 256) {
            int j = idx >> 3, hh = idx & 7;
            int sn = g_csr_src[cb + j];
            if (hh == 0) sj[j] = sn;
            float e = g_el1[sn * H1 + hh] + g_er1[n * H1 + hh];
            e = e > 0.f ? e : NEG_SLOPE * e;
            sw[j][hh] = __expf(e);
        }
        __syncthreads();
        for (int j = par; j < cnt; j += 2) {
            int sn = sj[j];
            float w0 = sw[j][ha];
            __half2 hv = *(const __half2*)&g_feat1h[(size_t)sn * 256 + grp * 64 + lane * 2];
            float2 f = __half22float2(hv);
            s += w0;
            acc.x += w0 * f.x;
            acc.y += w0 * f.y;
        }
        __syncthreads();
    }
    if (par == 1) { sacc[grp][lane] = acc; ssum[grp][lane] = s; }
    __syncthreads();
    if (par == 0) {
        acc.x += sacc[grp][lane].x;
        acc.y += sacc[grp][lane].y;
        s     += ssum[grp][lane];
        float inv = (end > beg) ? 1.0f / s : 0.f;
        int o = n * 256 + grp * 64 + lane * 2;
        float2 xr = *(const float2*)&x[o];
        float2 bb = *(const float2*)&b1[grp * 64 + lane * 2];
        float r0 = fmaxf(acc.x * inv + xr.x + bb.x, 0.f);
        float r1 = fmaxf(acc.y * inv + xr.y + bb.y, 0.f);
        *(float2*)&g_y[o] = make_float2(r0, r1);
    }
}

// ---------------- layer2 fused softmax+aggregate (half-warp parity, half2) ----
__global__ void agg2_kernel(const float* __restrict__ b2, float* __restrict__ out) {
    int t = blockIdx.x * blockDim.x + threadIdx.x;
    int n = t >> 5;
    if (n >= NN) return;
    int lane = t & 31;
    int par = lane >> 4;
    int cl = (lane & 15) * 2;
    int beg = g_rowoff[n], end = g_rowoff[n + 1];
    float ern = g_er2[n];
    float2 acc = make_float2(0.f, 0.f);
    float s = 0.f;
    for (int i = beg + par; i < end; i += 2) {
        int sn = g_csr_src[i];
        float e0 = g_el2[sn] + ern;
        e0 = e0 > 0.f ? e0 : NEG_SLOPE * e0;
        float w0 = __expf(e0);
        __half2 hv = *(const __half2*)&g_f2h[(size_t)sn * 32 + cl];
        float2 f = __half22float2(hv);
        s += w0;
        acc.x += w0 * f.x;
        acc.y += w0 * f.y;
    }
    acc.x += __shfl_xor_sync(0xffffffffu, acc.x, 16);
    acc.y += __shfl_xor_sync(0xffffffffu, acc.y, 16);
    s     += __shfl_xor_sync(0xffffffffu, s, 16);
    if (par == 0) {
        float inv = (end > beg) ? 1.0f / s : 0.f;
        float2 rr = *(const float2*)&g_f2[(size_t)n * 64 + 32 + cl];
        float2 bb = *(const float2*)&b2[cl];
        *(float2*)&out[n * 32 + cl] =
            make_float2(acc.x * inv + rr.x + bb.x, acc.y * inv + rr.y + bb.y);
    }
}

// ---------------- side stream + events (created once at static init; ----------
// ---------------- streams/events are not device-memory allocations) ----------
static cudaStream_t g_s2;
static cudaEvent_t  g_evFork, g_evJoin;
static struct StreamInit {
    StreamInit() {
        cudaStreamCreateWithFlags(&g_s2, cudaStreamNonBlocking);
        cudaEventCreateWithFlags(&g_evFork, cudaEventDisableTiming);
        cudaEventCreateWithFlags(&g_evJoin, cudaEventDisableTiming);
    }
} g_streamInit;

// ---------------- launch: two parallel branches, joined before agg1 ----------
extern "C" void kernel_launch(void* const* d_in, const int* in_sizes, int n_in,
                              void* d_out, int out_size) {
    const float* x     = (const float*)d_in[0];
    const int*   src   = (const int*)d_in[1];
    const int*   dst   = (const int*)d_in[2];
    const float* W1    = (const float*)d_in[3];
    const float* al1   = (const float*)d_in[4];
    const float* ar1   = (const float*)d_in[5];
    const float* b1    = (const float*)d_in[6];
    const float* W2    = (const float*)d_in[7];
    const float* al2   = (const float*)d_in[8];
    const float* ar2   = (const float*)d_in[9];
    const float* resW2 = (const float*)d_in[10];
    const float* b2    = (const float*)d_in[11];
    float* out = (float*)d_out;

    float *yb, *f2;
    __half *w1t, *wct;
    cudaGetSymbolAddress((void**)&yb,   g_y);
    cudaGetSymbolAddress((void**)&f2,   g_f2);
    cudaGetSymbolAddress((void**)&w1t,  g_w1t);
    cudaGetSymbolAddress((void**)&wct,  g_wct);

    const int LDSC = 40;
    const int smem128 = (2 * 64 * LDSC + 2 * 128 * LDSC) * 2;   // 30720 B
    const int smem64  = (2 * 64 * LDSC + 2 * 64 * LDSC) * 2;    // 20480 B
    cudaFuncSetAttribute(mma_gemm_kernel<128, 1>,
                         cudaFuncAttributeMaxDynamicSharedMemorySize, smem128);
    cudaFuncSetAttribute(mma_gemm_kernel<64, 2>,
                         cudaFuncAttributeMaxDynamicSharedMemorySize, smem64);

    // ---- fork: CSR branch on side stream ----
    cudaEventRecord(g_evFork, 0);
    cudaStreamWaitEvent(g_s2, g_evFork, 0);

    zero_kernel<<<(NN + 255) / 256, 256, 0, g_s2>>>();
    hist_kernel<<<(EE + 255) / 256, 256, 0, g_s2>>>(dst);
    scan1_kernel<<<SCAN_BC, 1024, 0, g_s2>>>();
    scan2_kernel<<<1, 64, 0, g_s2>>>();
    scan3_kernel<<<SCAN_BC, 1024, 0, g_s2>>>();
    scatter_kernel<<<(EE + 255) / 256, 256, 0, g_s2>>>(src, dst);
    cudaEventRecord(g_evJoin, g_s2);

    // ---- main branch: weights + layer-1 GEMM (fused attn) ----
    convert_w_kernel<<<(256 * 256 + 255) / 256, 256>>>(W1, W2, resW2);
    mma_gemm_kernel<128, 1><<<dim3(2, (NN + 63) / 64), 256, smem128>>>(
        x, w1t, nullptr, al1, ar1, NN, 256);

    // ---- join, then the serial tail ----
    cudaStreamWaitEvent(0, g_evJoin, 0);
    agg1_kernel<<<NN, 256>>>(x, b1);
    mma_gemm_kernel<64, 2><<<dim3(1, (NN + 63) / 64), 256, smem64>>>(
        yb, wct, f2, al2, ar2, NN, 64);
    agg2_kernel<<<(NN * 32 + 255) / 256, 256>>>(b2, out);
}

// round 14
// speedup vs baseline: 3.6936x; 1.1504x over previous
#include <cuda_runtime.h>
#include <cuda_fp16.h>
#include <math.h>
#include <stdint.h>

#define NN 50000
#define EE 800000
#define H1 8
#define NEG_SLOPE 0.2f
#define SCAN_BC ((NN + 1023) / 1024)   // 49

// ---------------- scratch (device globals; no allocation allowed) ----------------
__device__ __half g_feat1h[NN * 256];        // layer1 features (fp16 gather)
__device__ float  g_y[NN * 256];             // layer1 output (fp32, after relu)
__device__ float  g_el1[NN * H1];
__device__ float  g_er1[NN * H1];
__device__ float  g_f2[NN * 64];             // [ feat2 (0..31) | res2 (32..63) ] fp32
__device__ __half g_f2h[NN * 32];            // fp16 copy of feat2 (agg2 gather)
__device__ float  g_el2[NN];
__device__ float  g_er2[NN];
__device__ __half g_w1t[256 * 256];          // W1^T [n][k] fp16
__device__ __half g_wct[64 * 256];           // [W2|resW2]^T [n][k] fp16
__device__ int   g_deg[NN];                  // zero-init at load; self-reset each run
__device__ int   g_rowoff[NN + 1];
__device__ int   g_cursor[NN];
__device__ int   g_csr_src[EE];
__device__ int   g_bsum[SCAN_BC];
__device__ int   g_flag[SCAN_BC];

// ---------------- helpers ----------------
__device__ __forceinline__ uint32_t smem_u32(const void* p) {
    uint32_t a;
    asm("{ .reg .u64 t; cvta.to.shared.u64 t, %1; cvt.u32.u64 %0, t; }" : "=r"(a) : "l"(p));
    return a;
}
__device__ __forceinline__ void ldsm_x4(uint32_t (&r)[4], const void* p) {
    uint32_t a = smem_u32(p);
    asm volatile("ldmatrix.sync.aligned.m8n8.x4.shared.b16 {%0,%1,%2,%3}, [%4];"
                 : "=r"(r[0]), "=r"(r[1]), "=r"(r[2]), "=r"(r[3]) : "r"(a));
}
__device__ __forceinline__ void mma_f16(float (&d)[4], const uint32_t (&a)[4],
                                        uint32_t b0, uint32_t b1) {
    asm volatile("mma.sync.aligned.m16n8k16.row.col.f32.f16.f16.f32 "
                 "{%0,%1,%2,%3},{%4,%5,%6,%7},{%8,%9},{%0,%1,%2,%3};"
                 : "+f"(d[0]), "+f"(d[1]), "+f"(d[2]), "+f"(d[3])
                 : "r"(a[0]), "r"(a[1]), "r"(a[2]), "r"(a[3]), "r"(b0), "r"(b1));
}
__device__ __forceinline__ void cp16(uint32_t dst, const void* src) {
    asm volatile("cp.async.cg.shared.global [%0], [%1], 16;" :: "r"(dst), "l"(src));
}
#define CP_COMMIT() asm volatile("cp.async.commit_group;" ::: "memory")
#define CP_WAIT0()  asm volatile("cp.async.wait_group 0;" ::: "memory")

// ============ fp16 tensor-core GEMM + fused attention epilogue (as R12/13) ============
template<int BN, int MODE>
__global__ void __launch_bounds__(256, 3) mma_gemm_kernel(
        const float* __restrict__ A, const __half* __restrict__ Bt,
        float* __restrict__ C, const float* __restrict__ av,
        const float* __restrict__ rv, int M, int N) {
    constexpr int LDS = 40;
    constexpr int WN  = BN / 4;
    constexpr int NJ  = WN / 16;
    extern __shared__ __half dyn[];
    __half* pA = dyn;                         // [2][64][LDS]
    __half* pB = dyn + 2 * 64 * LDS;          // [2][BN][LDS]

    int tid = threadIdx.x, lane = tid & 31, wid = tid >> 5;
    int wm = wid & 1, wn = wid >> 1;
    int row0 = blockIdx.y * 64, col0 = blockIdx.x * BN;
    float acc[2][2 * NJ][4] = {};

    int rA = tid >> 2, cA = (tid & 3) * 8;
    const float* aBase = &A[(size_t)(row0 + rA) * 256 + cA];
    bool aValid = (row0 + rA < M);

    auto loadB = [&](int k0, int b) {
        #pragma unroll
        for (int t = 0; t < BN / 64; t++) {
            int v = tid + t * 256;
            int r = v >> 2, c = (v & 3) * 8;
            cp16(smem_u32(pB + (b * BN + r) * LDS + c), &Bt[(size_t)(col0 + r) * 256 + k0 + c]);
        }
        CP_COMMIT();
    };
    auto storeA = [&](const float* fv, int b) {
        union { __half hh[8]; uint4 u; } uc;
        #pragma unroll
        for (int e = 0; e < 8; e++) uc.hh[e] = __float2half_rn(fv[e]);
        *(uint4*)(pA + (b * 64 + rA) * LDS + cA) = uc.u;
    };

    loadB(0, 0);
    {
        float fv[8] = {};
        if (aValid) { *(float4*)fv = *(const float4*)aBase; *(float4*)(fv + 4) = *(const float4*)(aBase + 4); }
        storeA(fv, 0);
    }
    CP_WAIT0();
    __syncthreads();

    for (int chunk = 0; chunk < 8; chunk++) {
        int cur = chunk & 1, nxt = chunk + 1;
        float fv[8] = {};
        if (nxt < 8) {
            loadB(nxt * 32, nxt & 1);
            if (aValid) {
                const float* ap = aBase + nxt * 32;
                *(float4*)fv = *(const float4*)ap;
                *(float4*)(fv + 4) = *(const float4*)(ap + 4);
            }
        }
        #pragma unroll
        for (int kk = 0; kk < 2; kk++) {
            int kc = kk * 16 + (lane >> 4) * 8;
            uint32_t af[2][4];
            #pragma unroll
            for (int mi = 0; mi < 2; mi++) {
                int r = wm * 32 + mi * 16 + (lane & 15);
                ldsm_x4(af[mi], pA + (cur * 64 + r) * LDS + kc);
            }
            #pragma unroll
            for (int nj = 0; nj < NJ; nj++) {
                uint32_t bf[4];
                int r = wn * WN + nj * 16 + (lane & 15);
                ldsm_x4(bf, pB + (cur * BN + r) * LDS + kc);
                #pragma unroll
                for (int half_ = 0; half_ < 2; half_++)
                    #pragma unroll
                    for (int mi = 0; mi < 2; mi++)
                        mma_f16(acc[mi][nj * 2 + half_], af[mi], bf[half_], bf[2 + half_]);
            }
        }
        if (nxt < 8) storeA(fv, nxt & 1);
        CP_WAIT0();
        __syncthreads();
    }

    // ---- epilogue: store + fused attention partials ----
    float elp[4] = {}, erp[4] = {};
    #pragma unroll
    for (int mi = 0; mi < 2; mi++) {
        #pragma unroll
        for (int f = 0; f < 2 * NJ; f++) {
            int r0 = row0 + wm * 32 + mi * 16 + (lane >> 2);
            int c  = col0 + wn * WN + f * 8 + (lane & 3) * 2;
            #pragma unroll
            for (int hh = 0; hh < 2; hh++) {
                int r = r0 + hh * 8;
                if (r >= M) continue;
                float v0 = acc[mi][f][hh * 2], v1 = acc[mi][f][hh * 2 + 1];
                int ri = mi * 2 + hh;
                if (MODE == 1) {
                    *(__half2*)&g_feat1h[(size_t)r * 256 + c] = __floats2half2_rn(v0, v1);
                    elp[ri] += v0 * av[c] + v1 * av[c + 1];
                    erp[ri] += v0 * rv[c] + v1 * rv[c + 1];
                } else {
                    *(float2*)&C[(size_t)r * N + c] = make_float2(v0, v1);
                    if (c < 32) {
                        *(__half2*)&g_f2h[(size_t)r * 32 + c] = __floats2half2_rn(v0, v1);
                        elp[ri] += v0 * av[c] + v1 * av[c + 1];
                        erp[ri] += v0 * rv[c] + v1 * rv[c + 1];
                    }
                }
            }
        }
    }
    #pragma unroll
    for (int ri = 0; ri < 4; ri++) {
        #pragma unroll
        for (int o = 1; o <= 2; o <<= 1) {
            elp[ri] += __shfl_xor_sync(0xffffffffu, elp[ri], o);
            erp[ri] += __shfl_xor_sync(0xffffffffu, erp[ri], o);
        }
    }
    if ((lane & 3) == 0) {
        int q = row0 + wm * 32 + (lane >> 2);
        if (MODE == 1) {
            int head = (col0 >> 5) + wn;
            #pragma unroll
            for (int ri = 0; ri < 4; ri++) {
                int r = q + (ri & 1) * 8 + (ri >> 1) * 16;
                if (r < M) {
                    g_el1[r * H1 + head] = elp[ri];
                    g_er1[r * H1 + head] = erp[ri];
                }
            }
        } else if (wn < 2) {
            #pragma unroll
            for (int ri = 0; ri < 4; ri++) {
                int r = q + (ri & 1) * 8 + (ri >> 1) * 16;
                if (r < M) {
                    atomicAdd(&g_el2[r], elp[ri]);
                    atomicAdd(&g_er2[r], erp[ri]);
                }
            }
        }
    }
}

// ---------------- weight conversion (GEMM branch) ----------------
__global__ void convert_w_kernel(const float* __restrict__ W1, const float* __restrict__ W2,
                                 const float* __restrict__ resW2) {
    int i = blockIdx.x * blockDim.x + threadIdx.x;   // i = n*256 + k
    if (i < 256 * 256) {
        int n = i >> 8, k = i & 255;
        g_w1t[i] = __float2half_rn(W1[k * 256 + n]);
        if (n < 64) {
            float v = (n < 32) ? W2[k * 32 + n] : resW2[k * 32 + (n - 32)];
            g_wct[i] = __float2half_rn(v);
        }
    }
}

// ---------------- CSR branch ----------------
// hist: degree histogram; also resets scan flags (same-stream ordering covers it).
// g_deg is zero at module load and self-reset by scan_fused each run.
__global__ void hist_kernel(const int* __restrict__ dst) {
    int e = blockIdx.x * blockDim.x + threadIdx.x;
    if (e < EE) atomicAdd(&g_deg[dst[e]], 1);
    if (e < SCAN_BC) g_flag[e] = 0;
}
// Single-kernel exclusive scan with ordered inter-block spin sync.
// Block b only waits on blocks < b (CTAs dispatch in ascending bid; all 49
// blocks co-resident) -> deadlock-free. Fuses rowoff + cursor init + deg reset.
__global__ void scan_fused_kernel() {
    __shared__ int sm[1024];
    __shared__ int base_s;
    int b = blockIdx.x, tid = threadIdx.x;
    int i = b * 1024 + tid;
    int v = (i < NN) ? g_deg[i] : 0;
    if (i < NN) g_deg[i] = 0;                 // self-reset for next replay
    sm[tid] = v;
    __syncthreads();
    #pragma unroll
    for (int off = 1; off < 1024; off <<= 1) {
        int t2 = (tid >= off) ? sm[tid - off] : 0;
        __syncthreads();
        sm[tid] += t2;
        __syncthreads();
    }
    int incl = sm[tid];
    if (tid == 1023) {
        g_bsum[b] = incl;
        __threadfence();
        atomicExch(&g_flag[b], 1);
    }
    if (tid == 0) {
        int acc = 0;
        for (int j = 0; j < b; j++) {
            while (atomicAdd(&g_flag[j], 0) == 0) {}
            acc += g_bsum[j];
        }
        base_s = acc;
    }
    __syncthreads();
    int r = base_s + incl - v;
    if (i < NN) { g_rowoff[i] = r; g_cursor[i] = r; }
    if (b == SCAN_BC - 1 && tid == 1023) g_rowoff[NN] = base_s + incl;
}
__global__ void scatter_kernel(const int* __restrict__ src, const int* __restrict__ dst) {
    int e = blockIdx.x * blockDim.x + threadIdx.x;
    if (e < EE) {
        int d = dst[e];
        int slot = atomicAdd(&g_cursor[d], 1);
        g_csr_src[slot] = src[e];
    }
}

// ---------------- layer1 softmax+aggregate: WARP per node, no barriers ----------
// Lanes 0-7 compute the 8 head weights per edge (1 sector + 1 MUFU/edge).
// 4 passes over 64-col groups; per-lane head = 2p + (lane>>4); per-lane
// softmax sum sv[p] equals the head's full sum (uniform within half-warp).
// Also zeroes el2/er2 (consumed by GEMM2 atomics later on this stream).
__global__ void __launch_bounds__(256) agg1_kernel(const float* __restrict__ x,
                                                   const float* __restrict__ b1) {
    int t = blockIdx.x * blockDim.x + threadIdx.x;
    int n = t >> 5;
    if (n >= NN) return;
    int lane = t & 31;
    if (lane == 0) { g_el2[n] = 0.f; g_er2[n] = 0.f; }
    int beg = g_rowoff[n], end = g_rowoff[n + 1];
    float er8 = (lane < H1) ? g_er1[n * H1 + lane] : 0.f;
    float2 acc[4] = {};
    float sv[4] = {};
    int srcLane = lane >> 4;                  // 0 or 1 within pass pair
    for (int i = beg; i < end; i++) {
        int sn = g_csr_src[i];
        float w8 = 0.f;
        if (lane < H1) {
            float e = g_el1[sn * H1 + lane] + er8;
            e = e > 0.f ? e : NEG_SLOPE * e;
            w8 = __expf(e);
        }
        const __half2* frow = (const __half2*)&g_feat1h[(size_t)sn * 256];
        #pragma unroll
        for (int p = 0; p < 4; p++) {
            float w = __shfl_sync(0xffffffffu, w8, 2 * p + srcLane);
            float2 f = __half22float2(frow[p * 32 + lane]);
            acc[p].x += w * f.x;
            acc[p].y += w * f.y;
            sv[p] += w;
        }
    }
    #pragma unroll
    for (int p = 0; p < 4; p++) {
        float inv = (end > beg) ? 1.0f / sv[p] : 0.f;
        int o = n * 256 + p * 64 + lane * 2;
        float2 xr = *(const float2*)&x[o];
        float2 bb = *(const float2*)&b1[p * 64 + lane * 2];
        *(float2*)&g_y[o] = make_float2(
            fmaxf(acc[p].x * inv + xr.x + bb.x, 0.f),
            fmaxf(acc[p].y * inv + xr.y + bb.y, 0.f));
    }
}

// ---------------- layer2 fused softmax+aggregate (half-warp parity, half2) ----
__global__ void agg2_kernel(const float* __restrict__ b2, float* __restrict__ out) {
    int t = blockIdx.x * blockDim.x + threadIdx.x;
    int n = t >> 5;
    if (n >= NN) return;
    int lane = t & 31;
    int par = lane >> 4;
    int cl = (lane & 15) * 2;
    int beg = g_rowoff[n], end = g_rowoff[n + 1];
    float ern = g_er2[n];
    float2 acc = make_float2(0.f, 0.f);
    float s = 0.f;
    for (int i = beg + par; i < end; i += 2) {
        int sn = g_csr_src[i];
        float e0 = g_el2[sn] + ern;
        e0 = e0 > 0.f ? e0 : NEG_SLOPE * e0;
        float w0 = __expf(e0);
        __half2 hv = *(const __half2*)&g_f2h[(size_t)sn * 32 + cl];
        float2 f = __half22float2(hv);
        s += w0;
        acc.x += w0 * f.x;
        acc.y += w0 * f.y;
    }
    acc.x += __shfl_xor_sync(0xffffffffu, acc.x, 16);
    acc.y += __shfl_xor_sync(0xffffffffu, acc.y, 16);
    s     += __shfl_xor_sync(0xffffffffu, s, 16);
    if (par == 0) {
        float inv = (end > beg) ? 1.0f / s : 0.f;
        float2 rr = *(const float2*)&g_f2[(size_t)n * 64 + 32 + cl];
        float2 bb = *(const float2*)&b2[cl];
        *(float2*)&out[n * 32 + cl] =
            make_float2(acc.x * inv + rr.x + bb.x, acc.y * inv + rr.y + bb.y);
    }
}

// ---------------- side stream + events (static init; not device allocations) ----
static cudaStream_t g_s2;
static cudaEvent_t  g_evFork, g_evJoin;
static struct StreamInit {
    StreamInit() {
        cudaStreamCreateWithFlags(&g_s2, cudaStreamNonBlocking);
        cudaEventCreateWithFlags(&g_evFork, cudaEventDisableTiming);
        cudaEventCreateWithFlags(&g_evJoin, cudaEventDisableTiming);
    }
} g_streamInit;

// ---------------- launch: two parallel branches, joined before agg1 ----------
extern "C" void kernel_launch(void* const* d_in, const int* in_sizes, int n_in,
                              void* d_out, int out_size) {
    const float* x     = (const float*)d_in[0];
    const int*   src   = (const int*)d_in[1];
    const int*   dst   = (const int*)d_in[2];
    const float* W1    = (const float*)d_in[3];
    const float* al1   = (const float*)d_in[4];
    const float* ar1   = (const float*)d_in[5];
    const float* b1    = (const float*)d_in[6];
    const float* W2    = (const float*)d_in[7];
    const float* al2   = (const float*)d_in[8];
    const float* ar2   = (const float*)d_in[9];
    const float* resW2 = (const float*)d_in[10];
    const float* b2    = (const float*)d_in[11];
    float* out = (float*)d_out;

    float *yb, *f2;
    __half *w1t, *wct;
    cudaGetSymbolAddress((void**)&yb,   g_y);
    cudaGetSymbolAddress((void**)&f2,   g_f2);
    cudaGetSymbolAddress((void**)&w1t,  g_w1t);
    cudaGetSymbolAddress((void**)&wct,  g_wct);

    const int LDSC = 40;
    const int smem128 = (2 * 64 * LDSC + 2 * 128 * LDSC) * 2;   // 30720 B
    const int smem64  = (2 * 64 * LDSC + 2 * 64 * LDSC) * 2;    // 20480 B
    cudaFuncSetAttribute(mma_gemm_kernel<128, 1>,
                         cudaFuncAttributeMaxDynamicSharedMemorySize, smem128);
    cudaFuncSetAttribute(mma_gemm_kernel<64, 2>,
                         cudaFuncAttributeMaxDynamicSharedMemorySize, smem64);

    // ---- fork: CSR branch on side stream ----
    cudaEventRecord(g_evFork, 0);
    cudaStreamWaitEvent(g_s2, g_evFork, 0);

    hist_kernel<<<(EE + 255) / 256, 256, 0, g_s2>>>(dst);
    scan_fused_kernel<<<SCAN_BC, 1024, 0, g_s2>>>();
    scatter_kernel<<<(EE + 255) / 256, 256, 0, g_s2>>>(src, dst);
    cudaEventRecord(g_evJoin, g_s2);

    // ---- main branch: weights + layer-1 GEMM (fused attn) ----
    convert_w_kernel<<<(256 * 256 + 255) / 256, 256>>>(W1, W2, resW2);
    mma_gemm_kernel<128, 1><<<dim3(2, (NN + 63) / 64), 256, smem128>>>(
        x, w1t, nullptr, al1, ar1, NN, 256);

    // ---- join, then the serial tail ----
    cudaStreamWaitEvent(0, g_evJoin, 0);
    agg1_kernel<<<(NN * 32 + 255) / 256, 256>>>(x, b1);
    mma_gemm_kernel<64, 2><<<dim3(1, (NN + 63) / 64), 256, smem64>>>(
        yb, wct, f2, al2, ar2, NN, 64);
    agg2_kernel<<<(NN * 32 + 255) / 256, 256>>>(b2, out);
}